// round 9
// baseline (speedup 1.0000x reference)
#include <cuda_runtime.h>
#include <cuda_fp16.h>
#include <math.h>
#include <stdint.h>

// Problem constants
constexpr int Bc  = 2;
constexpr int Sc  = 2048;
constexpr int Dc  = 2048;
constexpr int Hc  = 16;
constexpr int DHc = 128;
constexpr int Mc  = Bc * Sc;   // 4096 rows for projections

// ---------------------------------------------------------------------------
// Scratch (device globals: allocation-free per harness rules)
// ---------------------------------------------------------------------------
__device__ __half g_Qp [(size_t)Mc * Dc];      // pre-rope Q (half)
__device__ __half g_Kp [(size_t)Mc * Dc];      // pre-rope K (half)
__device__ __half g_Vh [(size_t)Mc * Dc];      // half V
__device__ __half g_xh [(size_t)Mc * Dc];
__device__ __half g_Qh [(size_t)Mc * Dc];      // roped + softmax-scaled
__device__ __half g_Kh [(size_t)Mc * Dc];      // roped
__device__ __half g_Ah [(size_t)Mc * Dc];      // attention out (half)
__device__ __half g_wqh[(size_t)Dc * Dc];
__device__ __half g_wkh[(size_t)Dc * Dc];
__device__ __half g_wvh[(size_t)Dc * Dc];
__device__ __half g_woh[(size_t)Dc * Dc];

#define CP_ASYNC16(dst, src) \
    asm volatile("cp.async.cg.shared.global [%0], [%1], 16;\n" :: "r"(dst), "l"(src))

#define MMA_F16(c, a0, a1, a2, a3, b0, b1)                                     \
    asm volatile(                                                              \
        "mma.sync.aligned.m16n8k16.row.col.f32.f16.f16.f32 "                   \
        "{%0,%1,%2,%3}, {%4,%5,%6,%7}, {%8,%9}, {%0,%1,%2,%3};\n"              \
        : "+f"((c)[0]), "+f"((c)[1]), "+f"((c)[2]), "+f"((c)[3])               \
        : "r"(a0), "r"(a1), "r"(a2), "r"(a3), "r"(b0), "r"(b1))

#define LDSM_X4(r0, r1, r2, r3, addr)                                          \
    asm volatile("ldmatrix.sync.aligned.m8n8.x4.shared.b16 {%0,%1,%2,%3}, [%4];" \
        : "=r"(r0), "=r"(r1), "=r"(r2), "=r"(r3) : "r"(addr))

#define LDSM_X4_T(r0, r1, r2, r3, addr)                                        \
    asm volatile("ldmatrix.sync.aligned.m8n8.x4.trans.shared.b16 {%0,%1,%2,%3}, [%4];" \
        : "=r"(r0), "=r"(r1), "=r"(r2), "=r"(r3) : "r"(addr))

// ---------------------------------------------------------------------------
// fp32 -> fp16 conversion (round-to-nearest)
// ---------------------------------------------------------------------------
__global__ void cvt_half(const float* __restrict__ in, __half* __restrict__ out,
                         int n4) {
    int i = blockIdx.x * blockDim.x + threadIdx.x;
    if (i >= n4) return;
    float4 v = *(const float4*)(in + (size_t)i * 4);
    __half2 h01 = __floats2half2_rn(v.x, v.y);
    __half2 h23 = __floats2half2_rn(v.z, v.w);
    uint2 u;
    u.x = *(uint32_t*)&h01;
    u.y = *(uint32_t*)&h23;
    *(uint2*)(out + (size_t)i * 4) = u;
}

// ---------------------------------------------------------------------------
// fp16 mma GEMM:  C[M,N] = A[M,K] @ B[N,K]^T   (row-major, K contiguous)
// BM=128, BN=256, BK=32 halves, 256 thr = 8 warps (2m x 4n), warp tile 64x64,
// m16n8k16 + ldmatrix, cp.async double-buffered, stride 40 halves.
// ---------------------------------------------------------------------------
constexpr int HST = 40;                                         // halves/row
constexpr int GEMM_SMEM_B = (2 * 128 * HST + 2 * 256 * HST) * 2; // 61440 B

__global__ void __launch_bounds__(256) gemm_f16(const __half* __restrict__ A,
                                                const __half* __restrict__ B,
                                                float* __restrict__ Cf,
                                                __half* __restrict__ Ch,
                                                int M, int N, int K) {
    extern __shared__ __half hsm[];
    __half* sA = hsm;                      // [2][128][40]
    __half* sB = hsm + 2 * 128 * HST;      // [2][256][40]

    const int tid  = threadIdx.x;
    const int wid  = tid >> 5;
    const int lane = tid & 31;
    const int wm = (wid & 1) * 64;         // 2 m-warps
    const int wn = (wid >> 1) * 64;        // 4 n-warps
    const int gp = lane >> 2;
    const int t4 = lane & 3;
    const int m0 = blockIdx.y * 128;
    const int n0 = blockIdx.x * 256;

    const int arow = (lane & 7) + ((lane >> 3) & 1) * 8;
    const int acol = (lane >> 4) * 8;
    const int brow = (lane & 7) + (lane >> 4) * 8;
    const int bcol = ((lane >> 3) & 1) * 8;

    // loaders: 256 threads; lrow 0..63, lseg 0..3 (8 halves = 16B)
    const int lrow = tid >> 2;
    const int lseg = tid & 3;
    const __half* Ag = A + (size_t)(m0 + lrow) * K + lseg * 8;
    const __half* Bg = B + (size_t)(n0 + lrow) * K + lseg * 8;

    const uint32_t sA_u = (uint32_t)__cvta_generic_to_shared(sA);
    const uint32_t sB_u = (uint32_t)__cvta_generic_to_shared(sB);

    float acc[4][8][4];
#pragma unroll
    for (int im = 0; im < 4; im++)
#pragma unroll
        for (int in_ = 0; in_ < 8; in_++)
#pragma unroll
            for (int r = 0; r < 4; r++) acc[im][in_][r] = 0.f;

    const int nt = K / 32;

    {
#pragma unroll
        for (int p = 0; p < 2; p++) {      // A: 128 rows
            int row = lrow + p * 64;
            CP_ASYNC16(sA_u + (uint32_t)((row * HST + lseg * 8) * 2),
                       Ag + (size_t)p * 64 * K);
        }
#pragma unroll
        for (int p = 0; p < 4; p++) {      // B: 256 rows
            int row = lrow + p * 64;
            CP_ASYNC16(sB_u + (uint32_t)((row * HST + lseg * 8) * 2),
                       Bg + (size_t)p * 64 * K);
        }
        asm volatile("cp.async.commit_group;\n");
    }

    for (int kt = 0; kt < nt; kt++) {
        const int cur = kt & 1;
        if (kt + 1 < nt) {
            const int nb = cur ^ 1;
            const int k0 = (kt + 1) * 32;
#pragma unroll
            for (int p = 0; p < 2; p++) {
                int row = lrow + p * 64;
                CP_ASYNC16(sA_u + (uint32_t)((((nb * 128) + row) * HST + lseg * 8) * 2),
                           Ag + (size_t)p * 64 * K + k0);
            }
#pragma unroll
            for (int p = 0; p < 4; p++) {
                int row = lrow + p * 64;
                CP_ASYNC16(sB_u + (uint32_t)((((nb * 256) + row) * HST + lseg * 8) * 2),
                           Bg + (size_t)p * 64 * K + k0);
            }
            asm volatile("cp.async.commit_group;\n");
            asm volatile("cp.async.wait_group 1;\n");
        } else {
            asm volatile("cp.async.wait_group 0;\n");
        }
        __syncthreads();

        const uint32_t cA_u = sA_u + (uint32_t)(cur * 128 * HST * 2);
        const uint32_t cB_u = sB_u + (uint32_t)(cur * 256 * HST * 2);

#pragma unroll
        for (int ks = 0; ks < 2; ks++) {
            const int kk = ks * 16;
            uint32_t af[4][4];
#pragma unroll
            for (int im = 0; im < 4; im++)
                LDSM_X4(af[im][0], af[im][1], af[im][2], af[im][3],
                        cA_u + (uint32_t)(((wm + im * 16 + arow) * HST + kk + acol) * 2));
            uint32_t bf[8][2];
#pragma unroll
            for (int j2 = 0; j2 < 4; j2++)
                LDSM_X4(bf[2 * j2][0], bf[2 * j2][1],
                        bf[2 * j2 + 1][0], bf[2 * j2 + 1][1],
                        cB_u + (uint32_t)(((wn + j2 * 16 + brow) * HST + kk + bcol) * 2));
#pragma unroll
            for (int im = 0; im < 4; im++)
#pragma unroll
                for (int in_ = 0; in_ < 8; in_++)
                    MMA_F16(acc[im][in_], af[im][0], af[im][1], af[im][2],
                            af[im][3], bf[in_][0], bf[in_][1]);
        }
        __syncthreads();
    }

#pragma unroll
    for (int im = 0; im < 4; im++) {
        const int mA = m0 + wm + im * 16 + gp;
#pragma unroll
        for (int in_ = 0; in_ < 8; in_++) {
            const int n = n0 + wn + in_ * 8 + 2 * t4;
            if (Ch) {
                *(__half2*)(Ch + (size_t)mA * N + n) =
                    __floats2half2_rn(acc[im][in_][0], acc[im][in_][1]);
                *(__half2*)(Ch + (size_t)(mA + 8) * N + n) =
                    __floats2half2_rn(acc[im][in_][2], acc[im][in_][3]);
            } else {
                *(float2*)(Cf + (size_t)mA * N + n) =
                    make_float2(acc[im][in_][0], acc[im][in_][1]);
                *(float2*)(Cf + (size_t)(mA + 8) * N + n) =
                    make_float2(acc[im][in_][2], acc[im][in_][3]);
            }
        }
    }
}

// ---------------------------------------------------------------------------
// RoPE: half in, half out. Qh pre-scaled by 1/sqrt(DH).
// ---------------------------------------------------------------------------
__global__ void rope_half(const __half* __restrict__ Qf,
                          const __half* __restrict__ Kf,
                          __half* __restrict__ Qh, __half* __restrict__ Kh,
                          const float* __restrict__ cosp,
                          const float* __restrict__ sinp) {
    int i = blockIdx.x * blockDim.x + threadIdx.x;
    const int total = Bc * Sc * Hc * 32;
    if (i >= total) return;
    int d2 = (i & 31) * 2;            // 0..62
    int h  = (i >> 5) & (Hc - 1);
    int bs = i >> 9;
    int s  = bs & (Sc - 1);
    size_t base = (size_t)bs * Dc + h * DHc;

    const __half* src = blockIdx.y ? Kf : Qf;
    float2 x1 = __half22float2(*(const __half2*)(src + base + d2));
    float2 x2 = __half22float2(*(const __half2*)(src + base + d2 + 64));
    float2 c  = *(const float2*)(cosp + s * DHc + d2);
    float2 sn = *(const float2*)(sinp + s * DHc + d2);

    float r1x = x1.x * c.x - x2.x * sn.x;
    float r1y = x1.y * c.y - x2.y * sn.y;
    float r2x = x2.x * c.x + x1.x * sn.x;
    float r2y = x2.y * c.y + x1.y * sn.y;

    if (blockIdx.y == 0) {
        const float scale = 0.08838834764831845f;
        r1x *= scale; r1y *= scale; r2x *= scale; r2y *= scale;
    }
    __half* dst = blockIdx.y ? Kh : Qh;
    *(__half2*)(dst + base + d2)      = __floats2half2_rn(r1x, r1y);
    *(__half2*)(dst + base + d2 + 64) = __floats2half2_rn(r2x, r2y);
}

// ---------------------------------------------------------------------------
// Flash attention (round-7 proven shape): BM=BN=64, 128 thr / 4 warps,
// all-fp16 mma, fp32 softmax/accum, ldmatrix (+trans for V).
// Double-buffered K; V overlaps QK; K(j+1) overlaps PV(j).
// ---------------------------------------------------------------------------
constexpr int QSH = 136;   // halves
constexpr int KSH = 136;
constexpr int VSH = 136;
constexpr int PSH = 72;
constexpr int OFF_Q  = 0;
constexpr int OFF_K0 = OFF_Q  + 64 * QSH * 2;        // 17408
constexpr int OFF_K1 = OFF_K0 + 64 * KSH * 2;        // 34816
constexpr int OFF_V  = OFF_K1 + 64 * KSH * 2;        // 52224
constexpr int OFF_P  = OFF_V  + 64 * VSH * 2;        // 69632
constexpr int FL_SMEM_B = OFF_P + 64 * PSH * 2;      // 78848

__global__ void __launch_bounds__(128) flash_tc(const __half* __restrict__ Q,
                                                const __half* __restrict__ K,
                                                const __half* __restrict__ V,
                                                __half* __restrict__ O) {
    extern __shared__ char smraw[];
    __half* sP = (__half*)(smraw + OFF_P);
    const uint32_t sQ_u  = (uint32_t)__cvta_generic_to_shared(smraw + OFF_Q);
    const uint32_t sK0_u = (uint32_t)__cvta_generic_to_shared(smraw + OFF_K0);
    const uint32_t sK1_u = (uint32_t)__cvta_generic_to_shared(smraw + OFF_K1);
    const uint32_t sV_u  = (uint32_t)__cvta_generic_to_shared(smraw + OFF_V);
    const uint32_t sP_u  = (uint32_t)__cvta_generic_to_shared(sP);

    const int tid  = threadIdx.x;
    const int wid  = tid >> 5;
    const int lane = tid & 31;
    const int gp   = lane >> 2;
    const int t4   = lane & 3;
    const int qb   = blockIdx.x;
    const int bh   = blockIdx.y;
    const int b    = bh >> 4;
    const int h    = bh & (Hc - 1);
    const size_t base = ((size_t)b * Sc) * Dc + (size_t)h * DHc;
    const int q0   = qb * 64;
    const int wrow = wid * 16;
    const int r0loc = wrow + gp;
    const int r1loc = r0loc + 8;

    const int arow = (lane & 7) + ((lane >> 3) & 1) * 8;
    const int acol = (lane >> 4) * 8;
    const int brow = (lane & 7) + (lane >> 4) * 8;
    const int bcol = ((lane >> 3) & 1) * 8;
    const int vrow = (lane & 7) + ((lane >> 3) & 1) * 8;
    const int vcol = (lane >> 4) * 8;

    // prologue: Q + K0 in group 0, V0 in group 1
    {
#pragma unroll
        for (int p = 0; p < 8; p++) {
            int idx = tid + p * 128;
            int r = idx >> 4, sg = (idx & 15) * 8;
            CP_ASYNC16(sQ_u + (uint32_t)((r * QSH + sg) * 2),
                       Q + base + (size_t)(q0 + r) * Dc + sg);
        }
#pragma unroll
        for (int p = 0; p < 8; p++) {
            int idx = tid + p * 128;
            int r = idx >> 4, sg = (idx & 15) * 8;
            CP_ASYNC16(sK0_u + (uint32_t)((r * KSH + sg) * 2),
                       K + base + (size_t)r * Dc + sg);
        }
        asm volatile("cp.async.commit_group;\n");
#pragma unroll
        for (int p = 0; p < 8; p++) {
            int idx = tid + p * 128;
            int r = idx >> 4, sg = (idx & 15) * 8;
            CP_ASYNC16(sV_u + (uint32_t)((r * VSH + sg) * 2),
                       V + base + (size_t)r * Dc + sg);
        }
        asm volatile("cp.async.commit_group;\n");
    }

    float o[16][4];
#pragma unroll
    for (int n = 0; n < 16; n++)
#pragma unroll
        for (int r = 0; r < 4; r++) o[n][r] = 0.f;
    float m0 = -1e30f, m1 = -1e30f, l0 = 0.f, l1 = 0.f;

    for (int j = 0; j <= qb; ++j) {
        const uint32_t sKc_u = (j & 1) ? sK1_u : sK0_u;
        const uint32_t sKn_u = (j & 1) ? sK0_u : sK1_u;

        asm volatile("cp.async.wait_group 1;\n");
        __syncthreads();

        // ---- S = Qs @ K^T ----
        float sacc[8][4];
#pragma unroll
        for (int n = 0; n < 8; n++)
#pragma unroll
            for (int r = 0; r < 4; r++) sacc[n][r] = 0.f;

#pragma unroll
        for (int kk8 = 0; kk8 < 8; kk8++) {
            const int kk = kk8 * 16;
            uint32_t a0, a1, a2, a3;
            LDSM_X4(a0, a1, a2, a3,
                    sQ_u + (uint32_t)(((wrow + arow) * QSH + kk + acol) * 2));
            uint32_t bf[8][2];
#pragma unroll
            for (int j2 = 0; j2 < 4; j2++)
                LDSM_X4(bf[2 * j2][0], bf[2 * j2][1],
                        bf[2 * j2 + 1][0], bf[2 * j2 + 1][1],
                        sKc_u + (uint32_t)(((j2 * 16 + brow) * KSH + kk + bcol) * 2));
#pragma unroll
            for (int nt = 0; nt < 8; nt++)
                MMA_F16(sacc[nt], a0, a1, a2, a3, bf[nt][0], bf[nt][1]);
        }

        if (j == qb) {
#pragma unroll
            for (int nt = 0; nt < 8; nt++) {
                int c0 = nt * 8 + 2 * t4;
                if (c0 > r0loc)     sacc[nt][0] = -1e30f;
                if (c0 + 1 > r0loc) sacc[nt][1] = -1e30f;
                if (c0 > r1loc)     sacc[nt][2] = -1e30f;
                if (c0 + 1 > r1loc) sacc[nt][3] = -1e30f;
            }
        }

        // ---- online softmax ----
        float mx0 = -1e30f, mx1 = -1e30f;
#pragma unroll
        for (int nt = 0; nt < 8; nt++) {
            mx0 = fmaxf(mx0, fmaxf(sacc[nt][0], sacc[nt][1]));
            mx1 = fmaxf(mx1, fmaxf(sacc[nt][2], sacc[nt][3]));
        }
        mx0 = fmaxf(mx0, __shfl_xor_sync(0xffffffff, mx0, 1));
        mx0 = fmaxf(mx0, __shfl_xor_sync(0xffffffff, mx0, 2));
        mx1 = fmaxf(mx1, __shfl_xor_sync(0xffffffff, mx1, 1));
        mx1 = fmaxf(mx1, __shfl_xor_sync(0xffffffff, mx1, 2));

        float m0n = fmaxf(m0, mx0);
        float m1n = fmaxf(m1, mx1);
        float corr0 = __expf(m0 - m0n);
        float corr1 = __expf(m1 - m1n);
        m0 = m0n; m1 = m1n;

        float ls0 = 0.f, ls1 = 0.f;
#pragma unroll
        for (int nt = 0; nt < 8; nt++) {
            float p0 = __expf(sacc[nt][0] - m0);
            float p1 = __expf(sacc[nt][1] - m0);
            float p2 = __expf(sacc[nt][2] - m1);
            float p3 = __expf(sacc[nt][3] - m1);
            ls0 += p0 + p1;
            ls1 += p2 + p3;
            int c0 = nt * 8 + 2 * t4;
            *(__half2*)(sP + r0loc * PSH + c0) = __floats2half2_rn(p0, p1);
            *(__half2*)(sP + r1loc * PSH + c0) = __floats2half2_rn(p2, p3);
        }
        ls0 += __shfl_xor_sync(0xffffffff, ls0, 1);
        ls0 += __shfl_xor_sync(0xffffffff, ls0, 2);
        ls1 += __shfl_xor_sync(0xffffffff, ls1, 1);
        ls1 += __shfl_xor_sync(0xffffffff, ls1, 2);
        l0 = l0 * corr0 + ls0;
        l1 = l1 * corr1 + ls1;

#pragma unroll
        for (int nt = 0; nt < 16; nt++) {
            o[nt][0] *= corr0; o[nt][1] *= corr0;
            o[nt][2] *= corr1; o[nt][3] *= corr1;
        }

        if (j < qb) {
            const int k0n = (j + 1) * 64;
#pragma unroll
            for (int p = 0; p < 8; p++) {
                int idx = tid + p * 128;
                int r = idx >> 4, sg = (idx & 15) * 8;
                CP_ASYNC16(sKn_u + (uint32_t)((r * KSH + sg) * 2),
                           K + base + (size_t)(k0n + r) * Dc + sg);
            }
            asm volatile("cp.async.commit_group;\n");
            asm volatile("cp.async.wait_group 1;\n");
        } else {
            asm volatile("cp.async.wait_group 0;\n");
        }
        __syncthreads();   // P visible + V ready

        // ---- O += P @ V ----
#pragma unroll
        for (int ks = 0; ks < 4; ks++) {
            const int kk = ks * 16;
            uint32_t a0, a1, a2, a3;
            LDSM_X4(a0, a1, a2, a3,
                    sP_u + (uint32_t)(((wrow + arow) * PSH + kk + acol) * 2));
#pragma unroll
            for (int j2 = 0; j2 < 8; j2++) {
                uint32_t b00, b01, b10, b11;
                LDSM_X4_T(b00, b01, b10, b11,
                    sV_u + (uint32_t)(((kk + vrow) * VSH + j2 * 16 + vcol) * 2));
                MMA_F16(o[2 * j2],     a0, a1, a2, a3, b00, b01);
                MMA_F16(o[2 * j2 + 1], a0, a1, a2, a3, b10, b11);
            }
        }
        __syncthreads();

        if (j < qb) {
            const int k0n = (j + 1) * 64;
#pragma unroll
            for (int p = 0; p < 8; p++) {
                int idx = tid + p * 128;
                int r = idx >> 4, sg = (idx & 15) * 8;
                CP_ASYNC16(sV_u + (uint32_t)((r * VSH + sg) * 2),
                           V + base + (size_t)(k0n + r) * Dc + sg);
            }
            asm volatile("cp.async.commit_group;\n");
        }
    }

    float inv0 = 1.0f / l0, inv1 = 1.0f / l1;
    const size_t row0 = base + (size_t)(q0 + r0loc) * Dc;
    const size_t row1 = base + (size_t)(q0 + r1loc) * Dc;
#pragma unroll
    for (int nt = 0; nt < 16; nt++) {
        int c0 = nt * 8 + 2 * t4;
        *(__half2*)(O + row0 + c0) =
            __floats2half2_rn(o[nt][0] * inv0, o[nt][1] * inv0);
        *(__half2*)(O + row1 + c0) =
            __floats2half2_rn(o[nt][2] * inv1, o[nt][3] * inv1);
    }
}

// ---------------------------------------------------------------------------
// Launch
// ---------------------------------------------------------------------------
extern "C" void kernel_launch(void* const* d_in, const int* in_sizes, int n_in,
                              void* d_out, int out_size) {
    const float* x    = (const float*)d_in[0];
    const float* cosp = (const float*)d_in[1];
    const float* sinp = (const float*)d_in[2];
    const float* Wq   = (const float*)d_in[3];
    const float* Wk   = (const float*)d_in[4];
    const float* Wv   = (const float*)d_in[5];
    const float* Wo   = (const float*)d_in[6];
    float* out = (float*)d_out;

    __half *Qp, *Kp, *Vh, *xh, *Qh, *Kh, *Ah, *wqh, *wkh, *wvh, *woh;
    cudaGetSymbolAddress((void**)&Qp, g_Qp);
    cudaGetSymbolAddress((void**)&Kp, g_Kp);
    cudaGetSymbolAddress((void**)&Vh, g_Vh);
    cudaGetSymbolAddress((void**)&xh, g_xh);
    cudaGetSymbolAddress((void**)&Qh, g_Qh);
    cudaGetSymbolAddress((void**)&Kh, g_Kh);
    cudaGetSymbolAddress((void**)&Ah, g_Ah);
    cudaGetSymbolAddress((void**)&wqh, g_wqh);
    cudaGetSymbolAddress((void**)&wkh, g_wkh);
    cudaGetSymbolAddress((void**)&wvh, g_wvh);
    cudaGetSymbolAddress((void**)&woh, g_woh);

    cudaFuncSetAttribute(gemm_f16, cudaFuncAttributeMaxDynamicSharedMemorySize,
                         GEMM_SMEM_B);
    cudaFuncSetAttribute(flash_tc, cudaFuncAttributeMaxDynamicSharedMemorySize,
                         FL_SMEM_B);

    // fp16 conversions of GEMM inputs
    {
        const int nx = Mc * Dc / 4, nw = Dc * Dc / 4;
        cvt_half<<<(nx + 255) / 256, 256>>>(x,  xh,  nx);
        cvt_half<<<(nw + 255) / 256, 256>>>(Wq, wqh, nw);
        cvt_half<<<(nw + 255) / 256, 256>>>(Wk, wkh, nw);
        cvt_half<<<(nw + 255) / 256, 256>>>(Wv, wvh, nw);
        cvt_half<<<(nw + 255) / 256, 256>>>(Wo, woh, nw);
    }

    dim3 ggrid(Dc / 256, Mc / 128);   // (8, 32)

    gemm_f16<<<ggrid, 256, GEMM_SMEM_B>>>(xh, wqh, nullptr, Qp, Mc, Dc, Dc);
    gemm_f16<<<ggrid, 256, GEMM_SMEM_B>>>(xh, wkh, nullptr, Kp, Mc, Dc, Dc);
    gemm_f16<<<ggrid, 256, GEMM_SMEM_B>>>(xh, wvh, nullptr, Vh, Mc, Dc, Dc);

    // RoPE (half -> half; Qh pre-scaled)
    {
        int total = Bc * Sc * Hc * 32;
        dim3 rgrid((total + 255) / 256, 2);
        rope_half<<<rgrid, 256>>>(Qp, Kp, Qh, Kh, cosp, sinp);
    }

    // flash attention (BM=64, proven round-7 shape)
    {
        dim3 fgrid(Sc / 64, Bc * Hc);   // (32, 32)
        flash_tc<<<fgrid, 128, FL_SMEM_B>>>(Qh, Kh, Vh, Ah);
    }

    // O projection (fp32 out)
    gemm_f16<<<ggrid, 256, GEMM_SMEM_B>>>(Ah, woh, out, nullptr, Mc, Dc, Dc);
}

// round 10
// speedup vs baseline: 1.0840x; 1.0840x over previous
#include <cuda_runtime.h>
#include <cuda_fp16.h>
#include <math.h>
#include <stdint.h>

// Problem constants
constexpr int Bc  = 2;
constexpr int Sc  = 2048;
constexpr int Dc  = 2048;
constexpr int Hc  = 16;
constexpr int DHc = 128;
constexpr int Mc  = Bc * Sc;   // 4096 rows for projections

// ---------------------------------------------------------------------------
// Scratch (device globals: allocation-free per harness rules)
// ---------------------------------------------------------------------------
__device__ __half g_Vh [(size_t)Mc * Dc];      // half V
__device__ __half g_xh [(size_t)Mc * Dc];
__device__ __half g_Qh [(size_t)Mc * Dc];      // roped + softmax-scaled
__device__ __half g_Kh [(size_t)Mc * Dc];      // roped
__device__ __half g_Ah [(size_t)Mc * Dc];      // attention out (half)
__device__ __half g_wqh[(size_t)Dc * Dc];
__device__ __half g_wkh[(size_t)Dc * Dc];
__device__ __half g_wvh[(size_t)Dc * Dc];
__device__ __half g_woh[(size_t)Dc * Dc];

#define CP_ASYNC16(dst, src) \
    asm volatile("cp.async.cg.shared.global [%0], [%1], 16;\n" :: "r"(dst), "l"(src))

#define MMA_F16(c, a0, a1, a2, a3, b0, b1)                                     \
    asm volatile(                                                              \
        "mma.sync.aligned.m16n8k16.row.col.f32.f16.f16.f32 "                   \
        "{%0,%1,%2,%3}, {%4,%5,%6,%7}, {%8,%9}, {%0,%1,%2,%3};\n"              \
        : "+f"((c)[0]), "+f"((c)[1]), "+f"((c)[2]), "+f"((c)[3])               \
        : "r"(a0), "r"(a1), "r"(a2), "r"(a3), "r"(b0), "r"(b1))

#define LDSM_X4(r0, r1, r2, r3, addr)                                          \
    asm volatile("ldmatrix.sync.aligned.m8n8.x4.shared.b16 {%0,%1,%2,%3}, [%4];" \
        : "=r"(r0), "=r"(r1), "=r"(r2), "=r"(r3) : "r"(addr))

#define LDSM_X4_T(r0, r1, r2, r3, addr)                                        \
    asm volatile("ldmatrix.sync.aligned.m8n8.x4.trans.shared.b16 {%0,%1,%2,%3}, [%4];" \
        : "=r"(r0), "=r"(r1), "=r"(r2), "=r"(r3) : "r"(addr))

// ---------------------------------------------------------------------------
// fp32 -> fp16 conversions
// ---------------------------------------------------------------------------
__global__ void cvt_half(const float* __restrict__ in, __half* __restrict__ out,
                         int n4) {
    int i = blockIdx.x * blockDim.x + threadIdx.x;
    if (i >= n4) return;
    float4 v = *(const float4*)(in + (size_t)i * 4);
    __half2 h01 = __floats2half2_rn(v.x, v.y);
    __half2 h23 = __floats2half2_rn(v.z, v.w);
    uint2 u;
    u.x = *(uint32_t*)&h01;
    u.y = *(uint32_t*)&h23;
    *(uint2*)(out + (size_t)i * 4) = u;
}

__global__ void cvt_w4(const float* __restrict__ w0, const float* __restrict__ w1,
                       const float* __restrict__ w2, const float* __restrict__ w3,
                       __half* __restrict__ o0, __half* __restrict__ o1,
                       __half* __restrict__ o2, __half* __restrict__ o3, int n4) {
    int i = blockIdx.x * blockDim.x + threadIdx.x;
    if (i >= n4) return;
    const float* in;
    __half* out;
    switch (blockIdx.y) {
        case 0:  in = w0; out = o0; break;
        case 1:  in = w1; out = o1; break;
        case 2:  in = w2; out = o2; break;
        default: in = w3; out = o3; break;
    }
    float4 v = *(const float4*)(in + (size_t)i * 4);
    __half2 h01 = __floats2half2_rn(v.x, v.y);
    __half2 h23 = __floats2half2_rn(v.z, v.w);
    uint2 u;
    u.x = *(uint32_t*)&h01;
    u.y = *(uint32_t*)&h23;
    *(uint2*)(out + (size_t)i * 4) = u;
}

// ---------------------------------------------------------------------------
// GEMM core constants (round-7 proven shape): BM=BN=128, BK=32, 128 thr.
// ---------------------------------------------------------------------------
constexpr int HST = 40;                               // halves per smem row
constexpr int GEMM_SMEM_B = 2 * 2 * 128 * HST * 2;    // 40960 bytes

// ---------------------------------------------------------------------------
// Fused QKV projection: z = blockIdx.z selects W (Wq/Wk/Wv) and output.
// z<2: RoPE (+ softmax scale for Q) fused into the epilogue via smem exchange
// (BN=128 == one head, so the (dh, dh+64) pair is intra-CTA).
// ---------------------------------------------------------------------------
__global__ void __launch_bounds__(128) gemm_qkv(
    const __half* __restrict__ A,
    const __half* __restrict__ Bq, const __half* __restrict__ Bk,
    const __half* __restrict__ Bv,
    __half* __restrict__ Qh, __half* __restrict__ Kh, __half* __restrict__ Vh,
    const float* __restrict__ cosp, const float* __restrict__ sinp) {
    extern __shared__ __half hsm[];
    __half* sA = hsm;
    __half* sB = hsm + 2 * 128 * HST;

    const int z = blockIdx.z;
    const __half* B = (z == 0) ? Bq : ((z == 1) ? Bk : Bv);
    const int K = Dc, N = Dc;

    const int tid  = threadIdx.x;
    const int wid  = tid >> 5;
    const int lane = tid & 31;
    const int wm = (wid & 1) * 64;
    const int wn = (wid >> 1) * 64;
    const int gp = lane >> 2;
    const int t4 = lane & 3;
    const int m0 = blockIdx.y * 128;
    const int n0 = blockIdx.x * 128;

    const int arow = (lane & 7) + ((lane >> 3) & 1) * 8;
    const int acol = (lane >> 4) * 8;
    const int brow = (lane & 7) + (lane >> 4) * 8;
    const int bcol = ((lane >> 3) & 1) * 8;

    const int lrow = tid >> 2;
    const int lseg = tid & 3;
    const __half* Ag = A + (size_t)(m0 + lrow) * K + lseg * 8;
    const __half* Bg = B + (size_t)(n0 + lrow) * K + lseg * 8;

    const uint32_t sA_u = (uint32_t)__cvta_generic_to_shared(sA);
    const uint32_t sB_u = (uint32_t)__cvta_generic_to_shared(sB);

    float acc[4][8][4];
#pragma unroll
    for (int im = 0; im < 4; im++)
#pragma unroll
        for (int in_ = 0; in_ < 8; in_++)
#pragma unroll
            for (int r = 0; r < 4; r++) acc[im][in_][r] = 0.f;

    const int nt = K / 32;

    {
#pragma unroll
        for (int p = 0; p < 4; p++) {
            int row = lrow + p * 32;
            CP_ASYNC16(sA_u + (uint32_t)((row * HST + lseg * 8) * 2),
                       Ag + (size_t)p * 32 * K);
            CP_ASYNC16(sB_u + (uint32_t)((row * HST + lseg * 8) * 2),
                       Bg + (size_t)p * 32 * K);
        }
        asm volatile("cp.async.commit_group;\n");
    }

    for (int kt = 0; kt < nt; kt++) {
        const int cur = kt & 1;
        if (kt + 1 < nt) {
            const int nb = cur ^ 1;
            const int k0 = (kt + 1) * 32;
#pragma unroll
            for (int p = 0; p < 4; p++) {
                int row = lrow + p * 32;
                CP_ASYNC16(sA_u + (uint32_t)((((nb * 128) + row) * HST + lseg * 8) * 2),
                           Ag + (size_t)p * 32 * K + k0);
                CP_ASYNC16(sB_u + (uint32_t)((((nb * 128) + row) * HST + lseg * 8) * 2),
                           Bg + (size_t)p * 32 * K + k0);
            }
            asm volatile("cp.async.commit_group;\n");
            asm volatile("cp.async.wait_group 1;\n");
        } else {
            asm volatile("cp.async.wait_group 0;\n");
        }
        __syncthreads();

        const uint32_t cA_u = sA_u + (uint32_t)(cur * 128 * HST * 2);
        const uint32_t cB_u = sB_u + (uint32_t)(cur * 128 * HST * 2);

#pragma unroll
        for (int ks = 0; ks < 2; ks++) {
            const int kk = ks * 16;
            uint32_t af[4][4];
#pragma unroll
            for (int im = 0; im < 4; im++)
                LDSM_X4(af[im][0], af[im][1], af[im][2], af[im][3],
                        cA_u + (uint32_t)(((wm + im * 16 + arow) * HST + kk + acol) * 2));
            uint32_t bf[8][2];
#pragma unroll
            for (int j2 = 0; j2 < 4; j2++)
                LDSM_X4(bf[2 * j2][0], bf[2 * j2][1],
                        bf[2 * j2 + 1][0], bf[2 * j2 + 1][1],
                        cB_u + (uint32_t)(((wn + j2 * 16 + brow) * HST + kk + bcol) * 2));
#pragma unroll
            for (int im = 0; im < 4; im++)
#pragma unroll
                for (int in_ = 0; in_ < 8; in_++)
                    MMA_F16(acc[im][in_], af[im][0], af[im][1], af[im][2],
                            af[im][3], bf[in_][0], bf[in_][1]);
        }
        __syncthreads();
    }

    if (z == 2) {
        // V: plain half output
#pragma unroll
        for (int im = 0; im < 4; im++) {
            const int mA = m0 + wm + im * 16 + gp;
#pragma unroll
            for (int in_ = 0; in_ < 8; in_++) {
                const int n = n0 + wn + in_ * 8 + 2 * t4;
                *(__half2*)(Vh + (size_t)mA * N + n) =
                    __floats2half2_rn(acc[im][in_][0], acc[im][in_][1]);
                *(__half2*)(Vh + (size_t)(mA + 8) * N + n) =
                    __floats2half2_rn(acc[im][in_][2], acc[im][in_][3]);
            }
        }
        return;
    }

    // ---- RoPE epilogue (Q/K). Warps with wn==64 (dh in [64,128)) stage their
    // fp32 accumulators into smem; warps with wn==0 combine pairs and write
    // both rotated halves. cos[dh]==cos[dh+64], sin[dh]==sin[dh+64].
    float* sf = (float*)hsm;   // [128][68] fp32 = 34816 B <= 40960 B
    if (wn == 64) {
#pragma unroll
        for (int im = 0; im < 4; im++) {
            int row = wm + im * 16 + gp;
#pragma unroll
            for (int in_ = 0; in_ < 8; in_++) {
                int col = in_ * 8 + 2 * t4;       // dh - 64
                sf[row * 68 + col]           = acc[im][in_][0];
                sf[row * 68 + col + 1]       = acc[im][in_][1];
                sf[(row + 8) * 68 + col]     = acc[im][in_][2];
                sf[(row + 8) * 68 + col + 1] = acc[im][in_][3];
            }
        }
    }
    __syncthreads();
    if (wn == 0) {
        const float scale = (z == 0) ? 0.08838834764831845f : 1.0f;
        __half* Out = (z == 0) ? Qh : Kh;
#pragma unroll
        for (int im = 0; im < 4; im++) {
            int row = wm + im * 16 + gp;          // local row 0..127
            int sAi = (m0 + row) & (Sc - 1);
            int sBi = (m0 + row + 8) & (Sc - 1);
#pragma unroll
            for (int in_ = 0; in_ < 8; in_++) {
                int col = in_ * 8 + 2 * t4;       // dh in [0,64), even
                float2 cA  = *(const float2*)(cosp + sAi * DHc + col);
                float2 snA = *(const float2*)(sinp + sAi * DHc + col);
                float2 cB  = *(const float2*)(cosp + sBi * DHc + col);
                float2 snB = *(const float2*)(sinp + sBi * DHc + col);
                float a0 = acc[im][in_][0], a1 = acc[im][in_][1];
                float a2 = acc[im][in_][2], a3 = acc[im][in_][3];
                float b0 = sf[row * 68 + col],       b1 = sf[row * 68 + col + 1];
                float b2 = sf[(row + 8) * 68 + col], b3 = sf[(row + 8) * 68 + col + 1];
                __half2 loA = __floats2half2_rn(scale * (a0 * cA.x - b0 * snA.x),
                                                scale * (a1 * cA.y - b1 * snA.y));
                __half2 hiA = __floats2half2_rn(scale * (b0 * cA.x + a0 * snA.x),
                                                scale * (b1 * cA.y + a1 * snA.y));
                __half2 loB = __floats2half2_rn(scale * (a2 * cB.x - b2 * snB.x),
                                                scale * (a3 * cB.y - b3 * snB.y));
                __half2 hiB = __floats2half2_rn(scale * (b2 * cB.x + a2 * snB.x),
                                                scale * (b3 * cB.y + a3 * snB.y));
                size_t gr = (size_t)(m0 + row) * Dc + n0 + col;
                *(__half2*)(Out + gr)                      = loA;
                *(__half2*)(Out + gr + 64)                 = hiA;
                *(__half2*)(Out + gr + (size_t)8 * Dc)      = loB;
                *(__half2*)(Out + gr + (size_t)8 * Dc + 64) = hiB;
            }
        }
    }
}

// ---------------------------------------------------------------------------
// Plain fp16 GEMM for the O projection (round-7 exact shape, fp32 out).
// ---------------------------------------------------------------------------
__global__ void __launch_bounds__(128) gemm_f16(const __half* __restrict__ A,
                                                const __half* __restrict__ B,
                                                float* __restrict__ Cf,
                                                int M, int N, int K) {
    extern __shared__ __half hsm[];
    __half* sA = hsm;
    __half* sB = hsm + 2 * 128 * HST;

    const int tid  = threadIdx.x;
    const int wid  = tid >> 5;
    const int lane = tid & 31;
    const int wm = (wid & 1) * 64;
    const int wn = (wid >> 1) * 64;
    const int gp = lane >> 2;
    const int t4 = lane & 3;
    const int m0 = blockIdx.y * 128;
    const int n0 = blockIdx.x * 128;

    const int arow = (lane & 7) + ((lane >> 3) & 1) * 8;
    const int acol = (lane >> 4) * 8;
    const int brow = (lane & 7) + (lane >> 4) * 8;
    const int bcol = ((lane >> 3) & 1) * 8;

    const int lrow = tid >> 2;
    const int lseg = tid & 3;
    const __half* Ag = A + (size_t)(m0 + lrow) * K + lseg * 8;
    const __half* Bg = B + (size_t)(n0 + lrow) * K + lseg * 8;

    const uint32_t sA_u = (uint32_t)__cvta_generic_to_shared(sA);
    const uint32_t sB_u = (uint32_t)__cvta_generic_to_shared(sB);

    float acc[4][8][4];
#pragma unroll
    for (int im = 0; im < 4; im++)
#pragma unroll
        for (int in_ = 0; in_ < 8; in_++)
#pragma unroll
            for (int r = 0; r < 4; r++) acc[im][in_][r] = 0.f;

    const int nt = K / 32;

    {
#pragma unroll
        for (int p = 0; p < 4; p++) {
            int row = lrow + p * 32;
            CP_ASYNC16(sA_u + (uint32_t)((row * HST + lseg * 8) * 2),
                       Ag + (size_t)p * 32 * K);
            CP_ASYNC16(sB_u + (uint32_t)((row * HST + lseg * 8) * 2),
                       Bg + (size_t)p * 32 * K);
        }
        asm volatile("cp.async.commit_group;\n");
    }

    for (int kt = 0; kt < nt; kt++) {
        const int cur = kt & 1;
        if (kt + 1 < nt) {
            const int nb = cur ^ 1;
            const int k0 = (kt + 1) * 32;
#pragma unroll
            for (int p = 0; p < 4; p++) {
                int row = lrow + p * 32;
                CP_ASYNC16(sA_u + (uint32_t)((((nb * 128) + row) * HST + lseg * 8) * 2),
                           Ag + (size_t)p * 32 * K + k0);
                CP_ASYNC16(sB_u + (uint32_t)((((nb * 128) + row) * HST + lseg * 8) * 2),
                           Bg + (size_t)p * 32 * K + k0);
            }
            asm volatile("cp.async.commit_group;\n");
            asm volatile("cp.async.wait_group 1;\n");
        } else {
            asm volatile("cp.async.wait_group 0;\n");
        }
        __syncthreads();

        const uint32_t cA_u = sA_u + (uint32_t)(cur * 128 * HST * 2);
        const uint32_t cB_u = sB_u + (uint32_t)(cur * 128 * HST * 2);

#pragma unroll
        for (int ks = 0; ks < 2; ks++) {
            const int kk = ks * 16;
            uint32_t af[4][4];
#pragma unroll
            for (int im = 0; im < 4; im++)
                LDSM_X4(af[im][0], af[im][1], af[im][2], af[im][3],
                        cA_u + (uint32_t)(((wm + im * 16 + arow) * HST + kk + acol) * 2));
            uint32_t bf[8][2];
#pragma unroll
            for (int j2 = 0; j2 < 4; j2++)
                LDSM_X4(bf[2 * j2][0], bf[2 * j2][1],
                        bf[2 * j2 + 1][0], bf[2 * j2 + 1][1],
                        cB_u + (uint32_t)(((wn + j2 * 16 + brow) * HST + kk + bcol) * 2));
#pragma unroll
            for (int im = 0; im < 4; im++)
#pragma unroll
                for (int in_ = 0; in_ < 8; in_++)
                    MMA_F16(acc[im][in_], af[im][0], af[im][1], af[im][2],
                            af[im][3], bf[in_][0], bf[in_][1]);
        }
        __syncthreads();
    }

#pragma unroll
    for (int im = 0; im < 4; im++) {
        const int mA = m0 + wm + im * 16 + gp;
#pragma unroll
        for (int in_ = 0; in_ < 8; in_++) {
            const int n = n0 + wn + in_ * 8 + 2 * t4;
            *(float2*)(Cf + (size_t)mA * N + n) =
                make_float2(acc[im][in_][0], acc[im][in_][1]);
            *(float2*)(Cf + (size_t)(mA + 8) * N + n) =
                make_float2(acc[im][in_][2], acc[im][in_][3]);
        }
    }
}

// ---------------------------------------------------------------------------
// Flash attention (round-7 proven shape): BM=BN=64, 128 thr / 4 warps,
// all-fp16 mma, fp32 softmax/accum, ldmatrix (+trans for V).
// ---------------------------------------------------------------------------
constexpr int QSH = 136;
constexpr int KSH = 136;
constexpr int VSH = 136;
constexpr int PSH = 72;
constexpr int OFF_Q  = 0;
constexpr int OFF_K0 = OFF_Q  + 64 * QSH * 2;
constexpr int OFF_K1 = OFF_K0 + 64 * KSH * 2;
constexpr int OFF_V  = OFF_K1 + 64 * KSH * 2;
constexpr int OFF_P  = OFF_V  + 64 * VSH * 2;
constexpr int FL_SMEM_B = OFF_P + 64 * PSH * 2;      // 78848

__global__ void __launch_bounds__(128) flash_tc(const __half* __restrict__ Q,
                                                const __half* __restrict__ K,
                                                const __half* __restrict__ V,
                                                __half* __restrict__ O) {
    extern __shared__ char smraw[];
    __half* sP = (__half*)(smraw + OFF_P);
    const uint32_t sQ_u  = (uint32_t)__cvta_generic_to_shared(smraw + OFF_Q);
    const uint32_t sK0_u = (uint32_t)__cvta_generic_to_shared(smraw + OFF_K0);
    const uint32_t sK1_u = (uint32_t)__cvta_generic_to_shared(smraw + OFF_K1);
    const uint32_t sV_u  = (uint32_t)__cvta_generic_to_shared(smraw + OFF_V);
    const uint32_t sP_u  = (uint32_t)__cvta_generic_to_shared(sP);

    const int tid  = threadIdx.x;
    const int wid  = tid >> 5;
    const int lane = tid & 31;
    const int gp   = lane >> 2;
    const int t4   = lane & 3;
    const int qb   = blockIdx.x;
    const int bh   = blockIdx.y;
    const int b    = bh >> 4;
    const int h    = bh & (Hc - 1);
    const size_t base = ((size_t)b * Sc) * Dc + (size_t)h * DHc;
    const int q0   = qb * 64;
    const int wrow = wid * 16;
    const int r0loc = wrow + gp;
    const int r1loc = r0loc + 8;

    const int arow = (lane & 7) + ((lane >> 3) & 1) * 8;
    const int acol = (lane >> 4) * 8;
    const int brow = (lane & 7) + (lane >> 4) * 8;
    const int bcol = ((lane >> 3) & 1) * 8;
    const int vrow = (lane & 7) + ((lane >> 3) & 1) * 8;
    const int vcol = (lane >> 4) * 8;

    {
#pragma unroll
        for (int p = 0; p < 8; p++) {
            int idx = tid + p * 128;
            int r = idx >> 4, sg = (idx & 15) * 8;
            CP_ASYNC16(sQ_u + (uint32_t)((r * QSH + sg) * 2),
                       Q + base + (size_t)(q0 + r) * Dc + sg);
        }
#pragma unroll
        for (int p = 0; p < 8; p++) {
            int idx = tid + p * 128;
            int r = idx >> 4, sg = (idx & 15) * 8;
            CP_ASYNC16(sK0_u + (uint32_t)((r * KSH + sg) * 2),
                       K + base + (size_t)r * Dc + sg);
        }
        asm volatile("cp.async.commit_group;\n");
#pragma unroll
        for (int p = 0; p < 8; p++) {
            int idx = tid + p * 128;
            int r = idx >> 4, sg = (idx & 15) * 8;
            CP_ASYNC16(sV_u + (uint32_t)((r * VSH + sg) * 2),
                       V + base + (size_t)r * Dc + sg);
        }
        asm volatile("cp.async.commit_group;\n");
    }

    float o[16][4];
#pragma unroll
    for (int n = 0; n < 16; n++)
#pragma unroll
        for (int r = 0; r < 4; r++) o[n][r] = 0.f;
    float m0 = -1e30f, m1 = -1e30f, l0 = 0.f, l1 = 0.f;

    for (int j = 0; j <= qb; ++j) {
        const uint32_t sKc_u = (j & 1) ? sK1_u : sK0_u;
        const uint32_t sKn_u = (j & 1) ? sK0_u : sK1_u;

        asm volatile("cp.async.wait_group 1;\n");
        __syncthreads();

        float sacc[8][4];
#pragma unroll
        for (int n = 0; n < 8; n++)
#pragma unroll
            for (int r = 0; r < 4; r++) sacc[n][r] = 0.f;

#pragma unroll
        for (int kk8 = 0; kk8 < 8; kk8++) {
            const int kk = kk8 * 16;
            uint32_t a0, a1, a2, a3;
            LDSM_X4(a0, a1, a2, a3,
                    sQ_u + (uint32_t)(((wrow + arow) * QSH + kk + acol) * 2));
            uint32_t bf[8][2];
#pragma unroll
            for (int j2 = 0; j2 < 4; j2++)
                LDSM_X4(bf[2 * j2][0], bf[2 * j2][1],
                        bf[2 * j2 + 1][0], bf[2 * j2 + 1][1],
                        sKc_u + (uint32_t)(((j2 * 16 + brow) * KSH + kk + bcol) * 2));
#pragma unroll
            for (int nt = 0; nt < 8; nt++)
                MMA_F16(sacc[nt], a0, a1, a2, a3, bf[nt][0], bf[nt][1]);
        }

        if (j == qb) {
#pragma unroll
            for (int nt = 0; nt < 8; nt++) {
                int c0 = nt * 8 + 2 * t4;
                if (c0 > r0loc)     sacc[nt][0] = -1e30f;
                if (c0 + 1 > r0loc) sacc[nt][1] = -1e30f;
                if (c0 > r1loc)     sacc[nt][2] = -1e30f;
                if (c0 + 1 > r1loc) sacc[nt][3] = -1e30f;
            }
        }

        float mx0 = -1e30f, mx1 = -1e30f;
#pragma unroll
        for (int nt = 0; nt < 8; nt++) {
            mx0 = fmaxf(mx0, fmaxf(sacc[nt][0], sacc[nt][1]));
            mx1 = fmaxf(mx1, fmaxf(sacc[nt][2], sacc[nt][3]));
        }
        mx0 = fmaxf(mx0, __shfl_xor_sync(0xffffffff, mx0, 1));
        mx0 = fmaxf(mx0, __shfl_xor_sync(0xffffffff, mx0, 2));
        mx1 = fmaxf(mx1, __shfl_xor_sync(0xffffffff, mx1, 1));
        mx1 = fmaxf(mx1, __shfl_xor_sync(0xffffffff, mx1, 2));

        float m0n = fmaxf(m0, mx0);
        float m1n = fmaxf(m1, mx1);
        float corr0 = __expf(m0 - m0n);
        float corr1 = __expf(m1 - m1n);
        m0 = m0n; m1 = m1n;

        float ls0 = 0.f, ls1 = 0.f;
#pragma unroll
        for (int nt = 0; nt < 8; nt++) {
            float p0 = __expf(sacc[nt][0] - m0);
            float p1 = __expf(sacc[nt][1] - m0);
            float p2 = __expf(sacc[nt][2] - m1);
            float p3 = __expf(sacc[nt][3] - m1);
            ls0 += p0 + p1;
            ls1 += p2 + p3;
            int c0 = nt * 8 + 2 * t4;
            *(__half2*)(sP + r0loc * PSH + c0) = __floats2half2_rn(p0, p1);
            *(__half2*)(sP + r1loc * PSH + c0) = __floats2half2_rn(p2, p3);
        }
        ls0 += __shfl_xor_sync(0xffffffff, ls0, 1);
        ls0 += __shfl_xor_sync(0xffffffff, ls0, 2);
        ls1 += __shfl_xor_sync(0xffffffff, ls1, 1);
        ls1 += __shfl_xor_sync(0xffffffff, ls1, 2);
        l0 = l0 * corr0 + ls0;
        l1 = l1 * corr1 + ls1;

#pragma unroll
        for (int nt = 0; nt < 16; nt++) {
            o[nt][0] *= corr0; o[nt][1] *= corr0;
            o[nt][2] *= corr1; o[nt][3] *= corr1;
        }

        if (j < qb) {
            const int k0n = (j + 1) * 64;
#pragma unroll
            for (int p = 0; p < 8; p++) {
                int idx = tid + p * 128;
                int r = idx >> 4, sg = (idx & 15) * 8;
                CP_ASYNC16(sKn_u + (uint32_t)((r * KSH + sg) * 2),
                           K + base + (size_t)(k0n + r) * Dc + sg);
            }
            asm volatile("cp.async.commit_group;\n");
            asm volatile("cp.async.wait_group 1;\n");
        } else {
            asm volatile("cp.async.wait_group 0;\n");
        }
        __syncthreads();

#pragma unroll
        for (int ks = 0; ks < 4; ks++) {
            const int kk = ks * 16;
            uint32_t a0, a1, a2, a3;
            LDSM_X4(a0, a1, a2, a3,
                    sP_u + (uint32_t)(((wrow + arow) * PSH + kk + acol) * 2));
#pragma unroll
            for (int j2 = 0; j2 < 8; j2++) {
                uint32_t b00, b01, b10, b11;
                LDSM_X4_T(b00, b01, b10, b11,
                    sV_u + (uint32_t)(((kk + vrow) * VSH + j2 * 16 + vcol) * 2));
                MMA_F16(o[2 * j2],     a0, a1, a2, a3, b00, b01);
                MMA_F16(o[2 * j2 + 1], a0, a1, a2, a3, b10, b11);
            }
        }
        __syncthreads();

        if (j < qb) {
            const int k0n = (j + 1) * 64;
#pragma unroll
            for (int p = 0; p < 8; p++) {
                int idx = tid + p * 128;
                int r = idx >> 4, sg = (idx & 15) * 8;
                CP_ASYNC16(sV_u + (uint32_t)((r * VSH + sg) * 2),
                           V + base + (size_t)(k0n + r) * Dc + sg);
            }
            asm volatile("cp.async.commit_group;\n");
        }
    }

    float inv0 = 1.0f / l0, inv1 = 1.0f / l1;
    const size_t row0 = base + (size_t)(q0 + r0loc) * Dc;
    const size_t row1 = base + (size_t)(q0 + r1loc) * Dc;
#pragma unroll
    for (int nt = 0; nt < 16; nt++) {
        int c0 = nt * 8 + 2 * t4;
        *(__half2*)(O + row0 + c0) =
            __floats2half2_rn(o[nt][0] * inv0, o[nt][1] * inv0);
        *(__half2*)(O + row1 + c0) =
            __floats2half2_rn(o[nt][2] * inv1, o[nt][3] * inv1);
    }
}

// ---------------------------------------------------------------------------
// Launch
// ---------------------------------------------------------------------------
extern "C" void kernel_launch(void* const* d_in, const int* in_sizes, int n_in,
                              void* d_out, int out_size) {
    const float* x    = (const float*)d_in[0];
    const float* cosp = (const float*)d_in[1];
    const float* sinp = (const float*)d_in[2];
    const float* Wq   = (const float*)d_in[3];
    const float* Wk   = (const float*)d_in[4];
    const float* Wv   = (const float*)d_in[5];
    const float* Wo   = (const float*)d_in[6];
    float* out = (float*)d_out;

    __half *Vh, *xh, *Qh, *Kh, *Ah, *wqh, *wkh, *wvh, *woh;
    cudaGetSymbolAddress((void**)&Vh, g_Vh);
    cudaGetSymbolAddress((void**)&xh, g_xh);
    cudaGetSymbolAddress((void**)&Qh, g_Qh);
    cudaGetSymbolAddress((void**)&Kh, g_Kh);
    cudaGetSymbolAddress((void**)&Ah, g_Ah);
    cudaGetSymbolAddress((void**)&wqh, g_wqh);
    cudaGetSymbolAddress((void**)&wkh, g_wkh);
    cudaGetSymbolAddress((void**)&wvh, g_wvh);
    cudaGetSymbolAddress((void**)&woh, g_woh);

    cudaFuncSetAttribute(gemm_qkv, cudaFuncAttributeMaxDynamicSharedMemorySize,
                         GEMM_SMEM_B);
    cudaFuncSetAttribute(gemm_f16, cudaFuncAttributeMaxDynamicSharedMemorySize,
                         GEMM_SMEM_B);
    cudaFuncSetAttribute(flash_tc, cudaFuncAttributeMaxDynamicSharedMemorySize,
                         FL_SMEM_B);

    // fp16 conversions of GEMM inputs (x + all four W in 2 launches)
    {
        const int nx = Mc * Dc / 4, nw = Dc * Dc / 4;
        cvt_half<<<(nx + 255) / 256, 256>>>(x, xh, nx);
        dim3 wgrid((nw + 255) / 256, 4);
        cvt_w4<<<wgrid, 256>>>(Wq, Wk, Wv, Wo, wqh, wkh, wvh, woh, nw);
    }

    // fused QKV projections + RoPE/scale epilogue
    {
        dim3 qgrid(Dc / 128, Mc / 128, 3);   // (16, 32, 3)
        gemm_qkv<<<qgrid, 128, GEMM_SMEM_B>>>(xh, wqh, wkh, wvh,
                                              Qh, Kh, Vh, cosp, sinp);
    }

    // flash attention (round-7 proven shape)
    {
        dim3 fgrid(Sc / 64, Bc * Hc);   // (32, 32)
        flash_tc<<<fgrid, 128, FL_SMEM_B>>>(Qh, Kh, Vh, Ah);
    }

    // O projection (fp32 out)
    {
        dim3 ggrid(Dc / 128, Mc / 128);   // (16, 32)
        gemm_f16<<<ggrid, 128, GEMM_SMEM_B>>>(Ah, woh, out, Mc, Dc, Dc);
    }
}

// round 11
// speedup vs baseline: 1.1134x; 1.0271x over previous
#include <cuda_runtime.h>
#include <cuda_fp16.h>
#include <math.h>
#include <stdint.h>

// Problem constants
constexpr int Bc  = 2;
constexpr int Sc  = 2048;
constexpr int Dc  = 2048;
constexpr int Hc  = 16;
constexpr int DHc = 128;
constexpr int Mc  = Bc * Sc;   // 4096 rows for projections

// ---------------------------------------------------------------------------
// Scratch (device globals: allocation-free per harness rules)
// ---------------------------------------------------------------------------
__device__ __half g_Vh [(size_t)Mc * Dc];      // half V
__device__ __half g_xh [(size_t)Mc * Dc];
__device__ __half g_Qh [(size_t)Mc * Dc];      // roped + softmax-scaled
__device__ __half g_Kh [(size_t)Mc * Dc];      // roped
__device__ __half g_Ah [(size_t)Mc * Dc];      // attention out (half)
__device__ __half g_wqh[(size_t)Dc * Dc];
__device__ __half g_wkh[(size_t)Dc * Dc];
__device__ __half g_wvh[(size_t)Dc * Dc];
__device__ __half g_woh[(size_t)Dc * Dc];

#define CP_ASYNC16(dst, src) \
    asm volatile("cp.async.cg.shared.global [%0], [%1], 16;\n" :: "r"(dst), "l"(src))

#define MMA_F16(c, a0, a1, a2, a3, b0, b1)                                     \
    asm volatile(                                                              \
        "mma.sync.aligned.m16n8k16.row.col.f32.f16.f16.f32 "                   \
        "{%0,%1,%2,%3}, {%4,%5,%6,%7}, {%8,%9}, {%0,%1,%2,%3};\n"              \
        : "+f"((c)[0]), "+f"((c)[1]), "+f"((c)[2]), "+f"((c)[3])               \
        : "r"(a0), "r"(a1), "r"(a2), "r"(a3), "r"(b0), "r"(b1))

#define LDSM_X4(r0, r1, r2, r3, addr)                                          \
    asm volatile("ldmatrix.sync.aligned.m8n8.x4.shared.b16 {%0,%1,%2,%3}, [%4];" \
        : "=r"(r0), "=r"(r1), "=r"(r2), "=r"(r3) : "r"(addr))

#define LDSM_X4_T(r0, r1, r2, r3, addr)                                        \
    asm volatile("ldmatrix.sync.aligned.m8n8.x4.trans.shared.b16 {%0,%1,%2,%3}, [%4];" \
        : "=r"(r0), "=r"(r1), "=r"(r2), "=r"(r3) : "r"(addr))

// 16B-granular XOR swizzles (byte offsets). Row widths: 16 segs (QKV), 8 (P).
__device__ __forceinline__ uint32_t swz16(int row, int seg) {
    return (uint32_t)((row * 16 + (seg ^ (row & 7))) << 4);
}
__device__ __forceinline__ uint32_t swz8(int row, int seg) {
    return (uint32_t)((row * 8 + (seg ^ (row & 7))) << 4);
}

// ---------------------------------------------------------------------------
// fp32 -> fp16 conversions
// ---------------------------------------------------------------------------
__global__ void cvt_half(const float* __restrict__ in, __half* __restrict__ out,
                         int n4) {
    int i = blockIdx.x * blockDim.x + threadIdx.x;
    if (i >= n4) return;
    float4 v = *(const float4*)(in + (size_t)i * 4);
    __half2 h01 = __floats2half2_rn(v.x, v.y);
    __half2 h23 = __floats2half2_rn(v.z, v.w);
    uint2 u;
    u.x = *(uint32_t*)&h01;
    u.y = *(uint32_t*)&h23;
    *(uint2*)(out + (size_t)i * 4) = u;
}

__global__ void cvt_w4(const float* __restrict__ w0, const float* __restrict__ w1,
                       const float* __restrict__ w2, const float* __restrict__ w3,
                       __half* __restrict__ o0, __half* __restrict__ o1,
                       __half* __restrict__ o2, __half* __restrict__ o3, int n4) {
    int i = blockIdx.x * blockDim.x + threadIdx.x;
    if (i >= n4) return;
    const float* in;
    __half* out;
    switch (blockIdx.y) {
        case 0:  in = w0; out = o0; break;
        case 1:  in = w1; out = o1; break;
        case 2:  in = w2; out = o2; break;
        default: in = w3; out = o3; break;
    }
    float4 v = *(const float4*)(in + (size_t)i * 4);
    __half2 h01 = __floats2half2_rn(v.x, v.y);
    __half2 h23 = __floats2half2_rn(v.z, v.w);
    uint2 u;
    u.x = *(uint32_t*)&h01;
    u.y = *(uint32_t*)&h23;
    *(uint2*)(out + (size_t)i * 4) = u;
}

// ---------------------------------------------------------------------------
// GEMM core constants (round-7 proven shape): BM=BN=128, BK=32, 128 thr.
// ---------------------------------------------------------------------------
constexpr int HST = 40;                               // halves per smem row
constexpr int GEMM_SMEM_B = 2 * 2 * 128 * HST * 2;    // 40960 bytes

// ---------------------------------------------------------------------------
// Fused QKV projection: z = blockIdx.z selects W (Wq/Wk/Wv) and output.
// z<2: RoPE (+ softmax scale for Q) fused into the epilogue via smem exchange.
// ---------------------------------------------------------------------------
__global__ void __launch_bounds__(128) gemm_qkv(
    const __half* __restrict__ A,
    const __half* __restrict__ Bq, const __half* __restrict__ Bk,
    const __half* __restrict__ Bv,
    __half* __restrict__ Qh, __half* __restrict__ Kh, __half* __restrict__ Vh,
    const float* __restrict__ cosp, const float* __restrict__ sinp) {
    extern __shared__ __half hsm[];
    __half* sA = hsm;
    __half* sB = hsm + 2 * 128 * HST;

    const int z = blockIdx.z;
    const __half* B = (z == 0) ? Bq : ((z == 1) ? Bk : Bv);
    const int K = Dc, N = Dc;

    const int tid  = threadIdx.x;
    const int wid  = tid >> 5;
    const int lane = tid & 31;
    const int wm = (wid & 1) * 64;
    const int wn = (wid >> 1) * 64;
    const int gp = lane >> 2;
    const int t4 = lane & 3;
    const int m0 = blockIdx.y * 128;
    const int n0 = blockIdx.x * 128;

    const int arow = (lane & 7) + ((lane >> 3) & 1) * 8;
    const int acol = (lane >> 4) * 8;
    const int brow = (lane & 7) + (lane >> 4) * 8;
    const int bcol = ((lane >> 3) & 1) * 8;

    const int lrow = tid >> 2;
    const int lseg = tid & 3;
    const __half* Ag = A + (size_t)(m0 + lrow) * K + lseg * 8;
    const __half* Bg = B + (size_t)(n0 + lrow) * K + lseg * 8;

    const uint32_t sA_u = (uint32_t)__cvta_generic_to_shared(sA);
    const uint32_t sB_u = (uint32_t)__cvta_generic_to_shared(sB);

    float acc[4][8][4];
#pragma unroll
    for (int im = 0; im < 4; im++)
#pragma unroll
        for (int in_ = 0; in_ < 8; in_++)
#pragma unroll
            for (int r = 0; r < 4; r++) acc[im][in_][r] = 0.f;

    const int nt = K / 32;

    {
#pragma unroll
        for (int p = 0; p < 4; p++) {
            int row = lrow + p * 32;
            CP_ASYNC16(sA_u + (uint32_t)((row * HST + lseg * 8) * 2),
                       Ag + (size_t)p * 32 * K);
            CP_ASYNC16(sB_u + (uint32_t)((row * HST + lseg * 8) * 2),
                       Bg + (size_t)p * 32 * K);
        }
        asm volatile("cp.async.commit_group;\n");
    }

    for (int kt = 0; kt < nt; kt++) {
        const int cur = kt & 1;
        if (kt + 1 < nt) {
            const int nb = cur ^ 1;
            const int k0 = (kt + 1) * 32;
#pragma unroll
            for (int p = 0; p < 4; p++) {
                int row = lrow + p * 32;
                CP_ASYNC16(sA_u + (uint32_t)((((nb * 128) + row) * HST + lseg * 8) * 2),
                           Ag + (size_t)p * 32 * K + k0);
                CP_ASYNC16(sB_u + (uint32_t)((((nb * 128) + row) * HST + lseg * 8) * 2),
                           Bg + (size_t)p * 32 * K + k0);
            }
            asm volatile("cp.async.commit_group;\n");
            asm volatile("cp.async.wait_group 1;\n");
        } else {
            asm volatile("cp.async.wait_group 0;\n");
        }
        __syncthreads();

        const uint32_t cA_u = sA_u + (uint32_t)(cur * 128 * HST * 2);
        const uint32_t cB_u = sB_u + (uint32_t)(cur * 128 * HST * 2);

#pragma unroll
        for (int ks = 0; ks < 2; ks++) {
            const int kk = ks * 16;
            uint32_t af[4][4];
#pragma unroll
            for (int im = 0; im < 4; im++)
                LDSM_X4(af[im][0], af[im][1], af[im][2], af[im][3],
                        cA_u + (uint32_t)(((wm + im * 16 + arow) * HST + kk + acol) * 2));
            uint32_t bf[8][2];
#pragma unroll
            for (int j2 = 0; j2 < 4; j2++)
                LDSM_X4(bf[2 * j2][0], bf[2 * j2][1],
                        bf[2 * j2 + 1][0], bf[2 * j2 + 1][1],
                        cB_u + (uint32_t)(((wn + j2 * 16 + brow) * HST + kk + bcol) * 2));
#pragma unroll
            for (int im = 0; im < 4; im++)
#pragma unroll
                for (int in_ = 0; in_ < 8; in_++)
                    MMA_F16(acc[im][in_], af[im][0], af[im][1], af[im][2],
                            af[im][3], bf[in_][0], bf[in_][1]);
        }
        __syncthreads();
    }

    if (z == 2) {
#pragma unroll
        for (int im = 0; im < 4; im++) {
            const int mA = m0 + wm + im * 16 + gp;
#pragma unroll
            for (int in_ = 0; in_ < 8; in_++) {
                const int n = n0 + wn + in_ * 8 + 2 * t4;
                *(__half2*)(Vh + (size_t)mA * N + n) =
                    __floats2half2_rn(acc[im][in_][0], acc[im][in_][1]);
                *(__half2*)(Vh + (size_t)(mA + 8) * N + n) =
                    __floats2half2_rn(acc[im][in_][2], acc[im][in_][3]);
            }
        }
        return;
    }

    // RoPE epilogue (Q/K) via smem exchange.
    float* sf = (float*)hsm;   // [128][68] fp32
    if (wn == 64) {
#pragma unroll
        for (int im = 0; im < 4; im++) {
            int row = wm + im * 16 + gp;
#pragma unroll
            for (int in_ = 0; in_ < 8; in_++) {
                int col = in_ * 8 + 2 * t4;
                sf[row * 68 + col]           = acc[im][in_][0];
                sf[row * 68 + col + 1]       = acc[im][in_][1];
                sf[(row + 8) * 68 + col]     = acc[im][in_][2];
                sf[(row + 8) * 68 + col + 1] = acc[im][in_][3];
            }
        }
    }
    __syncthreads();
    if (wn == 0) {
        const float scale = (z == 0) ? 0.08838834764831845f : 1.0f;
        __half* Out = (z == 0) ? Qh : Kh;
#pragma unroll
        for (int im = 0; im < 4; im++) {
            int row = wm + im * 16 + gp;
            int sAi = (m0 + row) & (Sc - 1);
            int sBi = (m0 + row + 8) & (Sc - 1);
#pragma unroll
            for (int in_ = 0; in_ < 8; in_++) {
                int col = in_ * 8 + 2 * t4;
                float2 cA  = *(const float2*)(cosp + sAi * DHc + col);
                float2 snA = *(const float2*)(sinp + sAi * DHc + col);
                float2 cB  = *(const float2*)(cosp + sBi * DHc + col);
                float2 snB = *(const float2*)(sinp + sBi * DHc + col);
                float a0 = acc[im][in_][0], a1 = acc[im][in_][1];
                float a2 = acc[im][in_][2], a3 = acc[im][in_][3];
                float b0 = sf[row * 68 + col],       b1 = sf[row * 68 + col + 1];
                float b2 = sf[(row + 8) * 68 + col], b3 = sf[(row + 8) * 68 + col + 1];
                __half2 loA = __floats2half2_rn(scale * (a0 * cA.x - b0 * snA.x),
                                                scale * (a1 * cA.y - b1 * snA.y));
                __half2 hiA = __floats2half2_rn(scale * (b0 * cA.x + a0 * snA.x),
                                                scale * (b1 * cA.y + a1 * snA.y));
                __half2 loB = __floats2half2_rn(scale * (a2 * cB.x - b2 * snB.x),
                                                scale * (a3 * cB.y - b3 * snB.y));
                __half2 hiB = __floats2half2_rn(scale * (b2 * cB.x + a2 * snB.x),
                                                scale * (b3 * cB.y + a3 * snB.y));
                size_t gr = (size_t)(m0 + row) * Dc + n0 + col;
                *(__half2*)(Out + gr)                      = loA;
                *(__half2*)(Out + gr + 64)                 = hiA;
                *(__half2*)(Out + gr + (size_t)8 * Dc)      = loB;
                *(__half2*)(Out + gr + (size_t)8 * Dc + 64) = hiB;
            }
        }
    }
}

// ---------------------------------------------------------------------------
// Plain fp16 GEMM for the O projection (fp32 out).
// ---------------------------------------------------------------------------
__global__ void __launch_bounds__(128) gemm_f16(const __half* __restrict__ A,
                                                const __half* __restrict__ B,
                                                float* __restrict__ Cf,
                                                int M, int N, int K) {
    extern __shared__ __half hsm[];
    __half* sA = hsm;
    __half* sB = hsm + 2 * 128 * HST;

    const int tid  = threadIdx.x;
    const int wid  = tid >> 5;
    const int lane = tid & 31;
    const int wm = (wid & 1) * 64;
    const int wn = (wid >> 1) * 64;
    const int gp = lane >> 2;
    const int t4 = lane & 3;
    const int m0 = blockIdx.y * 128;
    const int n0 = blockIdx.x * 128;

    const int arow = (lane & 7) + ((lane >> 3) & 1) * 8;
    const int acol = (lane >> 4) * 8;
    const int brow = (lane & 7) + (lane >> 4) * 8;
    const int bcol = ((lane >> 3) & 1) * 8;

    const int lrow = tid >> 2;
    const int lseg = tid & 3;
    const __half* Ag = A + (size_t)(m0 + lrow) * K + lseg * 8;
    const __half* Bg = B + (size_t)(n0 + lrow) * K + lseg * 8;

    const uint32_t sA_u = (uint32_t)__cvta_generic_to_shared(sA);
    const uint32_t sB_u = (uint32_t)__cvta_generic_to_shared(sB);

    float acc[4][8][4];
#pragma unroll
    for (int im = 0; im < 4; im++)
#pragma unroll
        for (int in_ = 0; in_ < 8; in_++)
#pragma unroll
            for (int r = 0; r < 4; r++) acc[im][in_][r] = 0.f;

    const int nt = K / 32;

    {
#pragma unroll
        for (int p = 0; p < 4; p++) {
            int row = lrow + p * 32;
            CP_ASYNC16(sA_u + (uint32_t)((row * HST + lseg * 8) * 2),
                       Ag + (size_t)p * 32 * K);
            CP_ASYNC16(sB_u + (uint32_t)((row * HST + lseg * 8) * 2),
                       Bg + (size_t)p * 32 * K);
        }
        asm volatile("cp.async.commit_group;\n");
    }

    for (int kt = 0; kt < nt; kt++) {
        const int cur = kt & 1;
        if (kt + 1 < nt) {
            const int nb = cur ^ 1;
            const int k0 = (kt + 1) * 32;
#pragma unroll
            for (int p = 0; p < 4; p++) {
                int row = lrow + p * 32;
                CP_ASYNC16(sA_u + (uint32_t)((((nb * 128) + row) * HST + lseg * 8) * 2),
                           Ag + (size_t)p * 32 * K + k0);
                CP_ASYNC16(sB_u + (uint32_t)((((nb * 128) + row) * HST + lseg * 8) * 2),
                           Bg + (size_t)p * 32 * K + k0);
            }
            asm volatile("cp.async.commit_group;\n");
            asm volatile("cp.async.wait_group 1;\n");
        } else {
            asm volatile("cp.async.wait_group 0;\n");
        }
        __syncthreads();

        const uint32_t cA_u = sA_u + (uint32_t)(cur * 128 * HST * 2);
        const uint32_t cB_u = sB_u + (uint32_t)(cur * 128 * HST * 2);

#pragma unroll
        for (int ks = 0; ks < 2; ks++) {
            const int kk = ks * 16;
            uint32_t af[4][4];
#pragma unroll
            for (int im = 0; im < 4; im++)
                LDSM_X4(af[im][0], af[im][1], af[im][2], af[im][3],
                        cA_u + (uint32_t)(((wm + im * 16 + arow) * HST + kk + acol) * 2));
            uint32_t bf[8][2];
#pragma unroll
            for (int j2 = 0; j2 < 4; j2++)
                LDSM_X4(bf[2 * j2][0], bf[2 * j2][1],
                        bf[2 * j2 + 1][0], bf[2 * j2 + 1][1],
                        cB_u + (uint32_t)(((wn + j2 * 16 + brow) * HST + kk + bcol) * 2));
#pragma unroll
            for (int im = 0; im < 4; im++)
#pragma unroll
                for (int in_ = 0; in_ < 8; in_++)
                    MMA_F16(acc[im][in_], af[im][0], af[im][1], af[im][2],
                            af[im][3], bf[in_][0], bf[in_][1]);
        }
        __syncthreads();
    }

#pragma unroll
    for (int im = 0; im < 4; im++) {
        const int mA = m0 + wm + im * 16 + gp;
#pragma unroll
        for (int in_ = 0; in_ < 8; in_++) {
            const int n = n0 + wn + in_ * 8 + 2 * t4;
            *(float2*)(Cf + (size_t)mA * N + n) =
                make_float2(acc[im][in_][0], acc[im][in_][1]);
            *(float2*)(Cf + (size_t)(mA + 8) * N + n) =
                make_float2(acc[im][in_][2], acc[im][in_][3]);
        }
    }
}

// ---------------------------------------------------------------------------
// Flash attention: BM=BN=64, 128 thr / 4 warps, fp16 mma, XOR-swizzled smem
// (73728 B -> 3 CTAs/SM with __launch_bounds__(128,3)).
// ---------------------------------------------------------------------------
constexpr int OFF_Q  = 0;          // 64 rows x 256 B
constexpr int OFF_K0 = 16384;
constexpr int OFF_K1 = 32768;
constexpr int OFF_V  = 49152;
constexpr int OFF_P  = 65536;      // 64 rows x 128 B
constexpr int FL_SMEM_B = 73728;

__global__ void __launch_bounds__(128, 3) flash_tc(const __half* __restrict__ Q,
                                                   const __half* __restrict__ K,
                                                   const __half* __restrict__ V,
                                                   __half* __restrict__ O) {
    extern __shared__ char smraw[];
    char* sPc = smraw + OFF_P;
    const uint32_t sQ_u  = (uint32_t)__cvta_generic_to_shared(smraw + OFF_Q);
    const uint32_t sK0_u = (uint32_t)__cvta_generic_to_shared(smraw + OFF_K0);
    const uint32_t sK1_u = (uint32_t)__cvta_generic_to_shared(smraw + OFF_K1);
    const uint32_t sV_u  = (uint32_t)__cvta_generic_to_shared(smraw + OFF_V);
    const uint32_t sP_u  = (uint32_t)__cvta_generic_to_shared(sPc);

    const int tid  = threadIdx.x;
    const int wid  = tid >> 5;
    const int lane = tid & 31;
    const int gp   = lane >> 2;
    const int t4   = lane & 3;
    const int qb   = blockIdx.x;
    const int bh   = blockIdx.y;
    const int b    = bh >> 4;
    const int h    = bh & (Hc - 1);
    const size_t base = ((size_t)b * Sc) * Dc + (size_t)h * DHc;
    const int q0   = qb * 64;
    const int wrow = wid * 16;
    const int r0loc = wrow + gp;
    const int r1loc = r0loc + 8;

    const int arow = (lane & 7) + ((lane >> 3) & 1) * 8;
    const int aseg = lane >> 4;            // acol/8
    const int brow = (lane & 7) + (lane >> 4) * 8;
    const int bseg = (lane >> 3) & 1;      // bcol/8
    const int vrow = (lane & 7) + ((lane >> 3) & 1) * 8;
    const int vseg = lane >> 4;            // vcol/8

    // prologue: Q + K0 (group 0), V0 (group 1)
    {
#pragma unroll
        for (int p = 0; p < 8; p++) {
            int idx = tid + p * 128;
            int r = idx >> 4, sg = idx & 15;
            CP_ASYNC16(sQ_u + swz16(r, sg),
                       Q + base + (size_t)(q0 + r) * Dc + sg * 8);
        }
#pragma unroll
        for (int p = 0; p < 8; p++) {
            int idx = tid + p * 128;
            int r = idx >> 4, sg = idx & 15;
            CP_ASYNC16(sK0_u + swz16(r, sg),
                       K + base + (size_t)r * Dc + sg * 8);
        }
        asm volatile("cp.async.commit_group;\n");
#pragma unroll
        for (int p = 0; p < 8; p++) {
            int idx = tid + p * 128;
            int r = idx >> 4, sg = idx & 15;
            CP_ASYNC16(sV_u + swz16(r, sg),
                       V + base + (size_t)r * Dc + sg * 8);
        }
        asm volatile("cp.async.commit_group;\n");
    }

    float o[16][4];
#pragma unroll
    for (int n = 0; n < 16; n++)
#pragma unroll
        for (int r = 0; r < 4; r++) o[n][r] = 0.f;
    float m0 = -1e30f, m1 = -1e30f, l0 = 0.f, l1 = 0.f;

    for (int j = 0; j <= qb; ++j) {
        const uint32_t sKc_u = (j & 1) ? sK1_u : sK0_u;
        const uint32_t sKn_u = (j & 1) ? sK0_u : sK1_u;

        asm volatile("cp.async.wait_group 1;\n");
        __syncthreads();

        // ---- S = Qs @ K^T ----
        float sacc[8][4];
#pragma unroll
        for (int n = 0; n < 8; n++)
#pragma unroll
            for (int r = 0; r < 4; r++) sacc[n][r] = 0.f;

#pragma unroll
        for (int kk8 = 0; kk8 < 8; kk8++) {
            uint32_t a0, a1, a2, a3;
            LDSM_X4(a0, a1, a2, a3,
                    sQ_u + swz16(wrow + arow, kk8 * 2 + aseg));
            uint32_t bf[8][2];
#pragma unroll
            for (int j2 = 0; j2 < 4; j2++)
                LDSM_X4(bf[2 * j2][0], bf[2 * j2][1],
                        bf[2 * j2 + 1][0], bf[2 * j2 + 1][1],
                        sKc_u + swz16(j2 * 16 + brow, kk8 * 2 + bseg));
#pragma unroll
            for (int nt = 0; nt < 8; nt++)
                MMA_F16(sacc[nt], a0, a1, a2, a3, bf[nt][0], bf[nt][1]);
        }

        if (j == qb) {
#pragma unroll
            for (int nt = 0; nt < 8; nt++) {
                int c0 = nt * 8 + 2 * t4;
                if (c0 > r0loc)     sacc[nt][0] = -1e30f;
                if (c0 + 1 > r0loc) sacc[nt][1] = -1e30f;
                if (c0 > r1loc)     sacc[nt][2] = -1e30f;
                if (c0 + 1 > r1loc) sacc[nt][3] = -1e30f;
            }
        }

        // ---- online softmax ----
        float mx0 = -1e30f, mx1 = -1e30f;
#pragma unroll
        for (int nt = 0; nt < 8; nt++) {
            mx0 = fmaxf(mx0, fmaxf(sacc[nt][0], sacc[nt][1]));
            mx1 = fmaxf(mx1, fmaxf(sacc[nt][2], sacc[nt][3]));
        }
        mx0 = fmaxf(mx0, __shfl_xor_sync(0xffffffff, mx0, 1));
        mx0 = fmaxf(mx0, __shfl_xor_sync(0xffffffff, mx0, 2));
        mx1 = fmaxf(mx1, __shfl_xor_sync(0xffffffff, mx1, 1));
        mx1 = fmaxf(mx1, __shfl_xor_sync(0xffffffff, mx1, 2));

        float m0n = fmaxf(m0, mx0);
        float m1n = fmaxf(m1, mx1);
        float corr0 = __expf(m0 - m0n);
        float corr1 = __expf(m1 - m1n);
        m0 = m0n; m1 = m1n;

        float ls0 = 0.f, ls1 = 0.f;
#pragma unroll
        for (int nt = 0; nt < 8; nt++) {
            float p0 = __expf(sacc[nt][0] - m0);
            float p1 = __expf(sacc[nt][1] - m0);
            float p2 = __expf(sacc[nt][2] - m1);
            float p3 = __expf(sacc[nt][3] - m1);
            ls0 += p0 + p1;
            ls1 += p2 + p3;
            *(__half2*)(sPc + swz8(r0loc, nt) + t4 * 4) = __floats2half2_rn(p0, p1);
            *(__half2*)(sPc + swz8(r1loc, nt) + t4 * 4) = __floats2half2_rn(p2, p3);
        }
        ls0 += __shfl_xor_sync(0xffffffff, ls0, 1);
        ls0 += __shfl_xor_sync(0xffffffff, ls0, 2);
        ls1 += __shfl_xor_sync(0xffffffff, ls1, 1);
        ls1 += __shfl_xor_sync(0xffffffff, ls1, 2);
        l0 = l0 * corr0 + ls0;
        l1 = l1 * corr1 + ls1;

#pragma unroll
        for (int nt = 0; nt < 16; nt++) {
            o[nt][0] *= corr0; o[nt][1] *= corr0;
            o[nt][2] *= corr1; o[nt][3] *= corr1;
        }

        if (j < qb) {
            const int k0n = (j + 1) * 64;
#pragma unroll
            for (int p = 0; p < 8; p++) {
                int idx = tid + p * 128;
                int r = idx >> 4, sg = idx & 15;
                CP_ASYNC16(sKn_u + swz16(r, sg),
                           K + base + (size_t)(k0n + r) * Dc + sg * 8);
            }
            asm volatile("cp.async.commit_group;\n");
            asm volatile("cp.async.wait_group 1;\n");
        } else {
            asm volatile("cp.async.wait_group 0;\n");
        }
        __syncthreads();   // P visible + V ready

        // ---- O += P @ V ----
#pragma unroll
        for (int ks = 0; ks < 4; ks++) {
            const int kk = ks * 16;
            uint32_t a0, a1, a2, a3;
            LDSM_X4(a0, a1, a2, a3,
                    sP_u + swz8(wrow + arow, ks * 2 + aseg));
#pragma unroll
            for (int j2 = 0; j2 < 8; j2++) {
                uint32_t b00, b01, b10, b11;
                LDSM_X4_T(b00, b01, b10, b11,
                          sV_u + swz16(kk + vrow, j2 * 2 + vseg));
                MMA_F16(o[2 * j2],     a0, a1, a2, a3, b00, b01);
                MMA_F16(o[2 * j2 + 1], a0, a1, a2, a3, b10, b11);
            }
        }
        __syncthreads();

        if (j < qb) {
            const int k0n = (j + 1) * 64;
#pragma unroll
            for (int p = 0; p < 8; p++) {
                int idx = tid + p * 128;
                int r = idx >> 4, sg = idx & 15;
                CP_ASYNC16(sV_u + swz16(r, sg),
                           V + base + (size_t)(k0n + r) * Dc + sg * 8);
            }
            asm volatile("cp.async.commit_group;\n");
        }
    }

    float inv0 = 1.0f / l0, inv1 = 1.0f / l1;
    const size_t row0 = base + (size_t)(q0 + r0loc) * Dc;
    const size_t row1 = base + (size_t)(q0 + r1loc) * Dc;
#pragma unroll
    for (int nt = 0; nt < 16; nt++) {
        int c0 = nt * 8 + 2 * t4;
        *(__half2*)(O + row0 + c0) =
            __floats2half2_rn(o[nt][0] * inv0, o[nt][1] * inv0);
        *(__half2*)(O + row1 + c0) =
            __floats2half2_rn(o[nt][2] * inv1, o[nt][3] * inv1);
    }
}

// ---------------------------------------------------------------------------
// Launch
// ---------------------------------------------------------------------------
extern "C" void kernel_launch(void* const* d_in, const int* in_sizes, int n_in,
                              void* d_out, int out_size) {
    const float* x    = (const float*)d_in[0];
    const float* cosp = (const float*)d_in[1];
    const float* sinp = (const float*)d_in[2];
    const float* Wq   = (const float*)d_in[3];
    const float* Wk   = (const float*)d_in[4];
    const float* Wv   = (const float*)d_in[5];
    const float* Wo   = (const float*)d_in[6];
    float* out = (float*)d_out;

    __half *Vh, *xh, *Qh, *Kh, *Ah, *wqh, *wkh, *wvh, *woh;
    cudaGetSymbolAddress((void**)&Vh, g_Vh);
    cudaGetSymbolAddress((void**)&xh, g_xh);
    cudaGetSymbolAddress((void**)&Qh, g_Qh);
    cudaGetSymbolAddress((void**)&Kh, g_Kh);
    cudaGetSymbolAddress((void**)&Ah, g_Ah);
    cudaGetSymbolAddress((void**)&wqh, g_wqh);
    cudaGetSymbolAddress((void**)&wkh, g_wkh);
    cudaGetSymbolAddress((void**)&wvh, g_wvh);
    cudaGetSymbolAddress((void**)&woh, g_woh);

    cudaFuncSetAttribute(gemm_qkv, cudaFuncAttributeMaxDynamicSharedMemorySize,
                         GEMM_SMEM_B);
    cudaFuncSetAttribute(gemm_f16, cudaFuncAttributeMaxDynamicSharedMemorySize,
                         GEMM_SMEM_B);
    cudaFuncSetAttribute(flash_tc, cudaFuncAttributeMaxDynamicSharedMemorySize,
                         FL_SMEM_B);

    // fp16 conversions (x + all four W)
    {
        const int nx = Mc * Dc / 4, nw = Dc * Dc / 4;
        cvt_half<<<(nx + 255) / 256, 256>>>(x, xh, nx);
        dim3 wgrid((nw + 255) / 256, 4);
        cvt_w4<<<wgrid, 256>>>(Wq, Wk, Wv, Wo, wqh, wkh, wvh, woh, nw);
    }

    // fused QKV projections + RoPE/scale epilogue
    {
        dim3 qgrid(Dc / 128, Mc / 128, 3);   // (16, 32, 3)
        gemm_qkv<<<qgrid, 128, GEMM_SMEM_B>>>(xh, wqh, wkh, wvh,
                                              Qh, Kh, Vh, cosp, sinp);
    }

    // flash attention (swizzled, 3 CTAs/SM)
    {
        dim3 fgrid(Sc / 64, Bc * Hc);   // (32, 32)
        flash_tc<<<fgrid, 128, FL_SMEM_B>>>(Qh, Kh, Vh, Ah);
    }

    // O projection (fp32 out)
    {
        dim3 ggrid(Dc / 128, Mc / 128);   // (16, 32)
        gemm_f16<<<ggrid, 128, GEMM_SMEM_B>>>(Ah, woh, out, Mc, Dc, Dc);
    }
}

// round 12
// speedup vs baseline: 1.1242x; 1.0097x over previous
#include <cuda_runtime.h>
#include <cuda_fp16.h>
#include <math.h>
#include <stdint.h>

// Problem constants
constexpr int Bc  = 2;
constexpr int Sc  = 2048;
constexpr int Dc  = 2048;
constexpr int Hc  = 16;
constexpr int DHc = 128;
constexpr int Mc  = Bc * Sc;   // 4096 rows for projections

// ---------------------------------------------------------------------------
// Scratch (device globals: allocation-free per harness rules)
// ---------------------------------------------------------------------------
__device__ __half g_Vh [(size_t)Mc * Dc];      // half V
__device__ __half g_xh [(size_t)Mc * Dc];
__device__ __half g_Qh [(size_t)Mc * Dc];      // roped + (scale*log2e)-scaled
__device__ __half g_Kh [(size_t)Mc * Dc];      // roped
__device__ __half g_Ah [(size_t)Mc * Dc];      // attention out (half)
__device__ __half g_wqh[(size_t)Dc * Dc];
__device__ __half g_wkh[(size_t)Dc * Dc];
__device__ __half g_wvh[(size_t)Dc * Dc];
__device__ __half g_woh[(size_t)Dc * Dc];

#define CP_ASYNC16(dst, src) \
    asm volatile("cp.async.cg.shared.global [%0], [%1], 16;\n" :: "r"(dst), "l"(src))

#define MMA_F16(c, a0, a1, a2, a3, b0, b1)                                     \
    asm volatile(                                                              \
        "mma.sync.aligned.m16n8k16.row.col.f32.f16.f16.f32 "                   \
        "{%0,%1,%2,%3}, {%4,%5,%6,%7}, {%8,%9}, {%0,%1,%2,%3};\n"              \
        : "+f"((c)[0]), "+f"((c)[1]), "+f"((c)[2]), "+f"((c)[3])               \
        : "r"(a0), "r"(a1), "r"(a2), "r"(a3), "r"(b0), "r"(b1))

#define LDSM_X4(r0, r1, r2, r3, addr)                                          \
    asm volatile("ldmatrix.sync.aligned.m8n8.x4.shared.b16 {%0,%1,%2,%3}, [%4];" \
        : "=r"(r0), "=r"(r1), "=r"(r2), "=r"(r3) : "r"(addr))

#define LDSM_X4_T(r0, r1, r2, r3, addr)                                        \
    asm volatile("ldmatrix.sync.aligned.m8n8.x4.trans.shared.b16 {%0,%1,%2,%3}, [%4];" \
        : "=r"(r0), "=r"(r1), "=r"(r2), "=r"(r3) : "r"(addr))

// 16B-granular XOR swizzles (byte offsets). Row widths: 16 segs (QKV), 8 (P).
__device__ __forceinline__ uint32_t swz16(int row, int seg) {
    return (uint32_t)((row * 16 + (seg ^ (row & 7))) << 4);
}
__device__ __forceinline__ uint32_t swz8(int row, int seg) {
    return (uint32_t)((row * 8 + (seg ^ (row & 7))) << 4);
}

// ---------------------------------------------------------------------------
// fp32 -> fp16: all five inputs in one launch. y<4: weights; y=4,5: x halves.
// ---------------------------------------------------------------------------
__global__ void cvt_all(const float* __restrict__ x,
                        const float* __restrict__ w0, const float* __restrict__ w1,
                        const float* __restrict__ w2, const float* __restrict__ w3,
                        __half* __restrict__ xh,
                        __half* __restrict__ o0, __half* __restrict__ o1,
                        __half* __restrict__ o2, __half* __restrict__ o3, int n4) {
    int i = blockIdx.x * blockDim.x + threadIdx.x;
    if (i >= n4) return;
    const float* in;
    __half* out;
    switch (blockIdx.y) {
        case 0:  in = w0; out = o0; break;
        case 1:  in = w1; out = o1; break;
        case 2:  in = w2; out = o2; break;
        case 3:  in = w3; out = o3; break;
        case 4:  in = x;                     out = xh;                     break;
        default: in = x + (size_t)n4 * 4;    out = xh + (size_t)n4 * 4;    break;
    }
    float4 v = *(const float4*)(in + (size_t)i * 4);
    __half2 h01 = __floats2half2_rn(v.x, v.y);
    __half2 h23 = __floats2half2_rn(v.z, v.w);
    uint2 u;
    u.x = *(uint32_t*)&h01;
    u.y = *(uint32_t*)&h23;
    *(uint2*)(out + (size_t)i * 4) = u;
}

// ---------------------------------------------------------------------------
// GEMM core constants (round-7 proven shape): BM=BN=128, BK=32, 128 thr.
// ---------------------------------------------------------------------------
constexpr int HST = 40;                               // halves per smem row
constexpr int GEMM_SMEM_B = 2 * 2 * 128 * HST * 2;    // 40960 bytes

// ---------------------------------------------------------------------------
// Fused QKV projection: z selects W/output; z<2 fuses RoPE (+ Q scale, with
// log2e folded in so flash can use exp2 directly).
// ---------------------------------------------------------------------------
__global__ void __launch_bounds__(128) gemm_qkv(
    const __half* __restrict__ A,
    const __half* __restrict__ Bq, const __half* __restrict__ Bk,
    const __half* __restrict__ Bv,
    __half* __restrict__ Qh, __half* __restrict__ Kh, __half* __restrict__ Vh,
    const float* __restrict__ cosp, const float* __restrict__ sinp) {
    extern __shared__ __half hsm[];
    __half* sA = hsm;
    __half* sB = hsm + 2 * 128 * HST;

    const int z = blockIdx.z;
    const __half* B = (z == 0) ? Bq : ((z == 1) ? Bk : Bv);
    const int K = Dc, N = Dc;

    const int tid  = threadIdx.x;
    const int wid  = tid >> 5;
    const int lane = tid & 31;
    const int wm = (wid & 1) * 64;
    const int wn = (wid >> 1) * 64;
    const int gp = lane >> 2;
    const int t4 = lane & 3;
    const int m0 = blockIdx.y * 128;
    const int n0 = blockIdx.x * 128;

    const int arow = (lane & 7) + ((lane >> 3) & 1) * 8;
    const int acol = (lane >> 4) * 8;
    const int brow = (lane & 7) + (lane >> 4) * 8;
    const int bcol = ((lane >> 3) & 1) * 8;

    const int lrow = tid >> 2;
    const int lseg = tid & 3;
    const __half* Ag = A + (size_t)(m0 + lrow) * K + lseg * 8;
    const __half* Bg = B + (size_t)(n0 + lrow) * K + lseg * 8;

    const uint32_t sA_u = (uint32_t)__cvta_generic_to_shared(sA);
    const uint32_t sB_u = (uint32_t)__cvta_generic_to_shared(sB);

    float acc[4][8][4];
#pragma unroll
    for (int im = 0; im < 4; im++)
#pragma unroll
        for (int in_ = 0; in_ < 8; in_++)
#pragma unroll
            for (int r = 0; r < 4; r++) acc[im][in_][r] = 0.f;

    const int nt = K / 32;

    {
#pragma unroll
        for (int p = 0; p < 4; p++) {
            int row = lrow + p * 32;
            CP_ASYNC16(sA_u + (uint32_t)((row * HST + lseg * 8) * 2),
                       Ag + (size_t)p * 32 * K);
            CP_ASYNC16(sB_u + (uint32_t)((row * HST + lseg * 8) * 2),
                       Bg + (size_t)p * 32 * K);
        }
        asm volatile("cp.async.commit_group;\n");
    }

    for (int kt = 0; kt < nt; kt++) {
        const int cur = kt & 1;
        if (kt + 1 < nt) {
            const int nb = cur ^ 1;
            const int k0 = (kt + 1) * 32;
#pragma unroll
            for (int p = 0; p < 4; p++) {
                int row = lrow + p * 32;
                CP_ASYNC16(sA_u + (uint32_t)((((nb * 128) + row) * HST + lseg * 8) * 2),
                           Ag + (size_t)p * 32 * K + k0);
                CP_ASYNC16(sB_u + (uint32_t)((((nb * 128) + row) * HST + lseg * 8) * 2),
                           Bg + (size_t)p * 32 * K + k0);
            }
            asm volatile("cp.async.commit_group;\n");
            asm volatile("cp.async.wait_group 1;\n");
        } else {
            asm volatile("cp.async.wait_group 0;\n");
        }
        __syncthreads();

        const uint32_t cA_u = sA_u + (uint32_t)(cur * 128 * HST * 2);
        const uint32_t cB_u = sB_u + (uint32_t)(cur * 128 * HST * 2);

#pragma unroll
        for (int ks = 0; ks < 2; ks++) {
            const int kk = ks * 16;
            uint32_t af[4][4];
#pragma unroll
            for (int im = 0; im < 4; im++)
                LDSM_X4(af[im][0], af[im][1], af[im][2], af[im][3],
                        cA_u + (uint32_t)(((wm + im * 16 + arow) * HST + kk + acol) * 2));
            uint32_t bf[8][2];
#pragma unroll
            for (int j2 = 0; j2 < 4; j2++)
                LDSM_X4(bf[2 * j2][0], bf[2 * j2][1],
                        bf[2 * j2 + 1][0], bf[2 * j2 + 1][1],
                        cB_u + (uint32_t)(((wn + j2 * 16 + brow) * HST + kk + bcol) * 2));
#pragma unroll
            for (int im = 0; im < 4; im++)
#pragma unroll
                for (int in_ = 0; in_ < 8; in_++)
                    MMA_F16(acc[im][in_], af[im][0], af[im][1], af[im][2],
                            af[im][3], bf[in_][0], bf[in_][1]);
        }
        __syncthreads();
    }

    if (z == 2) {
#pragma unroll
        for (int im = 0; im < 4; im++) {
            const int mA = m0 + wm + im * 16 + gp;
#pragma unroll
            for (int in_ = 0; in_ < 8; in_++) {
                const int n = n0 + wn + in_ * 8 + 2 * t4;
                *(__half2*)(Vh + (size_t)mA * N + n) =
                    __floats2half2_rn(acc[im][in_][0], acc[im][in_][1]);
                *(__half2*)(Vh + (size_t)(mA + 8) * N + n) =
                    __floats2half2_rn(acc[im][in_][2], acc[im][in_][3]);
            }
        }
        return;
    }

    // RoPE epilogue (Q/K) via smem exchange. Q scale includes log2(e).
    float* sf = (float*)hsm;   // [128][68] fp32
    if (wn == 64) {
#pragma unroll
        for (int im = 0; im < 4; im++) {
            int row = wm + im * 16 + gp;
#pragma unroll
            for (int in_ = 0; in_ < 8; in_++) {
                int col = in_ * 8 + 2 * t4;
                sf[row * 68 + col]           = acc[im][in_][0];
                sf[row * 68 + col + 1]       = acc[im][in_][1];
                sf[(row + 8) * 68 + col]     = acc[im][in_][2];
                sf[(row + 8) * 68 + col + 1] = acc[im][in_][3];
            }
        }
    }
    __syncthreads();
    if (wn == 0) {
        const float scale = (z == 0)
            ? 0.08838834764831845f * 1.44269504088896340736f : 1.0f;
        __half* Out = (z == 0) ? Qh : Kh;
#pragma unroll
        for (int im = 0; im < 4; im++) {
            int row = wm + im * 16 + gp;
            int sAi = (m0 + row) & (Sc - 1);
            int sBi = (m0 + row + 8) & (Sc - 1);
#pragma unroll
            for (int in_ = 0; in_ < 8; in_++) {
                int col = in_ * 8 + 2 * t4;
                float2 cA  = *(const float2*)(cosp + sAi * DHc + col);
                float2 snA = *(const float2*)(sinp + sAi * DHc + col);
                float2 cB  = *(const float2*)(cosp + sBi * DHc + col);
                float2 snB = *(const float2*)(sinp + sBi * DHc + col);
                float a0 = acc[im][in_][0], a1 = acc[im][in_][1];
                float a2 = acc[im][in_][2], a3 = acc[im][in_][3];
                float b0 = sf[row * 68 + col],       b1 = sf[row * 68 + col + 1];
                float b2 = sf[(row + 8) * 68 + col], b3 = sf[(row + 8) * 68 + col + 1];
                __half2 loA = __floats2half2_rn(scale * (a0 * cA.x - b0 * snA.x),
                                                scale * (a1 * cA.y - b1 * snA.y));
                __half2 hiA = __floats2half2_rn(scale * (b0 * cA.x + a0 * snA.x),
                                                scale * (b1 * cA.y + a1 * snA.y));
                __half2 loB = __floats2half2_rn(scale * (a2 * cB.x - b2 * snB.x),
                                                scale * (a3 * cB.y - b3 * snB.y));
                __half2 hiB = __floats2half2_rn(scale * (b2 * cB.x + a2 * snB.x),
                                                scale * (b3 * cB.y + a3 * snB.y));
                size_t gr = (size_t)(m0 + row) * Dc + n0 + col;
                *(__half2*)(Out + gr)                      = loA;
                *(__half2*)(Out + gr + 64)                 = hiA;
                *(__half2*)(Out + gr + (size_t)8 * Dc)      = loB;
                *(__half2*)(Out + gr + (size_t)8 * Dc + 64) = hiB;
            }
        }
    }
}

// ---------------------------------------------------------------------------
// Plain fp16 GEMM for the O projection (fp32 out).
// ---------------------------------------------------------------------------
__global__ void __launch_bounds__(128) gemm_f16(const __half* __restrict__ A,
                                                const __half* __restrict__ B,
                                                float* __restrict__ Cf,
                                                int M, int N, int K) {
    extern __shared__ __half hsm[];
    __half* sA = hsm;
    __half* sB = hsm + 2 * 128 * HST;

    const int tid  = threadIdx.x;
    const int wid  = tid >> 5;
    const int lane = tid & 31;
    const int wm = (wid & 1) * 64;
    const int wn = (wid >> 1) * 64;
    const int gp = lane >> 2;
    const int t4 = lane & 3;
    const int m0 = blockIdx.y * 128;
    const int n0 = blockIdx.x * 128;

    const int arow = (lane & 7) + ((lane >> 3) & 1) * 8;
    const int acol = (lane >> 4) * 8;
    const int brow = (lane & 7) + (lane >> 4) * 8;
    const int bcol = ((lane >> 3) & 1) * 8;

    const int lrow = tid >> 2;
    const int lseg = tid & 3;
    const __half* Ag = A + (size_t)(m0 + lrow) * K + lseg * 8;
    const __half* Bg = B + (size_t)(n0 + lrow) * K + lseg * 8;

    const uint32_t sA_u = (uint32_t)__cvta_generic_to_shared(sA);
    const uint32_t sB_u = (uint32_t)__cvta_generic_to_shared(sB);

    float acc[4][8][4];
#pragma unroll
    for (int im = 0; im < 4; im++)
#pragma unroll
        for (int in_ = 0; in_ < 8; in_++)
#pragma unroll
            for (int r = 0; r < 4; r++) acc[im][in_][r] = 0.f;

    const int nt = K / 32;

    {
#pragma unroll
        for (int p = 0; p < 4; p++) {
            int row = lrow + p * 32;
            CP_ASYNC16(sA_u + (uint32_t)((row * HST + lseg * 8) * 2),
                       Ag + (size_t)p * 32 * K);
            CP_ASYNC16(sB_u + (uint32_t)((row * HST + lseg * 8) * 2),
                       Bg + (size_t)p * 32 * K);
        }
        asm volatile("cp.async.commit_group;\n");
    }

    for (int kt = 0; kt < nt; kt++) {
        const int cur = kt & 1;
        if (kt + 1 < nt) {
            const int nb = cur ^ 1;
            const int k0 = (kt + 1) * 32;
#pragma unroll
            for (int p = 0; p < 4; p++) {
                int row = lrow + p * 32;
                CP_ASYNC16(sA_u + (uint32_t)((((nb * 128) + row) * HST + lseg * 8) * 2),
                           Ag + (size_t)p * 32 * K + k0);
                CP_ASYNC16(sB_u + (uint32_t)((((nb * 128) + row) * HST + lseg * 8) * 2),
                           Bg + (size_t)p * 32 * K + k0);
            }
            asm volatile("cp.async.commit_group;\n");
            asm volatile("cp.async.wait_group 1;\n");
        } else {
            asm volatile("cp.async.wait_group 0;\n");
        }
        __syncthreads();

        const uint32_t cA_u = sA_u + (uint32_t)(cur * 128 * HST * 2);
        const uint32_t cB_u = sB_u + (uint32_t)(cur * 128 * HST * 2);

#pragma unroll
        for (int ks = 0; ks < 2; ks++) {
            const int kk = ks * 16;
            uint32_t af[4][4];
#pragma unroll
            for (int im = 0; im < 4; im++)
                LDSM_X4(af[im][0], af[im][1], af[im][2], af[im][3],
                        cA_u + (uint32_t)(((wm + im * 16 + arow) * HST + kk + acol) * 2));
            uint32_t bf[8][2];
#pragma unroll
            for (int j2 = 0; j2 < 4; j2++)
                LDSM_X4(bf[2 * j2][0], bf[2 * j2][1],
                        bf[2 * j2 + 1][0], bf[2 * j2 + 1][1],
                        cB_u + (uint32_t)(((wn + j2 * 16 + brow) * HST + kk + bcol) * 2));
#pragma unroll
            for (int im = 0; im < 4; im++)
#pragma unroll
                for (int in_ = 0; in_ < 8; in_++)
                    MMA_F16(acc[im][in_], af[im][0], af[im][1], af[im][2],
                            af[im][3], bf[in_][0], bf[in_][1]);
        }
        __syncthreads();
    }

#pragma unroll
    for (int im = 0; im < 4; im++) {
        const int mA = m0 + wm + im * 16 + gp;
#pragma unroll
        for (int in_ = 0; in_ < 8; in_++) {
            const int n = n0 + wn + in_ * 8 + 2 * t4;
            *(float2*)(Cf + (size_t)mA * N + n) =
                make_float2(acc[im][in_][0], acc[im][in_][1]);
            *(float2*)(Cf + (size_t)(mA + 8) * N + n) =
                make_float2(acc[im][in_][2], acc[im][in_][3]);
        }
    }
}

// ---------------------------------------------------------------------------
// Flash attention: BM=BN=64, 128 thr / 4 warps, fp16 mma, XOR-swizzled smem,
// 3 CTAs/SM. exp2-domain softmax (log2e pre-folded into Q); skip-rescale;
// early K(j+1) prefetch overlapping QK mma.
// ---------------------------------------------------------------------------
constexpr int OFF_Q  = 0;
constexpr int OFF_K0 = 16384;
constexpr int OFF_K1 = 32768;
constexpr int OFF_V  = 49152;
constexpr int OFF_P  = 65536;
constexpr int FL_SMEM_B = 73728;

__global__ void __launch_bounds__(128, 3) flash_tc(const __half* __restrict__ Q,
                                                   const __half* __restrict__ K,
                                                   const __half* __restrict__ V,
                                                   __half* __restrict__ O) {
    extern __shared__ char smraw[];
    char* sPc = smraw + OFF_P;
    const uint32_t sQ_u  = (uint32_t)__cvta_generic_to_shared(smraw + OFF_Q);
    const uint32_t sK0_u = (uint32_t)__cvta_generic_to_shared(smraw + OFF_K0);
    const uint32_t sK1_u = (uint32_t)__cvta_generic_to_shared(smraw + OFF_K1);
    const uint32_t sV_u  = (uint32_t)__cvta_generic_to_shared(smraw + OFF_V);
    const uint32_t sP_u  = (uint32_t)__cvta_generic_to_shared(sPc);

    const int tid  = threadIdx.x;
    const int wid  = tid >> 5;
    const int lane = tid & 31;
    const int gp   = lane >> 2;
    const int t4   = lane & 3;
    const int qb   = blockIdx.x;
    const int bh   = blockIdx.y;
    const int b    = bh >> 4;
    const int h    = bh & (Hc - 1);
    const size_t base = ((size_t)b * Sc) * Dc + (size_t)h * DHc;
    const int q0   = qb * 64;
    const int wrow = wid * 16;
    const int r0loc = wrow + gp;
    const int r1loc = r0loc + 8;

    const int arow = (lane & 7) + ((lane >> 3) & 1) * 8;
    const int aseg = lane >> 4;
    const int brow = (lane & 7) + (lane >> 4) * 8;
    const int bseg = (lane >> 3) & 1;
    const int vrow = (lane & 7) + ((lane >> 3) & 1) * 8;
    const int vseg = lane >> 4;

    // prologue: Q + K0 (group 0), V0 (group 1)
    {
#pragma unroll
        for (int p = 0; p < 8; p++) {
            int idx = tid + p * 128;
            int r = idx >> 4, sg = idx & 15;
            CP_ASYNC16(sQ_u + swz16(r, sg),
                       Q + base + (size_t)(q0 + r) * Dc + sg * 8);
        }
#pragma unroll
        for (int p = 0; p < 8; p++) {
            int idx = tid + p * 128;
            int r = idx >> 4, sg = idx & 15;
            CP_ASYNC16(sK0_u + swz16(r, sg),
                       K + base + (size_t)r * Dc + sg * 8);
        }
        asm volatile("cp.async.commit_group;\n");
#pragma unroll
        for (int p = 0; p < 8; p++) {
            int idx = tid + p * 128;
            int r = idx >> 4, sg = idx & 15;
            CP_ASYNC16(sV_u + swz16(r, sg),
                       V + base + (size_t)r * Dc + sg * 8);
        }
        asm volatile("cp.async.commit_group;\n");
    }

    float o[16][4];
#pragma unroll
    for (int n = 0; n < 16; n++)
#pragma unroll
        for (int r = 0; r < 4; r++) o[n][r] = 0.f;
    float m0 = -1e30f, m1 = -1e30f, l0 = 0.f, l1 = 0.f;

    for (int j = 0; j <= qb; ++j) {
        const uint32_t sKc_u = (j & 1) ? sK1_u : sK0_u;
        const uint32_t sKn_u = (j & 1) ? sK0_u : sK1_u;

        asm volatile("cp.async.wait_group 1;\n");   // K_j (and Q) ready
        __syncthreads();

        // early K(j+1) prefetch: target buffer's readers finished last iter
        if (j < qb) {
            const int k0n = (j + 1) * 64;
#pragma unroll
            for (int p = 0; p < 8; p++) {
                int idx = tid + p * 128;
                int r = idx >> 4, sg = idx & 15;
                CP_ASYNC16(sKn_u + swz16(r, sg),
                           K + base + (size_t)(k0n + r) * Dc + sg * 8);
            }
            asm volatile("cp.async.commit_group;\n");
        }

        // ---- S = Qs @ K^T  (log2-domain scores) ----
        float sacc[8][4];
#pragma unroll
        for (int n = 0; n < 8; n++)
#pragma unroll
            for (int r = 0; r < 4; r++) sacc[n][r] = 0.f;

#pragma unroll
        for (int kk8 = 0; kk8 < 8; kk8++) {
            uint32_t a0, a1, a2, a3;
            LDSM_X4(a0, a1, a2, a3,
                    sQ_u + swz16(wrow + arow, kk8 * 2 + aseg));
            uint32_t bf[8][2];
#pragma unroll
            for (int j2 = 0; j2 < 4; j2++)
                LDSM_X4(bf[2 * j2][0], bf[2 * j2][1],
                        bf[2 * j2 + 1][0], bf[2 * j2 + 1][1],
                        sKc_u + swz16(j2 * 16 + brow, kk8 * 2 + bseg));
#pragma unroll
            for (int nt = 0; nt < 8; nt++)
                MMA_F16(sacc[nt], a0, a1, a2, a3, bf[nt][0], bf[nt][1]);
        }

        if (j == qb) {
#pragma unroll
            for (int nt = 0; nt < 8; nt++) {
                int c0 = nt * 8 + 2 * t4;
                if (c0 > r0loc)     sacc[nt][0] = -1e30f;
                if (c0 + 1 > r0loc) sacc[nt][1] = -1e30f;
                if (c0 > r1loc)     sacc[nt][2] = -1e30f;
                if (c0 + 1 > r1loc) sacc[nt][3] = -1e30f;
            }
        }

        // ---- online softmax (exp2 domain) ----
        float mx0 = -1e30f, mx1 = -1e30f;
#pragma unroll
        for (int nt = 0; nt < 8; nt++) {
            mx0 = fmaxf(mx0, fmaxf(sacc[nt][0], sacc[nt][1]));
            mx1 = fmaxf(mx1, fmaxf(sacc[nt][2], sacc[nt][3]));
        }
        mx0 = fmaxf(mx0, __shfl_xor_sync(0xffffffff, mx0, 1));
        mx0 = fmaxf(mx0, __shfl_xor_sync(0xffffffff, mx0, 2));
        mx1 = fmaxf(mx1, __shfl_xor_sync(0xffffffff, mx1, 1));
        mx1 = fmaxf(mx1, __shfl_xor_sync(0xffffffff, mx1, 2));

        float m0n = fmaxf(m0, mx0);
        float m1n = fmaxf(m1, mx1);
        bool nochg = (m0n == m0) && (m1n == m1);
        if (!__all_sync(0xffffffff, nochg)) {
            float corr0 = exp2f(m0 - m0n);
            float corr1 = exp2f(m1 - m1n);
            l0 *= corr0;
            l1 *= corr1;
#pragma unroll
            for (int nt = 0; nt < 16; nt++) {
                o[nt][0] *= corr0; o[nt][1] *= corr0;
                o[nt][2] *= corr1; o[nt][3] *= corr1;
            }
            m0 = m0n; m1 = m1n;
        }

        float ls0 = 0.f, ls1 = 0.f;
#pragma unroll
        for (int nt = 0; nt < 8; nt++) {
            float p0 = exp2f(sacc[nt][0] - m0);
            float p1 = exp2f(sacc[nt][1] - m0);
            float p2 = exp2f(sacc[nt][2] - m1);
            float p3 = exp2f(sacc[nt][3] - m1);
            ls0 += p0 + p1;
            ls1 += p2 + p3;
            *(__half2*)(sPc + swz8(r0loc, nt) + t4 * 4) = __floats2half2_rn(p0, p1);
            *(__half2*)(sPc + swz8(r1loc, nt) + t4 * 4) = __floats2half2_rn(p2, p3);
        }
        ls0 += __shfl_xor_sync(0xffffffff, ls0, 1);
        ls0 += __shfl_xor_sync(0xffffffff, ls0, 2);
        ls1 += __shfl_xor_sync(0xffffffff, ls1, 1);
        ls1 += __shfl_xor_sync(0xffffffff, ls1, 2);
        l0 += ls0;
        l1 += ls1;

        // wait for V_j (leave K_{j+1} in flight)
        if (j < qb) asm volatile("cp.async.wait_group 1;\n");
        else        asm volatile("cp.async.wait_group 0;\n");
        __syncthreads();   // P visible + V ready

        // ---- O += P @ V ----
#pragma unroll
        for (int ks = 0; ks < 4; ks++) {
            const int kk = ks * 16;
            uint32_t a0, a1, a2, a3;
            LDSM_X4(a0, a1, a2, a3,
                    sP_u + swz8(wrow + arow, ks * 2 + aseg));
#pragma unroll
            for (int j2 = 0; j2 < 8; j2++) {
                uint32_t b00, b01, b10, b11;
                LDSM_X4_T(b00, b01, b10, b11,
                          sV_u + swz16(kk + vrow, j2 * 2 + vseg));
                MMA_F16(o[2 * j2],     a0, a1, a2, a3, b00, b01);
                MMA_F16(o[2 * j2 + 1], a0, a1, a2, a3, b10, b11);
            }
        }
        __syncthreads();

        if (j < qb) {
            const int k0n = (j + 1) * 64;
#pragma unroll
            for (int p = 0; p < 8; p++) {
                int idx = tid + p * 128;
                int r = idx >> 4, sg = idx & 15;
                CP_ASYNC16(sV_u + swz16(r, sg),
                           V + base + (size_t)(k0n + r) * Dc + sg * 8);
            }
            asm volatile("cp.async.commit_group;\n");
        }
    }

    float inv0 = 1.0f / l0, inv1 = 1.0f / l1;
    const size_t row0 = base + (size_t)(q0 + r0loc) * Dc;
    const size_t row1 = base + (size_t)(q0 + r1loc) * Dc;
#pragma unroll
    for (int nt = 0; nt < 16; nt++) {
        int c0 = nt * 8 + 2 * t4;
        *(__half2*)(O + row0 + c0) =
            __floats2half2_rn(o[nt][0] * inv0, o[nt][1] * inv0);
        *(__half2*)(O + row1 + c0) =
            __floats2half2_rn(o[nt][2] * inv1, o[nt][3] * inv1);
    }
}

// ---------------------------------------------------------------------------
// Launch
// ---------------------------------------------------------------------------
extern "C" void kernel_launch(void* const* d_in, const int* in_sizes, int n_in,
                              void* d_out, int out_size) {
    const float* x    = (const float*)d_in[0];
    const float* cosp = (const float*)d_in[1];
    const float* sinp = (const float*)d_in[2];
    const float* Wq   = (const float*)d_in[3];
    const float* Wk   = (const float*)d_in[4];
    const float* Wv   = (const float*)d_in[5];
    const float* Wo   = (const float*)d_in[6];
    float* out = (float*)d_out;

    __half *Vh, *xh, *Qh, *Kh, *Ah, *wqh, *wkh, *wvh, *woh;
    cudaGetSymbolAddress((void**)&Vh, g_Vh);
    cudaGetSymbolAddress((void**)&xh, g_xh);
    cudaGetSymbolAddress((void**)&Qh, g_Qh);
    cudaGetSymbolAddress((void**)&Kh, g_Kh);
    cudaGetSymbolAddress((void**)&Ah, g_Ah);
    cudaGetSymbolAddress((void**)&wqh, g_wqh);
    cudaGetSymbolAddress((void**)&wkh, g_wkh);
    cudaGetSymbolAddress((void**)&wvh, g_wvh);
    cudaGetSymbolAddress((void**)&woh, g_woh);

    cudaFuncSetAttribute(gemm_qkv, cudaFuncAttributeMaxDynamicSharedMemorySize,
                         GEMM_SMEM_B);
    cudaFuncSetAttribute(gemm_f16, cudaFuncAttributeMaxDynamicSharedMemorySize,
                         GEMM_SMEM_B);
    cudaFuncSetAttribute(flash_tc, cudaFuncAttributeMaxDynamicSharedMemorySize,
                         FL_SMEM_B);

    // all fp16 conversions in one launch (y: 4 weights + 2 x halves)
    {
        const int nw = Dc * Dc / 4;
        dim3 cgrid((nw + 255) / 256, 6);
        cvt_all<<<cgrid, 256>>>(x, Wq, Wk, Wv, Wo,
                                xh, wqh, wkh, wvh, woh, nw);
    }

    // fused QKV projections + RoPE/scale epilogue
    {
        dim3 qgrid(Dc / 128, Mc / 128, 3);   // (16, 32, 3)
        gemm_qkv<<<qgrid, 128, GEMM_SMEM_B>>>(xh, wqh, wkh, wvh,
                                              Qh, Kh, Vh, cosp, sinp);
    }

    // flash attention
    {
        dim3 fgrid(Sc / 64, Bc * Hc);   // (32, 32)
        flash_tc<<<fgrid, 128, FL_SMEM_B>>>(Qh, Kh, Vh, Ah);
    }

    // O projection (fp32 out)
    {
        dim3 ggrid(Dc / 128, Mc / 128);   // (16, 32)
        gemm_f16<<<ggrid, 128, GEMM_SMEM_B>>>(Ah, woh, out, Mc, Dc, Dc);
    }
}

// round 13
// speedup vs baseline: 1.1393x; 1.0134x over previous
#include <cuda_runtime.h>
#include <cuda_fp16.h>
#include <math.h>
#include <stdint.h>

// Problem constants
constexpr int Bc  = 2;
constexpr int Sc  = 2048;
constexpr int Dc  = 2048;
constexpr int Hc  = 16;
constexpr int DHc = 128;
constexpr int Mc  = Bc * Sc;   // 4096 rows for projections

// ---------------------------------------------------------------------------
// Scratch (device globals: allocation-free per harness rules)
// ---------------------------------------------------------------------------
__device__ __half g_Vh [(size_t)Mc * Dc];      // half V
__device__ __half g_xh [(size_t)Mc * Dc];
__device__ __half g_Qh [(size_t)Mc * Dc];      // roped + (scale*log2e)-scaled
__device__ __half g_Kh [(size_t)Mc * Dc];      // roped
__device__ __half g_Ah [(size_t)Mc * Dc];      // attention out (half)
__device__ __half g_wqh[(size_t)Dc * Dc];
__device__ __half g_wkh[(size_t)Dc * Dc];
__device__ __half g_wvh[(size_t)Dc * Dc];
__device__ __half g_woh[(size_t)Dc * Dc];

#define CP_ASYNC16(dst, src) \
    asm volatile("cp.async.cg.shared.global [%0], [%1], 16;\n" :: "r"(dst), "l"(src))

#define MMA_F16(c, a0, a1, a2, a3, b0, b1)                                     \
    asm volatile(                                                              \
        "mma.sync.aligned.m16n8k16.row.col.f32.f16.f16.f32 "                   \
        "{%0,%1,%2,%3}, {%4,%5,%6,%7}, {%8,%9}, {%0,%1,%2,%3};\n"              \
        : "+f"((c)[0]), "+f"((c)[1]), "+f"((c)[2]), "+f"((c)[3])               \
        : "r"(a0), "r"(a1), "r"(a2), "r"(a3), "r"(b0), "r"(b1))

#define LDSM_X4(r0, r1, r2, r3, addr)                                          \
    asm volatile("ldmatrix.sync.aligned.m8n8.x4.shared.b16 {%0,%1,%2,%3}, [%4];" \
        : "=r"(r0), "=r"(r1), "=r"(r2), "=r"(r3) : "r"(addr))

#define LDSM_X4_T(r0, r1, r2, r3, addr)                                        \
    asm volatile("ldmatrix.sync.aligned.m8n8.x4.trans.shared.b16 {%0,%1,%2,%3}, [%4];" \
        : "=r"(r0), "=r"(r1), "=r"(r2), "=r"(r3) : "r"(addr))

// 16B-granular XOR swizzles (byte offsets). Row widths: 16 segs (QKV), 8 (P).
__device__ __forceinline__ uint32_t swz16(int row, int seg) {
    return (uint32_t)((row * 16 + (seg ^ (row & 7))) << 4);
}
__device__ __forceinline__ uint32_t swz8(int row, int seg) {
    return (uint32_t)((row * 8 + (seg ^ (row & 7))) << 4);
}

// ---------------------------------------------------------------------------
// fp32 -> fp16: all five inputs in one launch. y<4: weights; y=4,5: x halves.
// ---------------------------------------------------------------------------
__global__ void cvt_all(const float* __restrict__ x,
                        const float* __restrict__ w0, const float* __restrict__ w1,
                        const float* __restrict__ w2, const float* __restrict__ w3,
                        __half* __restrict__ xh,
                        __half* __restrict__ o0, __half* __restrict__ o1,
                        __half* __restrict__ o2, __half* __restrict__ o3, int n4) {
    int i = blockIdx.x * blockDim.x + threadIdx.x;
    if (i >= n4) return;
    const float* in;
    __half* out;
    switch (blockIdx.y) {
        case 0:  in = w0; out = o0; break;
        case 1:  in = w1; out = o1; break;
        case 2:  in = w2; out = o2; break;
        case 3:  in = w3; out = o3; break;
        case 4:  in = x;                     out = xh;                     break;
        default: in = x + (size_t)n4 * 4;    out = xh + (size_t)n4 * 4;    break;
    }
    float4 v = *(const float4*)(in + (size_t)i * 4);
    __half2 h01 = __floats2half2_rn(v.x, v.y);
    __half2 h23 = __floats2half2_rn(v.z, v.w);
    uint2 u;
    u.x = *(uint32_t*)&h01;
    u.y = *(uint32_t*)&h23;
    *(uint2*)(out + (size_t)i * 4) = u;
}

// ---------------------------------------------------------------------------
// Shared GEMM constants
// ---------------------------------------------------------------------------
constexpr int HST = 40;                               // halves per smem row
constexpr int GEMM_SMEM_B = 2 * 2 * 128 * HST * 2;    // 40960 bytes (QKV kernel)

// ---------------------------------------------------------------------------
// Fused QKV projection (unchanged proven shape): BM=BN=128, BK=32, 128 thr.
// z selects W/output; z<2 fuses RoPE (+ Q scale with log2e folded in).
// ---------------------------------------------------------------------------
__global__ void __launch_bounds__(128) gemm_qkv(
    const __half* __restrict__ A,
    const __half* __restrict__ Bq, const __half* __restrict__ Bk,
    const __half* __restrict__ Bv,
    __half* __restrict__ Qh, __half* __restrict__ Kh, __half* __restrict__ Vh,
    const float* __restrict__ cosp, const float* __restrict__ sinp) {
    extern __shared__ __half hsm[];
    __half* sA = hsm;
    __half* sB = hsm + 2 * 128 * HST;

    const int z = blockIdx.z;
    const __half* B = (z == 0) ? Bq : ((z == 1) ? Bk : Bv);
    const int K = Dc, N = Dc;

    const int tid  = threadIdx.x;
    const int wid  = tid >> 5;
    const int lane = tid & 31;
    const int wm = (wid & 1) * 64;
    const int wn = (wid >> 1) * 64;
    const int gp = lane >> 2;
    const int t4 = lane & 3;
    const int m0 = blockIdx.y * 128;
    const int n0 = blockIdx.x * 128;

    const int arow = (lane & 7) + ((lane >> 3) & 1) * 8;
    const int acol = (lane >> 4) * 8;
    const int brow = (lane & 7) + (lane >> 4) * 8;
    const int bcol = ((lane >> 3) & 1) * 8;

    const int lrow = tid >> 2;
    const int lseg = tid & 3;
    const __half* Ag = A + (size_t)(m0 + lrow) * K + lseg * 8;
    const __half* Bg = B + (size_t)(n0 + lrow) * K + lseg * 8;

    const uint32_t sA_u = (uint32_t)__cvta_generic_to_shared(sA);
    const uint32_t sB_u = (uint32_t)__cvta_generic_to_shared(sB);

    float acc[4][8][4];
#pragma unroll
    for (int im = 0; im < 4; im++)
#pragma unroll
        for (int in_ = 0; in_ < 8; in_++)
#pragma unroll
            for (int r = 0; r < 4; r++) acc[im][in_][r] = 0.f;

    const int nt = K / 32;

    {
#pragma unroll
        for (int p = 0; p < 4; p++) {
            int row = lrow + p * 32;
            CP_ASYNC16(sA_u + (uint32_t)((row * HST + lseg * 8) * 2),
                       Ag + (size_t)p * 32 * K);
            CP_ASYNC16(sB_u + (uint32_t)((row * HST + lseg * 8) * 2),
                       Bg + (size_t)p * 32 * K);
        }
        asm volatile("cp.async.commit_group;\n");
    }

    for (int kt = 0; kt < nt; kt++) {
        const int cur = kt & 1;
        if (kt + 1 < nt) {
            const int nb = cur ^ 1;
            const int k0 = (kt + 1) * 32;
#pragma unroll
            for (int p = 0; p < 4; p++) {
                int row = lrow + p * 32;
                CP_ASYNC16(sA_u + (uint32_t)((((nb * 128) + row) * HST + lseg * 8) * 2),
                           Ag + (size_t)p * 32 * K + k0);
                CP_ASYNC16(sB_u + (uint32_t)((((nb * 128) + row) * HST + lseg * 8) * 2),
                           Bg + (size_t)p * 32 * K + k0);
            }
            asm volatile("cp.async.commit_group;\n");
            asm volatile("cp.async.wait_group 1;\n");
        } else {
            asm volatile("cp.async.wait_group 0;\n");
        }
        __syncthreads();

        const uint32_t cA_u = sA_u + (uint32_t)(cur * 128 * HST * 2);
        const uint32_t cB_u = sB_u + (uint32_t)(cur * 128 * HST * 2);

#pragma unroll
        for (int ks = 0; ks < 2; ks++) {
            const int kk = ks * 16;
            uint32_t af[4][4];
#pragma unroll
            for (int im = 0; im < 4; im++)
                LDSM_X4(af[im][0], af[im][1], af[im][2], af[im][3],
                        cA_u + (uint32_t)(((wm + im * 16 + arow) * HST + kk + acol) * 2));
            uint32_t bf[8][2];
#pragma unroll
            for (int j2 = 0; j2 < 4; j2++)
                LDSM_X4(bf[2 * j2][0], bf[2 * j2][1],
                        bf[2 * j2 + 1][0], bf[2 * j2 + 1][1],
                        cB_u + (uint32_t)(((wn + j2 * 16 + brow) * HST + kk + bcol) * 2));
#pragma unroll
            for (int im = 0; im < 4; im++)
#pragma unroll
                for (int in_ = 0; in_ < 8; in_++)
                    MMA_F16(acc[im][in_], af[im][0], af[im][1], af[im][2],
                            af[im][3], bf[in_][0], bf[in_][1]);
        }
        __syncthreads();
    }

    if (z == 2) {
#pragma unroll
        for (int im = 0; im < 4; im++) {
            const int mA = m0 + wm + im * 16 + gp;
#pragma unroll
            for (int in_ = 0; in_ < 8; in_++) {
                const int n = n0 + wn + in_ * 8 + 2 * t4;
                *(__half2*)(Vh + (size_t)mA * N + n) =
                    __floats2half2_rn(acc[im][in_][0], acc[im][in_][1]);
                *(__half2*)(Vh + (size_t)(mA + 8) * N + n) =
                    __floats2half2_rn(acc[im][in_][2], acc[im][in_][3]);
            }
        }
        return;
    }

    // RoPE epilogue (Q/K) via smem exchange. Q scale includes log2(e).
    float* sf = (float*)hsm;   // [128][68] fp32
    if (wn == 64) {
#pragma unroll
        for (int im = 0; im < 4; im++) {
            int row = wm + im * 16 + gp;
#pragma unroll
            for (int in_ = 0; in_ < 8; in_++) {
                int col = in_ * 8 + 2 * t4;
                sf[row * 68 + col]           = acc[im][in_][0];
                sf[row * 68 + col + 1]       = acc[im][in_][1];
                sf[(row + 8) * 68 + col]     = acc[im][in_][2];
                sf[(row + 8) * 68 + col + 1] = acc[im][in_][3];
            }
        }
    }
    __syncthreads();
    if (wn == 0) {
        const float scale = (z == 0)
            ? 0.08838834764831845f * 1.44269504088896340736f : 1.0f;
        __half* Out = (z == 0) ? Qh : Kh;
#pragma unroll
        for (int im = 0; im < 4; im++) {
            int row = wm + im * 16 + gp;
            int sAi = (m0 + row) & (Sc - 1);
            int sBi = (m0 + row + 8) & (Sc - 1);
#pragma unroll
            for (int in_ = 0; in_ < 8; in_++) {
                int col = in_ * 8 + 2 * t4;
                float2 cA  = *(const float2*)(cosp + sAi * DHc + col);
                float2 snA = *(const float2*)(sinp + sAi * DHc + col);
                float2 cB  = *(const float2*)(cosp + sBi * DHc + col);
                float2 snB = *(const float2*)(sinp + sBi * DHc + col);
                float a0 = acc[im][in_][0], a1 = acc[im][in_][1];
                float a2 = acc[im][in_][2], a3 = acc[im][in_][3];
                float b0 = sf[row * 68 + col],       b1 = sf[row * 68 + col + 1];
                float b2 = sf[(row + 8) * 68 + col], b3 = sf[(row + 8) * 68 + col + 1];
                __half2 loA = __floats2half2_rn(scale * (a0 * cA.x - b0 * snA.x),
                                                scale * (a1 * cA.y - b1 * snA.y));
                __half2 hiA = __floats2half2_rn(scale * (b0 * cA.x + a0 * snA.x),
                                                scale * (b1 * cA.y + a1 * snA.y));
                __half2 loB = __floats2half2_rn(scale * (a2 * cB.x - b2 * snB.x),
                                                scale * (a3 * cB.y - b3 * snB.y));
                __half2 hiB = __floats2half2_rn(scale * (b2 * cB.x + a2 * snB.x),
                                                scale * (b3 * cB.y + a3 * snB.y));
                size_t gr = (size_t)(m0 + row) * Dc + n0 + col;
                *(__half2*)(Out + gr)                      = loA;
                *(__half2*)(Out + gr + 64)                 = hiA;
                *(__half2*)(Out + gr + (size_t)8 * Dc)      = loB;
                *(__half2*)(Out + gr + (size_t)8 * Dc + 64) = hiB;
            }
        }
    }
}

// ---------------------------------------------------------------------------
// O projection GEMM, occupancy-shaped: BM=64, BN=128, 128 thr = 4 warps,
// warp tile 64x32 (wn = wid*32), acc 64 regs -> 4+ CTAs/SM; 1024 tiles
// for finer wave granularity. fp32 out.
// ---------------------------------------------------------------------------
constexpr int GO_SMEM_B = (2 * 64 * HST + 2 * 128 * HST) * 2;   // 30720 bytes

__global__ void __launch_bounds__(128, 4) gemm_o(const __half* __restrict__ A,
                                                 const __half* __restrict__ B,
                                                 float* __restrict__ Cf,
                                                 int M, int N, int K) {
    extern __shared__ __half hsm[];
    __half* sA = hsm;                      // [2][64][40]
    __half* sB = hsm + 2 * 64 * HST;       // [2][128][40]

    const int tid  = threadIdx.x;
    const int wid  = tid >> 5;
    const int lane = tid & 31;
    const int wn = wid * 32;
    const int gp = lane >> 2;
    const int t4 = lane & 3;
    const int m0 = blockIdx.y * 64;
    const int n0 = blockIdx.x * 128;

    const int arow = (lane & 7) + ((lane >> 3) & 1) * 8;
    const int acol = (lane >> 4) * 8;
    const int brow = (lane & 7) + (lane >> 4) * 8;
    const int bcol = ((lane >> 3) & 1) * 8;

    const int lrow = tid >> 2;         // 0..31
    const int lseg = tid & 3;
    const __half* Ag = A + (size_t)(m0 + lrow) * K + lseg * 8;
    const __half* Bg = B + (size_t)(n0 + lrow) * K + lseg * 8;

    const uint32_t sA_u = (uint32_t)__cvta_generic_to_shared(sA);
    const uint32_t sB_u = (uint32_t)__cvta_generic_to_shared(sB);

    float acc[4][4][4];
#pragma unroll
    for (int im = 0; im < 4; im++)
#pragma unroll
        for (int in_ = 0; in_ < 4; in_++)
#pragma unroll
            for (int r = 0; r < 4; r++) acc[im][in_][r] = 0.f;

    const int nt = K / 32;

    {
#pragma unroll
        for (int p = 0; p < 2; p++) {      // A: 64 rows
            int row = lrow + p * 32;
            CP_ASYNC16(sA_u + (uint32_t)((row * HST + lseg * 8) * 2),
                       Ag + (size_t)p * 32 * K);
        }
#pragma unroll
        for (int p = 0; p < 4; p++) {      // B: 128 rows
            int row = lrow + p * 32;
            CP_ASYNC16(sB_u + (uint32_t)((row * HST + lseg * 8) * 2),
                       Bg + (size_t)p * 32 * K);
        }
        asm volatile("cp.async.commit_group;\n");
    }

    for (int kt = 0; kt < nt; kt++) {
        const int cur = kt & 1;
        if (kt + 1 < nt) {
            const int nb = cur ^ 1;
            const int k0 = (kt + 1) * 32;
#pragma unroll
            for (int p = 0; p < 2; p++) {
                int row = lrow + p * 32;
                CP_ASYNC16(sA_u + (uint32_t)((((nb * 64) + row) * HST + lseg * 8) * 2),
                           Ag + (size_t)p * 32 * K + k0);
            }
#pragma unroll
            for (int p = 0; p < 4; p++) {
                int row = lrow + p * 32;
                CP_ASYNC16(sB_u + (uint32_t)((((nb * 128) + row) * HST + lseg * 8) * 2),
                           Bg + (size_t)p * 32 * K + k0);
            }
            asm volatile("cp.async.commit_group;\n");
            asm volatile("cp.async.wait_group 1;\n");
        } else {
            asm volatile("cp.async.wait_group 0;\n");
        }
        __syncthreads();

        const uint32_t cA_u = sA_u + (uint32_t)(cur * 64 * HST * 2);
        const uint32_t cB_u = sB_u + (uint32_t)(cur * 128 * HST * 2);

#pragma unroll
        for (int ks = 0; ks < 2; ks++) {
            const int kk = ks * 16;
            uint32_t af[4][4];
#pragma unroll
            for (int im = 0; im < 4; im++)
                LDSM_X4(af[im][0], af[im][1], af[im][2], af[im][3],
                        cA_u + (uint32_t)(((im * 16 + arow) * HST + kk + acol) * 2));
            uint32_t bf[4][2];
#pragma unroll
            for (int j2 = 0; j2 < 2; j2++)
                LDSM_X4(bf[2 * j2][0], bf[2 * j2][1],
                        bf[2 * j2 + 1][0], bf[2 * j2 + 1][1],
                        cB_u + (uint32_t)(((wn + j2 * 16 + brow) * HST + kk + bcol) * 2));
#pragma unroll
            for (int im = 0; im < 4; im++)
#pragma unroll
                for (int in_ = 0; in_ < 4; in_++)
                    MMA_F16(acc[im][in_], af[im][0], af[im][1], af[im][2],
                            af[im][3], bf[in_][0], bf[in_][1]);
        }
        __syncthreads();
    }

#pragma unroll
    for (int im = 0; im < 4; im++) {
        const int mA = m0 + im * 16 + gp;
#pragma unroll
        for (int in_ = 0; in_ < 4; in_++) {
            const int n = n0 + wn + in_ * 8 + 2 * t4;
            *(float2*)(Cf + (size_t)mA * N + n) =
                make_float2(acc[im][in_][0], acc[im][in_][1]);
            *(float2*)(Cf + (size_t)(mA + 8) * N + n) =
                make_float2(acc[im][in_][2], acc[im][in_][3]);
        }
    }
}

// ---------------------------------------------------------------------------
// Flash attention: BM=BN=64, 128 thr / 4 warps, fp16 mma, XOR-swizzled smem,
// 3 CTAs/SM, exp2 softmax, skip-rescale, early K prefetch. Heavy-first:
// qb = gridDim.x-1-blockIdx.x so large-workload CTAs launch first.
// ---------------------------------------------------------------------------
constexpr int OFF_Q  = 0;
constexpr int OFF_K0 = 16384;
constexpr int OFF_K1 = 32768;
constexpr int OFF_V  = 49152;
constexpr int OFF_P  = 65536;
constexpr int FL_SMEM_B = 73728;

__global__ void __launch_bounds__(128, 3) flash_tc(const __half* __restrict__ Q,
                                                   const __half* __restrict__ K,
                                                   const __half* __restrict__ V,
                                                   __half* __restrict__ O) {
    extern __shared__ char smraw[];
    char* sPc = smraw + OFF_P;
    const uint32_t sQ_u  = (uint32_t)__cvta_generic_to_shared(smraw + OFF_Q);
    const uint32_t sK0_u = (uint32_t)__cvta_generic_to_shared(smraw + OFF_K0);
    const uint32_t sK1_u = (uint32_t)__cvta_generic_to_shared(smraw + OFF_K1);
    const uint32_t sV_u  = (uint32_t)__cvta_generic_to_shared(smraw + OFF_V);
    const uint32_t sP_u  = (uint32_t)__cvta_generic_to_shared(sPc);

    const int tid  = threadIdx.x;
    const int wid  = tid >> 5;
    const int lane = tid & 31;
    const int gp   = lane >> 2;
    const int t4   = lane & 3;
    const int qb   = gridDim.x - 1 - blockIdx.x;   // heavy blocks first
    const int bh   = blockIdx.y;
    const int b    = bh >> 4;
    const int h    = bh & (Hc - 1);
    const size_t base = ((size_t)b * Sc) * Dc + (size_t)h * DHc;
    const int q0   = qb * 64;
    const int wrow = wid * 16;
    const int r0loc = wrow + gp;
    const int r1loc = r0loc + 8;

    const int arow = (lane & 7) + ((lane >> 3) & 1) * 8;
    const int aseg = lane >> 4;
    const int brow = (lane & 7) + (lane >> 4) * 8;
    const int bseg = (lane >> 3) & 1;
    const int vrow = (lane & 7) + ((lane >> 3) & 1) * 8;
    const int vseg = lane >> 4;

    // prologue: Q + K0 (group 0), V0 (group 1)
    {
#pragma unroll
        for (int p = 0; p < 8; p++) {
            int idx = tid + p * 128;
            int r = idx >> 4, sg = idx & 15;
            CP_ASYNC16(sQ_u + swz16(r, sg),
                       Q + base + (size_t)(q0 + r) * Dc + sg * 8);
        }
#pragma unroll
        for (int p = 0; p < 8; p++) {
            int idx = tid + p * 128;
            int r = idx >> 4, sg = idx & 15;
            CP_ASYNC16(sK0_u + swz16(r, sg),
                       K + base + (size_t)r * Dc + sg * 8);
        }
        asm volatile("cp.async.commit_group;\n");
#pragma unroll
        for (int p = 0; p < 8; p++) {
            int idx = tid + p * 128;
            int r = idx >> 4, sg = idx & 15;
            CP_ASYNC16(sV_u + swz16(r, sg),
                       V + base + (size_t)r * Dc + sg * 8);
        }
        asm volatile("cp.async.commit_group;\n");
    }

    float o[16][4];
#pragma unroll
    for (int n = 0; n < 16; n++)
#pragma unroll
        for (int r = 0; r < 4; r++) o[n][r] = 0.f;
    float m0 = -1e30f, m1 = -1e30f, l0 = 0.f, l1 = 0.f;

    for (int j = 0; j <= qb; ++j) {
        const uint32_t sKc_u = (j & 1) ? sK1_u : sK0_u;
        const uint32_t sKn_u = (j & 1) ? sK0_u : sK1_u;

        asm volatile("cp.async.wait_group 1;\n");   // K_j (and Q) ready
        __syncthreads();

        // early K(j+1) prefetch
        if (j < qb) {
            const int k0n = (j + 1) * 64;
#pragma unroll
            for (int p = 0; p < 8; p++) {
                int idx = tid + p * 128;
                int r = idx >> 4, sg = idx & 15;
                CP_ASYNC16(sKn_u + swz16(r, sg),
                           K + base + (size_t)(k0n + r) * Dc + sg * 8);
            }
            asm volatile("cp.async.commit_group;\n");
        }

        // ---- S = Qs @ K^T  (log2-domain scores) ----
        float sacc[8][4];
#pragma unroll
        for (int n = 0; n < 8; n++)
#pragma unroll
            for (int r = 0; r < 4; r++) sacc[n][r] = 0.f;

#pragma unroll
        for (int kk8 = 0; kk8 < 8; kk8++) {
            uint32_t a0, a1, a2, a3;
            LDSM_X4(a0, a1, a2, a3,
                    sQ_u + swz16(wrow + arow, kk8 * 2 + aseg));
            uint32_t bf[8][2];
#pragma unroll
            for (int j2 = 0; j2 < 4; j2++)
                LDSM_X4(bf[2 * j2][0], bf[2 * j2][1],
                        bf[2 * j2 + 1][0], bf[2 * j2 + 1][1],
                        sKc_u + swz16(j2 * 16 + brow, kk8 * 2 + bseg));
#pragma unroll
            for (int nt = 0; nt < 8; nt++)
                MMA_F16(sacc[nt], a0, a1, a2, a3, bf[nt][0], bf[nt][1]);
        }

        if (j == qb) {
#pragma unroll
            for (int nt = 0; nt < 8; nt++) {
                int c0 = nt * 8 + 2 * t4;
                if (c0 > r0loc)     sacc[nt][0] = -1e30f;
                if (c0 + 1 > r0loc) sacc[nt][1] = -1e30f;
                if (c0 > r1loc)     sacc[nt][2] = -1e30f;
                if (c0 + 1 > r1loc) sacc[nt][3] = -1e30f;
            }
        }

        // ---- online softmax (exp2 domain) ----
        float mx0 = -1e30f, mx1 = -1e30f;
#pragma unroll
        for (int nt = 0; nt < 8; nt++) {
            mx0 = fmaxf(mx0, fmaxf(sacc[nt][0], sacc[nt][1]));
            mx1 = fmaxf(mx1, fmaxf(sacc[nt][2], sacc[nt][3]));
        }
        mx0 = fmaxf(mx0, __shfl_xor_sync(0xffffffff, mx0, 1));
        mx0 = fmaxf(mx0, __shfl_xor_sync(0xffffffff, mx0, 2));
        mx1 = fmaxf(mx1, __shfl_xor_sync(0xffffffff, mx1, 1));
        mx1 = fmaxf(mx1, __shfl_xor_sync(0xffffffff, mx1, 2));

        float m0n = fmaxf(m0, mx0);
        float m1n = fmaxf(m1, mx1);
        bool nochg = (m0n == m0) && (m1n == m1);
        if (!__all_sync(0xffffffff, nochg)) {
            float corr0 = exp2f(m0 - m0n);
            float corr1 = exp2f(m1 - m1n);
            l0 *= corr0;
            l1 *= corr1;
#pragma unroll
            for (int nt = 0; nt < 16; nt++) {
                o[nt][0] *= corr0; o[nt][1] *= corr0;
                o[nt][2] *= corr1; o[nt][3] *= corr1;
            }
            m0 = m0n; m1 = m1n;
        }

        float ls0 = 0.f, ls1 = 0.f;
#pragma unroll
        for (int nt = 0; nt < 8; nt++) {
            float p0 = exp2f(sacc[nt][0] - m0);
            float p1 = exp2f(sacc[nt][1] - m0);
            float p2 = exp2f(sacc[nt][2] - m1);
            float p3 = exp2f(sacc[nt][3] - m1);
            ls0 += p0 + p1;
            ls1 += p2 + p3;
            *(__half2*)(sPc + swz8(r0loc, nt) + t4 * 4) = __floats2half2_rn(p0, p1);
            *(__half2*)(sPc + swz8(r1loc, nt) + t4 * 4) = __floats2half2_rn(p2, p3);
        }
        ls0 += __shfl_xor_sync(0xffffffff, ls0, 1);
        ls0 += __shfl_xor_sync(0xffffffff, ls0, 2);
        ls1 += __shfl_xor_sync(0xffffffff, ls1, 1);
        ls1 += __shfl_xor_sync(0xffffffff, ls1, 2);
        l0 += ls0;
        l1 += ls1;

        // wait for V_j (leave K_{j+1} in flight)
        if (j < qb) asm volatile("cp.async.wait_group 1;\n");
        else        asm volatile("cp.async.wait_group 0;\n");
        __syncthreads();   // P visible + V ready

        // ---- O += P @ V ----
#pragma unroll
        for (int ks = 0; ks < 4; ks++) {
            const int kk = ks * 16;
            uint32_t a0, a1, a2, a3;
            LDSM_X4(a0, a1, a2, a3,
                    sP_u + swz8(wrow + arow, ks * 2 + aseg));
#pragma unroll
            for (int j2 = 0; j2 < 8; j2++) {
                uint32_t b00, b01, b10, b11;
                LDSM_X4_T(b00, b01, b10, b11,
                          sV_u + swz16(kk + vrow, j2 * 2 + vseg));
                MMA_F16(o[2 * j2],     a0, a1, a2, a3, b00, b01);
                MMA_F16(o[2 * j2 + 1], a0, a1, a2, a3, b10, b11);
            }
        }
        __syncthreads();

        if (j < qb) {
            const int k0n = (j + 1) * 64;
#pragma unroll
            for (int p = 0; p < 8; p++) {
                int idx = tid + p * 128;
                int r = idx >> 4, sg = idx & 15;
                CP_ASYNC16(sV_u + swz16(r, sg),
                           V + base + (size_t)(k0n + r) * Dc + sg * 8);
            }
            asm volatile("cp.async.commit_group;\n");
        }
    }

    float inv0 = 1.0f / l0, inv1 = 1.0f / l1;
    const size_t row0 = base + (size_t)(q0 + r0loc) * Dc;
    const size_t row1 = base + (size_t)(q0 + r1loc) * Dc;
#pragma unroll
    for (int nt = 0; nt < 16; nt++) {
        int c0 = nt * 8 + 2 * t4;
        *(__half2*)(O + row0 + c0) =
            __floats2half2_rn(o[nt][0] * inv0, o[nt][1] * inv0);
        *(__half2*)(O + row1 + c0) =
            __floats2half2_rn(o[nt][2] * inv1, o[nt][3] * inv1);
    }
}

// ---------------------------------------------------------------------------
// Launch
// ---------------------------------------------------------------------------
extern "C" void kernel_launch(void* const* d_in, const int* in_sizes, int n_in,
                              void* d_out, int out_size) {
    const float* x    = (const float*)d_in[0];
    const float* cosp = (const float*)d_in[1];
    const float* sinp = (const float*)d_in[2];
    const float* Wq   = (const float*)d_in[3];
    const float* Wk   = (const float*)d_in[4];
    const float* Wv   = (const float*)d_in[5];
    const float* Wo   = (const float*)d_in[6];
    float* out = (float*)d_out;

    __half *Vh, *xh, *Qh, *Kh, *Ah, *wqh, *wkh, *wvh, *woh;
    cudaGetSymbolAddress((void**)&Vh, g_Vh);
    cudaGetSymbolAddress((void**)&xh, g_xh);
    cudaGetSymbolAddress((void**)&Qh, g_Qh);
    cudaGetSymbolAddress((void**)&Kh, g_Kh);
    cudaGetSymbolAddress((void**)&Ah, g_Ah);
    cudaGetSymbolAddress((void**)&wqh, g_wqh);
    cudaGetSymbolAddress((void**)&wkh, g_wkh);
    cudaGetSymbolAddress((void**)&wvh, g_wvh);
    cudaGetSymbolAddress((void**)&woh, g_woh);

    cudaFuncSetAttribute(gemm_qkv, cudaFuncAttributeMaxDynamicSharedMemorySize,
                         GEMM_SMEM_B);
    cudaFuncSetAttribute(gemm_o, cudaFuncAttributeMaxDynamicSharedMemorySize,
                         GO_SMEM_B);
    cudaFuncSetAttribute(flash_tc, cudaFuncAttributeMaxDynamicSharedMemorySize,
                         FL_SMEM_B);

    // all fp16 conversions in one launch
    {
        const int nw = Dc * Dc / 4;
        dim3 cgrid((nw + 255) / 256, 6);
        cvt_all<<<cgrid, 256>>>(x, Wq, Wk, Wv, Wo,
                                xh, wqh, wkh, wvh, woh, nw);
    }

    // fused QKV projections + RoPE/scale epilogue
    {
        dim3 qgrid(Dc / 128, Mc / 128, 3);   // (16, 32, 3)
        gemm_qkv<<<qgrid, 128, GEMM_SMEM_B>>>(xh, wqh, wkh, wvh,
                                              Qh, Kh, Vh, cosp, sinp);
    }

    // flash attention (heavy-first)
    {
        dim3 fgrid(Sc / 64, Bc * Hc);   // (32, 32)
        flash_tc<<<fgrid, 128, FL_SMEM_B>>>(Qh, Kh, Vh, Ah);
    }

    // O projection (occupancy-shaped, fp32 out)
    {
        dim3 ggrid(Dc / 128, Mc / 64);   // (16, 64)
        gemm_o<<<ggrid, 128, GO_SMEM_B>>>(Ah, woh, out, Mc, Dc, Dc);
    }
}

// round 14
// speedup vs baseline: 1.2081x; 1.0604x over previous
#include <cuda_runtime.h>
#include <cuda_fp16.h>
#include <math.h>
#include <stdint.h>

// Problem constants
constexpr int Bc  = 2;
constexpr int Sc  = 2048;
constexpr int Dc  = 2048;
constexpr int Hc  = 16;
constexpr int DHc = 128;
constexpr int Mc  = Bc * Sc;   // 4096 rows for projections

// ---------------------------------------------------------------------------
// Scratch (device globals: allocation-free per harness rules)
// ---------------------------------------------------------------------------
__device__ __half g_Vh [(size_t)Mc * Dc];      // half V
__device__ __half g_xh [(size_t)Mc * Dc];
__device__ __half g_Qh [(size_t)Mc * Dc];      // roped + (scale*log2e)-scaled
__device__ __half g_Kh [(size_t)Mc * Dc];      // roped
__device__ __half g_Ah [(size_t)Mc * Dc];      // attention out (half)
__device__ __half g_wqh[(size_t)Dc * Dc];
__device__ __half g_wkh[(size_t)Dc * Dc];
__device__ __half g_wvh[(size_t)Dc * Dc];
__device__ __half g_woh[(size_t)Dc * Dc];

#define CP_ASYNC16(dst, src) \
    asm volatile("cp.async.cg.shared.global [%0], [%1], 16;\n" :: "r"(dst), "l"(src))

#define MMA_F16(c, a0, a1, a2, a3, b0, b1)                                     \
    asm volatile(                                                              \
        "mma.sync.aligned.m16n8k16.row.col.f32.f16.f16.f32 "                   \
        "{%0,%1,%2,%3}, {%4,%5,%6,%7}, {%8,%9}, {%0,%1,%2,%3};\n"              \
        : "+f"((c)[0]), "+f"((c)[1]), "+f"((c)[2]), "+f"((c)[3])               \
        : "r"(a0), "r"(a1), "r"(a2), "r"(a3), "r"(b0), "r"(b1))

#define LDSM_X4(r0, r1, r2, r3, addr)                                          \
    asm volatile("ldmatrix.sync.aligned.m8n8.x4.shared.b16 {%0,%1,%2,%3}, [%4];" \
        : "=r"(r0), "=r"(r1), "=r"(r2), "=r"(r3) : "r"(addr))

#define LDSM_X4_T(r0, r1, r2, r3, addr)                                        \
    asm volatile("ldmatrix.sync.aligned.m8n8.x4.trans.shared.b16 {%0,%1,%2,%3}, [%4];" \
        : "=r"(r0), "=r"(r1), "=r"(r2), "=r"(r3) : "r"(addr))

// 16B-granular XOR swizzles (byte offsets). Row widths: 16 segs (QKV), 8 (P).
__device__ __forceinline__ uint32_t swz16(int row, int seg) {
    return (uint32_t)((row * 16 + (seg ^ (row & 7))) << 4);
}
__device__ __forceinline__ uint32_t swz8(int row, int seg) {
    return (uint32_t)((row * 8 + (seg ^ (row & 7))) << 4);
}

// ---------------------------------------------------------------------------
// fp32 -> fp16: all five inputs in one launch. y<4: weights; y=4,5: x halves.
// ---------------------------------------------------------------------------
__global__ void cvt_all(const float* __restrict__ x,
                        const float* __restrict__ w0, const float* __restrict__ w1,
                        const float* __restrict__ w2, const float* __restrict__ w3,
                        __half* __restrict__ xh,
                        __half* __restrict__ o0, __half* __restrict__ o1,
                        __half* __restrict__ o2, __half* __restrict__ o3, int n4) {
    int i = blockIdx.x * blockDim.x + threadIdx.x;
    if (i >= n4) return;
    const float* in;
    __half* out;
    switch (blockIdx.y) {
        case 0:  in = w0; out = o0; break;
        case 1:  in = w1; out = o1; break;
        case 2:  in = w2; out = o2; break;
        case 3:  in = w3; out = o3; break;
        case 4:  in = x;                     out = xh;                     break;
        default: in = x + (size_t)n4 * 4;    out = xh + (size_t)n4 * 4;    break;
    }
    float4 v = *(const float4*)(in + (size_t)i * 4);
    __half2 h01 = __floats2half2_rn(v.x, v.y);
    __half2 h23 = __floats2half2_rn(v.z, v.w);
    uint2 u;
    u.x = *(uint32_t*)&h01;
    u.y = *(uint32_t*)&h23;
    *(uint2*)(out + (size_t)i * 4) = u;
}

// ---------------------------------------------------------------------------
// Shared GEMM constants
// ---------------------------------------------------------------------------
constexpr int HST = 40;                          // halves per smem row
constexpr int QKV_STG_H = 256 * HST;             // stage: A 128 + B 128 rows
constexpr int GEMM_SMEM_B = 3 * QKV_STG_H * 2;   // 61440 bytes (3-stage)
constexpr int GO_STG_H = 192 * HST;              // stage: A 64 + B 128 rows
constexpr int GO_SMEM_B = 3 * GO_STG_H * 2;      // 46080 bytes (3-stage)

// ---------------------------------------------------------------------------
// Fused QKV projection: BM=BN=128, BK=32, 128 thr, 3-stage cp.async pipeline
// (loads issued after the barrier into stage (kt+2)%3 — race-free).
// z selects W/output; z<2 fuses RoPE (+ Q scale with log2e folded in).
// ---------------------------------------------------------------------------
__global__ void __launch_bounds__(128, 3) gemm_qkv(
    const __half* __restrict__ A,
    const __half* __restrict__ Bq, const __half* __restrict__ Bk,
    const __half* __restrict__ Bv,
    __half* __restrict__ Qh, __half* __restrict__ Kh, __half* __restrict__ Vh,
    const float* __restrict__ cosp, const float* __restrict__ sinp) {
    extern __shared__ __half hsm[];

    const int z = blockIdx.z;
    const __half* B = (z == 0) ? Bq : ((z == 1) ? Bk : Bv);
    const int K = Dc, N = Dc;

    const int tid  = threadIdx.x;
    const int wid  = tid >> 5;
    const int lane = tid & 31;
    const int wm = (wid & 1) * 64;
    const int wn = (wid >> 1) * 64;
    const int gp = lane >> 2;
    const int t4 = lane & 3;
    const int m0 = blockIdx.y * 128;
    const int n0 = blockIdx.x * 128;

    const int arow = (lane & 7) + ((lane >> 3) & 1) * 8;
    const int acol = (lane >> 4) * 8;
    const int brow = (lane & 7) + (lane >> 4) * 8;
    const int bcol = ((lane >> 3) & 1) * 8;

    const int lrow = tid >> 2;
    const int lseg = tid & 3;
    const __half* Ag = A + (size_t)(m0 + lrow) * K + lseg * 8;
    const __half* Bg = B + (size_t)(n0 + lrow) * K + lseg * 8;

    const uint32_t sS_u = (uint32_t)__cvta_generic_to_shared(hsm);

    auto load_st = [&](int st, int k0) {
        uint32_t bA = sS_u + (uint32_t)(st * QKV_STG_H * 2);
        uint32_t bB = bA + (uint32_t)(128 * HST * 2);
#pragma unroll
        for (int p = 0; p < 4; p++) {
            int row = lrow + p * 32;
            CP_ASYNC16(bA + (uint32_t)((row * HST + lseg * 8) * 2),
                       Ag + (size_t)p * 32 * K + k0);
            CP_ASYNC16(bB + (uint32_t)((row * HST + lseg * 8) * 2),
                       Bg + (size_t)p * 32 * K + k0);
        }
        asm volatile("cp.async.commit_group;\n");
    };

    float acc[4][8][4];
#pragma unroll
    for (int im = 0; im < 4; im++)
#pragma unroll
        for (int in_ = 0; in_ < 8; in_++)
#pragma unroll
            for (int r = 0; r < 4; r++) acc[im][in_][r] = 0.f;

    const int nt = K / 32;

    load_st(0, 0);
    load_st(1, 32);

    int cs = 0, ld = 2;
    for (int kt = 0; kt < nt; kt++) {
        if (kt + 1 < nt) asm volatile("cp.async.wait_group 1;\n");
        else             asm volatile("cp.async.wait_group 0;\n");
        __syncthreads();

        if (kt + 2 < nt) {
            load_st(ld, (kt + 2) * 32);
            ld = (ld == 2) ? 0 : ld + 1;
        }

        const uint32_t cA_u = sS_u + (uint32_t)(cs * QKV_STG_H * 2);
        const uint32_t cB_u = cA_u + (uint32_t)(128 * HST * 2);
        cs = (cs == 2) ? 0 : cs + 1;

#pragma unroll
        for (int ks = 0; ks < 2; ks++) {
            const int kk = ks * 16;
            uint32_t af[4][4];
#pragma unroll
            for (int im = 0; im < 4; im++)
                LDSM_X4(af[im][0], af[im][1], af[im][2], af[im][3],
                        cA_u + (uint32_t)(((wm + im * 16 + arow) * HST + kk + acol) * 2));
            uint32_t bf[8][2];
#pragma unroll
            for (int j2 = 0; j2 < 4; j2++)
                LDSM_X4(bf[2 * j2][0], bf[2 * j2][1],
                        bf[2 * j2 + 1][0], bf[2 * j2 + 1][1],
                        cB_u + (uint32_t)(((wn + j2 * 16 + brow) * HST + kk + bcol) * 2));
#pragma unroll
            for (int im = 0; im < 4; im++)
#pragma unroll
                for (int in_ = 0; in_ < 8; in_++)
                    MMA_F16(acc[im][in_], af[im][0], af[im][1], af[im][2],
                            af[im][3], bf[in_][0], bf[in_][1]);
        }
    }
    __syncthreads();   // done with smem before epilogue reuses it

    if (z == 2) {
#pragma unroll
        for (int im = 0; im < 4; im++) {
            const int mA = m0 + wm + im * 16 + gp;
#pragma unroll
            for (int in_ = 0; in_ < 8; in_++) {
                const int n = n0 + wn + in_ * 8 + 2 * t4;
                *(__half2*)(Vh + (size_t)mA * N + n) =
                    __floats2half2_rn(acc[im][in_][0], acc[im][in_][1]);
                *(__half2*)(Vh + (size_t)(mA + 8) * N + n) =
                    __floats2half2_rn(acc[im][in_][2], acc[im][in_][3]);
            }
        }
        return;
    }

    // RoPE epilogue (Q/K) via smem exchange. Q scale includes log2(e).
    float* sf = (float*)hsm;   // [128][68] fp32 = 34816 B <= 61440 B
    if (wn == 64) {
#pragma unroll
        for (int im = 0; im < 4; im++) {
            int row = wm + im * 16 + gp;
#pragma unroll
            for (int in_ = 0; in_ < 8; in_++) {
                int col = in_ * 8 + 2 * t4;
                sf[row * 68 + col]           = acc[im][in_][0];
                sf[row * 68 + col + 1]       = acc[im][in_][1];
                sf[(row + 8) * 68 + col]     = acc[im][in_][2];
                sf[(row + 8) * 68 + col + 1] = acc[im][in_][3];
            }
        }
    }
    __syncthreads();
    if (wn == 0) {
        const float scale = (z == 0)
            ? 0.08838834764831845f * 1.44269504088896340736f : 1.0f;
        __half* Out = (z == 0) ? Qh : Kh;
#pragma unroll
        for (int im = 0; im < 4; im++) {
            int row = wm + im * 16 + gp;
            int sAi = (m0 + row) & (Sc - 1);
            int sBi = (m0 + row + 8) & (Sc - 1);
#pragma unroll
            for (int in_ = 0; in_ < 8; in_++) {
                int col = in_ * 8 + 2 * t4;
                float2 cA  = *(const float2*)(cosp + sAi * DHc + col);
                float2 snA = *(const float2*)(sinp + sAi * DHc + col);
                float2 cB  = *(const float2*)(cosp + sBi * DHc + col);
                float2 snB = *(const float2*)(sinp + sBi * DHc + col);
                float a0 = acc[im][in_][0], a1 = acc[im][in_][1];
                float a2 = acc[im][in_][2], a3 = acc[im][in_][3];
                float b0 = sf[row * 68 + col],       b1 = sf[row * 68 + col + 1];
                float b2 = sf[(row + 8) * 68 + col], b3 = sf[(row + 8) * 68 + col + 1];
                __half2 loA = __floats2half2_rn(scale * (a0 * cA.x - b0 * snA.x),
                                                scale * (a1 * cA.y - b1 * snA.y));
                __half2 hiA = __floats2half2_rn(scale * (b0 * cA.x + a0 * snA.x),
                                                scale * (b1 * cA.y + a1 * snA.y));
                __half2 loB = __floats2half2_rn(scale * (a2 * cB.x - b2 * snB.x),
                                                scale * (a3 * cB.y - b3 * snB.y));
                __half2 hiB = __floats2half2_rn(scale * (b2 * cB.x + a2 * snB.x),
                                                scale * (b3 * cB.y + a3 * snB.y));
                size_t gr = (size_t)(m0 + row) * Dc + n0 + col;
                *(__half2*)(Out + gr)                      = loA;
                *(__half2*)(Out + gr + 64)                 = hiA;
                *(__half2*)(Out + gr + (size_t)8 * Dc)      = loB;
                *(__half2*)(Out + gr + (size_t)8 * Dc + 64) = hiB;
            }
        }
    }
}

// ---------------------------------------------------------------------------
// O projection GEMM: BM=64, BN=128, 128 thr, warp tile 64x32, 3-stage
// pipeline (same race-free structure), 4 CTAs/SM. fp32 out.
// ---------------------------------------------------------------------------
__global__ void __launch_bounds__(128, 4) gemm_o(const __half* __restrict__ A,
                                                 const __half* __restrict__ B,
                                                 float* __restrict__ Cf,
                                                 int M, int N, int K) {
    extern __shared__ __half hsm[];

    const int tid  = threadIdx.x;
    const int wid  = tid >> 5;
    const int lane = tid & 31;
    const int wn = wid * 32;
    const int gp = lane >> 2;
    const int t4 = lane & 3;
    const int m0 = blockIdx.y * 64;
    const int n0 = blockIdx.x * 128;

    const int arow = (lane & 7) + ((lane >> 3) & 1) * 8;
    const int acol = (lane >> 4) * 8;
    const int brow = (lane & 7) + (lane >> 4) * 8;
    const int bcol = ((lane >> 3) & 1) * 8;

    const int lrow = tid >> 2;         // 0..31
    const int lseg = tid & 3;
    const __half* Ag = A + (size_t)(m0 + lrow) * K + lseg * 8;
    const __half* Bg = B + (size_t)(n0 + lrow) * K + lseg * 8;

    const uint32_t sS_u = (uint32_t)__cvta_generic_to_shared(hsm);

    auto load_st = [&](int st, int k0) {
        uint32_t bA = sS_u + (uint32_t)(st * GO_STG_H * 2);
        uint32_t bB = bA + (uint32_t)(64 * HST * 2);
#pragma unroll
        for (int p = 0; p < 2; p++) {
            int row = lrow + p * 32;
            CP_ASYNC16(bA + (uint32_t)((row * HST + lseg * 8) * 2),
                       Ag + (size_t)p * 32 * K + k0);
        }
#pragma unroll
        for (int p = 0; p < 4; p++) {
            int row = lrow + p * 32;
            CP_ASYNC16(bB + (uint32_t)((row * HST + lseg * 8) * 2),
                       Bg + (size_t)p * 32 * K + k0);
        }
        asm volatile("cp.async.commit_group;\n");
    };

    float acc[4][4][4];
#pragma unroll
    for (int im = 0; im < 4; im++)
#pragma unroll
        for (int in_ = 0; in_ < 4; in_++)
#pragma unroll
            for (int r = 0; r < 4; r++) acc[im][in_][r] = 0.f;

    const int nt = K / 32;

    load_st(0, 0);
    load_st(1, 32);

    int cs = 0, ld = 2;
    for (int kt = 0; kt < nt; kt++) {
        if (kt + 1 < nt) asm volatile("cp.async.wait_group 1;\n");
        else             asm volatile("cp.async.wait_group 0;\n");
        __syncthreads();

        if (kt + 2 < nt) {
            load_st(ld, (kt + 2) * 32);
            ld = (ld == 2) ? 0 : ld + 1;
        }

        const uint32_t cA_u = sS_u + (uint32_t)(cs * GO_STG_H * 2);
        const uint32_t cB_u = cA_u + (uint32_t)(64 * HST * 2);
        cs = (cs == 2) ? 0 : cs + 1;

#pragma unroll
        for (int ks = 0; ks < 2; ks++) {
            const int kk = ks * 16;
            uint32_t af[4][4];
#pragma unroll
            for (int im = 0; im < 4; im++)
                LDSM_X4(af[im][0], af[im][1], af[im][2], af[im][3],
                        cA_u + (uint32_t)(((im * 16 + arow) * HST + kk + acol) * 2));
            uint32_t bf[4][2];
#pragma unroll
            for (int j2 = 0; j2 < 2; j2++)
                LDSM_X4(bf[2 * j2][0], bf[2 * j2][1],
                        bf[2 * j2 + 1][0], bf[2 * j2 + 1][1],
                        cB_u + (uint32_t)(((wn + j2 * 16 + brow) * HST + kk + bcol) * 2));
#pragma unroll
            for (int im = 0; im < 4; im++)
#pragma unroll
                for (int in_ = 0; in_ < 4; in_++)
                    MMA_F16(acc[im][in_], af[im][0], af[im][1], af[im][2],
                            af[im][3], bf[in_][0], bf[in_][1]);
        }
    }

#pragma unroll
    for (int im = 0; im < 4; im++) {
        const int mA = m0 + im * 16 + gp;
#pragma unroll
        for (int in_ = 0; in_ < 4; in_++) {
            const int n = n0 + wn + in_ * 8 + 2 * t4;
            *(float2*)(Cf + (size_t)mA * N + n) =
                make_float2(acc[im][in_][0], acc[im][in_][1]);
            *(float2*)(Cf + (size_t)(mA + 8) * N + n) =
                make_float2(acc[im][in_][2], acc[im][in_][3]);
        }
    }
}

// ---------------------------------------------------------------------------
// Flash attention: BM=BN=64, 128 thr / 4 warps, fp16 mma, XOR-swizzled smem,
// 3 CTAs/SM, exp2 softmax, skip-rescale, early K prefetch, heavy-first.
// (Unchanged from round 13.)
// ---------------------------------------------------------------------------
constexpr int OFF_Q  = 0;
constexpr int OFF_K0 = 16384;
constexpr int OFF_K1 = 32768;
constexpr int OFF_V  = 49152;
constexpr int OFF_P  = 65536;
constexpr int FL_SMEM_B = 73728;

__global__ void __launch_bounds__(128, 3) flash_tc(const __half* __restrict__ Q,
                                                   const __half* __restrict__ K,
                                                   const __half* __restrict__ V,
                                                   __half* __restrict__ O) {
    extern __shared__ char smraw[];
    char* sPc = smraw + OFF_P;
    const uint32_t sQ_u  = (uint32_t)__cvta_generic_to_shared(smraw + OFF_Q);
    const uint32_t sK0_u = (uint32_t)__cvta_generic_to_shared(smraw + OFF_K0);
    const uint32_t sK1_u = (uint32_t)__cvta_generic_to_shared(smraw + OFF_K1);
    const uint32_t sV_u  = (uint32_t)__cvta_generic_to_shared(smraw + OFF_V);
    const uint32_t sP_u  = (uint32_t)__cvta_generic_to_shared(sPc);

    const int tid  = threadIdx.x;
    const int wid  = tid >> 5;
    const int lane = tid & 31;
    const int gp   = lane >> 2;
    const int t4   = lane & 3;
    const int qb   = gridDim.x - 1 - blockIdx.x;   // heavy blocks first
    const int bh   = blockIdx.y;
    const int b    = bh >> 4;
    const int h    = bh & (Hc - 1);
    const size_t base = ((size_t)b * Sc) * Dc + (size_t)h * DHc;
    const int q0   = qb * 64;
    const int wrow = wid * 16;
    const int r0loc = wrow + gp;
    const int r1loc = r0loc + 8;

    const int arow = (lane & 7) + ((lane >> 3) & 1) * 8;
    const int aseg = lane >> 4;
    const int brow = (lane & 7) + (lane >> 4) * 8;
    const int bseg = (lane >> 3) & 1;
    const int vrow = (lane & 7) + ((lane >> 3) & 1) * 8;
    const int vseg = lane >> 4;

    {
#pragma unroll
        for (int p = 0; p < 8; p++) {
            int idx = tid + p * 128;
            int r = idx >> 4, sg = idx & 15;
            CP_ASYNC16(sQ_u + swz16(r, sg),
                       Q + base + (size_t)(q0 + r) * Dc + sg * 8);
        }
#pragma unroll
        for (int p = 0; p < 8; p++) {
            int idx = tid + p * 128;
            int r = idx >> 4, sg = idx & 15;
            CP_ASYNC16(sK0_u + swz16(r, sg),
                       K + base + (size_t)r * Dc + sg * 8);
        }
        asm volatile("cp.async.commit_group;\n");
#pragma unroll
        for (int p = 0; p < 8; p++) {
            int idx = tid + p * 128;
            int r = idx >> 4, sg = idx & 15;
            CP_ASYNC16(sV_u + swz16(r, sg),
                       V + base + (size_t)r * Dc + sg * 8);
        }
        asm volatile("cp.async.commit_group;\n");
    }

    float o[16][4];
#pragma unroll
    for (int n = 0; n < 16; n++)
#pragma unroll
        for (int r = 0; r < 4; r++) o[n][r] = 0.f;
    float m0 = -1e30f, m1 = -1e30f, l0 = 0.f, l1 = 0.f;

    for (int j = 0; j <= qb; ++j) {
        const uint32_t sKc_u = (j & 1) ? sK1_u : sK0_u;
        const uint32_t sKn_u = (j & 1) ? sK0_u : sK1_u;

        asm volatile("cp.async.wait_group 1;\n");
        __syncthreads();

        if (j < qb) {
            const int k0n = (j + 1) * 64;
#pragma unroll
            for (int p = 0; p < 8; p++) {
                int idx = tid + p * 128;
                int r = idx >> 4, sg = idx & 15;
                CP_ASYNC16(sKn_u + swz16(r, sg),
                           K + base + (size_t)(k0n + r) * Dc + sg * 8);
            }
            asm volatile("cp.async.commit_group;\n");
        }

        float sacc[8][4];
#pragma unroll
        for (int n = 0; n < 8; n++)
#pragma unroll
            for (int r = 0; r < 4; r++) sacc[n][r] = 0.f;

#pragma unroll
        for (int kk8 = 0; kk8 < 8; kk8++) {
            uint32_t a0, a1, a2, a3;
            LDSM_X4(a0, a1, a2, a3,
                    sQ_u + swz16(wrow + arow, kk8 * 2 + aseg));
            uint32_t bf[8][2];
#pragma unroll
            for (int j2 = 0; j2 < 4; j2++)
                LDSM_X4(bf[2 * j2][0], bf[2 * j2][1],
                        bf[2 * j2 + 1][0], bf[2 * j2 + 1][1],
                        sKc_u + swz16(j2 * 16 + brow, kk8 * 2 + bseg));
#pragma unroll
            for (int nt = 0; nt < 8; nt++)
                MMA_F16(sacc[nt], a0, a1, a2, a3, bf[nt][0], bf[nt][1]);
        }

        if (j == qb) {
#pragma unroll
            for (int nt = 0; nt < 8; nt++) {
                int c0 = nt * 8 + 2 * t4;
                if (c0 > r0loc)     sacc[nt][0] = -1e30f;
                if (c0 + 1 > r0loc) sacc[nt][1] = -1e30f;
                if (c0 > r1loc)     sacc[nt][2] = -1e30f;
                if (c0 + 1 > r1loc) sacc[nt][3] = -1e30f;
            }
        }

        float mx0 = -1e30f, mx1 = -1e30f;
#pragma unroll
        for (int nt = 0; nt < 8; nt++) {
            mx0 = fmaxf(mx0, fmaxf(sacc[nt][0], sacc[nt][1]));
            mx1 = fmaxf(mx1, fmaxf(sacc[nt][2], sacc[nt][3]));
        }
        mx0 = fmaxf(mx0, __shfl_xor_sync(0xffffffff, mx0, 1));
        mx0 = fmaxf(mx0, __shfl_xor_sync(0xffffffff, mx0, 2));
        mx1 = fmaxf(mx1, __shfl_xor_sync(0xffffffff, mx1, 1));
        mx1 = fmaxf(mx1, __shfl_xor_sync(0xffffffff, mx1, 2));

        float m0n = fmaxf(m0, mx0);
        float m1n = fmaxf(m1, mx1);
        bool nochg = (m0n == m0) && (m1n == m1);
        if (!__all_sync(0xffffffff, nochg)) {
            float corr0 = exp2f(m0 - m0n);
            float corr1 = exp2f(m1 - m1n);
            l0 *= corr0;
            l1 *= corr1;
#pragma unroll
            for (int nt = 0; nt < 16; nt++) {
                o[nt][0] *= corr0; o[nt][1] *= corr0;
                o[nt][2] *= corr1; o[nt][3] *= corr1;
            }
            m0 = m0n; m1 = m1n;
        }

        float ls0 = 0.f, ls1 = 0.f;
#pragma unroll
        for (int nt = 0; nt < 8; nt++) {
            float p0 = exp2f(sacc[nt][0] - m0);
            float p1 = exp2f(sacc[nt][1] - m0);
            float p2 = exp2f(sacc[nt][2] - m1);
            float p3 = exp2f(sacc[nt][3] - m1);
            ls0 += p0 + p1;
            ls1 += p2 + p3;
            *(__half2*)(sPc + swz8(r0loc, nt) + t4 * 4) = __floats2half2_rn(p0, p1);
            *(__half2*)(sPc + swz8(r1loc, nt) + t4 * 4) = __floats2half2_rn(p2, p3);
        }
        ls0 += __shfl_xor_sync(0xffffffff, ls0, 1);
        ls0 += __shfl_xor_sync(0xffffffff, ls0, 2);
        ls1 += __shfl_xor_sync(0xffffffff, ls1, 1);
        ls1 += __shfl_xor_sync(0xffffffff, ls1, 2);
        l0 += ls0;
        l1 += ls1;

        if (j < qb) asm volatile("cp.async.wait_group 1;\n");
        else        asm volatile("cp.async.wait_group 0;\n");
        __syncthreads();

#pragma unroll
        for (int ks = 0; ks < 4; ks++) {
            const int kk = ks * 16;
            uint32_t a0, a1, a2, a3;
            LDSM_X4(a0, a1, a2, a3,
                    sP_u + swz8(wrow + arow, ks * 2 + aseg));
#pragma unroll
            for (int j2 = 0; j2 < 8; j2++) {
                uint32_t b00, b01, b10, b11;
                LDSM_X4_T(b00, b01, b10, b11,
                          sV_u + swz16(kk + vrow, j2 * 2 + vseg));
                MMA_F16(o[2 * j2],     a0, a1, a2, a3, b00, b01);
                MMA_F16(o[2 * j2 + 1], a0, a1, a2, a3, b10, b11);
            }
        }
        __syncthreads();

        if (j < qb) {
            const int k0n = (j + 1) * 64;
#pragma unroll
            for (int p = 0; p < 8; p++) {
                int idx = tid + p * 128;
                int r = idx >> 4, sg = idx & 15;
                CP_ASYNC16(sV_u + swz16(r, sg),
                           V + base + (size_t)(k0n + r) * Dc + sg * 8);
            }
            asm volatile("cp.async.commit_group;\n");
        }
    }

    float inv0 = 1.0f / l0, inv1 = 1.0f / l1;
    const size_t row0 = base + (size_t)(q0 + r0loc) * Dc;
    const size_t row1 = base + (size_t)(q0 + r1loc) * Dc;
#pragma unroll
    for (int nt = 0; nt < 16; nt++) {
        int c0 = nt * 8 + 2 * t4;
        *(__half2*)(O + row0 + c0) =
            __floats2half2_rn(o[nt][0] * inv0, o[nt][1] * inv0);
        *(__half2*)(O + row1 + c0) =
            __floats2half2_rn(o[nt][2] * inv1, o[nt][3] * inv1);
    }
}

// ---------------------------------------------------------------------------
// Launch
// ---------------------------------------------------------------------------
extern "C" void kernel_launch(void* const* d_in, const int* in_sizes, int n_in,
                              void* d_out, int out_size) {
    const float* x    = (const float*)d_in[0];
    const float* cosp = (const float*)d_in[1];
    const float* sinp = (const float*)d_in[2];
    const float* Wq   = (const float*)d_in[3];
    const float* Wk   = (const float*)d_in[4];
    const float* Wv   = (const float*)d_in[5];
    const float* Wo   = (const float*)d_in[6];
    float* out = (float*)d_out;

    __half *Vh, *xh, *Qh, *Kh, *Ah, *wqh, *wkh, *wvh, *woh;
    cudaGetSymbolAddress((void**)&Vh, g_Vh);
    cudaGetSymbolAddress((void**)&xh, g_xh);
    cudaGetSymbolAddress((void**)&Qh, g_Qh);
    cudaGetSymbolAddress((void**)&Kh, g_Kh);
    cudaGetSymbolAddress((void**)&Ah, g_Ah);
    cudaGetSymbolAddress((void**)&wqh, g_wqh);
    cudaGetSymbolAddress((void**)&wkh, g_wkh);
    cudaGetSymbolAddress((void**)&wvh, g_wvh);
    cudaGetSymbolAddress((void**)&woh, g_woh);

    cudaFuncSetAttribute(gemm_qkv, cudaFuncAttributeMaxDynamicSharedMemorySize,
                         GEMM_SMEM_B);
    cudaFuncSetAttribute(gemm_o, cudaFuncAttributeMaxDynamicSharedMemorySize,
                         GO_SMEM_B);
    cudaFuncSetAttribute(flash_tc, cudaFuncAttributeMaxDynamicSharedMemorySize,
                         FL_SMEM_B);

    // all fp16 conversions in one launch
    {
        const int nw = Dc * Dc / 4;
        dim3 cgrid((nw + 255) / 256, 6);
        cvt_all<<<cgrid, 256>>>(x, Wq, Wk, Wv, Wo,
                                xh, wqh, wkh, wvh, woh, nw);
    }

    // fused QKV projections + RoPE/scale epilogue (3-stage pipeline)
    {
        dim3 qgrid(Dc / 128, Mc / 128, 3);   // (16, 32, 3)
        gemm_qkv<<<qgrid, 128, GEMM_SMEM_B>>>(xh, wqh, wkh, wvh,
                                              Qh, Kh, Vh, cosp, sinp);
    }

    // flash attention (heavy-first)
    {
        dim3 fgrid(Sc / 64, Bc * Hc);   // (32, 32)
        flash_tc<<<fgrid, 128, FL_SMEM_B>>>(Qh, Kh, Vh, Ah);
    }

    // O projection (3-stage pipeline, fp32 out)
    {
        dim3 ggrid(Dc / 128, Mc / 64);   // (16, 64)
        gemm_o<<<ggrid, 128, GO_SMEM_B>>>(Ah, woh, out, Mc, Dc, Dc);
    }
}

// round 15
// speedup vs baseline: 1.2190x; 1.0091x over previous
#include <cuda_runtime.h>
#include <cuda_fp16.h>
#include <math.h>
#include <stdint.h>

// Problem constants
constexpr int Bc  = 2;
constexpr int Sc  = 2048;
constexpr int Dc  = 2048;
constexpr int Hc  = 16;
constexpr int DHc = 128;
constexpr int Mc  = Bc * Sc;   // 4096 rows for projections

// ---------------------------------------------------------------------------
// Scratch (device globals: allocation-free per harness rules)
// ---------------------------------------------------------------------------
__device__ __half g_Vh [(size_t)Mc * Dc];      // half V
__device__ __half g_xh [(size_t)Mc * Dc];
__device__ __half g_Qh [(size_t)Mc * Dc];      // roped + (scale*log2e)-scaled
__device__ __half g_Kh [(size_t)Mc * Dc];      // roped
__device__ __half g_Ah [(size_t)Mc * Dc];      // attention out (half)
__device__ __half g_wqh[(size_t)Dc * Dc];
__device__ __half g_wkh[(size_t)Dc * Dc];
__device__ __half g_wvh[(size_t)Dc * Dc];
__device__ __half g_woh[(size_t)Dc * Dc];

#define CP_ASYNC16(dst, src) \
    asm volatile("cp.async.cg.shared.global [%0], [%1], 16;\n" :: "r"(dst), "l"(src))

#define MMA_F16(c, a0, a1, a2, a3, b0, b1)                                     \
    asm volatile(                                                              \
        "mma.sync.aligned.m16n8k16.row.col.f32.f16.f16.f32 "                   \
        "{%0,%1,%2,%3}, {%4,%5,%6,%7}, {%8,%9}, {%0,%1,%2,%3};\n"              \
        : "+f"((c)[0]), "+f"((c)[1]), "+f"((c)[2]), "+f"((c)[3])               \
        : "r"(a0), "r"(a1), "r"(a2), "r"(a3), "r"(b0), "r"(b1))

#define LDSM_X4(r0, r1, r2, r3, addr)                                          \
    asm volatile("ldmatrix.sync.aligned.m8n8.x4.shared.b16 {%0,%1,%2,%3}, [%4];" \
        : "=r"(r0), "=r"(r1), "=r"(r2), "=r"(r3) : "r"(addr))

#define LDSM_X4_T(r0, r1, r2, r3, addr)                                        \
    asm volatile("ldmatrix.sync.aligned.m8n8.x4.trans.shared.b16 {%0,%1,%2,%3}, [%4];" \
        : "=r"(r0), "=r"(r1), "=r"(r2), "=r"(r3) : "r"(addr))

// 16B-granular XOR swizzles (byte offsets). Row widths: 16 segs (QKV), 8 (P).
__device__ __forceinline__ uint32_t swz16(int row, int seg) {
    return (uint32_t)((row * 16 + (seg ^ (row & 7))) << 4);
}
__device__ __forceinline__ uint32_t swz8(int row, int seg) {
    return (uint32_t)((row * 8 + (seg ^ (row & 7))) << 4);
}

// ---------------------------------------------------------------------------
// fp32 -> fp16: all five inputs, one launch, 4 independent float4 per thread
// (MLP=4 covers DRAM latency). y<4: weights; y=4,5: x halves.
// ---------------------------------------------------------------------------
__global__ void cvt_all(const float* __restrict__ x,
                        const float* __restrict__ w0, const float* __restrict__ w1,
                        const float* __restrict__ w2, const float* __restrict__ w3,
                        __half* __restrict__ xh,
                        __half* __restrict__ o0, __half* __restrict__ o1,
                        __half* __restrict__ o2, __half* __restrict__ o3, int n4) {
    const float* in;
    __half* out;
    switch (blockIdx.y) {
        case 0:  in = w0; out = o0; break;
        case 1:  in = w1; out = o1; break;
        case 2:  in = w2; out = o2; break;
        case 3:  in = w3; out = o3; break;
        case 4:  in = x;                     out = xh;                     break;
        default: in = x + (size_t)n4 * 4;    out = xh + (size_t)n4 * 4;    break;
    }
    // 4 strided float4 loads per thread (independent -> 4 outstanding LDGs)
    int i0 = blockIdx.x * (blockDim.x * 4) + threadIdx.x;
    float4 v[4];
    bool ok[4];
#pragma unroll
    for (int q = 0; q < 4; q++) {
        int i = i0 + q * blockDim.x;
        ok[q] = (i < n4);
        if (ok[q]) v[q] = *(const float4*)(in + (size_t)i * 4);
    }
#pragma unroll
    for (int q = 0; q < 4; q++) {
        if (!ok[q]) continue;
        int i = i0 + q * blockDim.x;
        __half2 h01 = __floats2half2_rn(v[q].x, v[q].y);
        __half2 h23 = __floats2half2_rn(v[q].z, v[q].w);
        uint2 u;
        u.x = *(uint32_t*)&h01;
        u.y = *(uint32_t*)&h23;
        *(uint2*)(out + (size_t)i * 4) = u;
    }
}

// ---------------------------------------------------------------------------
// Shared GEMM constants
// ---------------------------------------------------------------------------
constexpr int HST = 40;                          // halves per smem row
constexpr int QKV_STG_H = 256 * HST;             // stage: A 128 + B 128 rows
constexpr int GEMM_SMEM_B = 3 * QKV_STG_H * 2;   // 61440 bytes (3-stage)
constexpr int GO_STG_H = 192 * HST;              // stage: A 64 + B 128 rows
constexpr int GO_SMEM_B = 3 * GO_STG_H * 2;      // 46080 bytes (3-stage)

// ---------------------------------------------------------------------------
// Fused QKV projection: BM=BN=128, BK=32, 128 thr, 3-stage cp.async pipeline
// (loads issued after the barrier into stage (kt+2)%3 — race-free).
// z selects W/output; z<2 fuses RoPE (+ Q scale with log2e folded in).
// ---------------------------------------------------------------------------
__global__ void __launch_bounds__(128, 3) gemm_qkv(
    const __half* __restrict__ A,
    const __half* __restrict__ Bq, const __half* __restrict__ Bk,
    const __half* __restrict__ Bv,
    __half* __restrict__ Qh, __half* __restrict__ Kh, __half* __restrict__ Vh,
    const float* __restrict__ cosp, const float* __restrict__ sinp) {
    extern __shared__ __half hsm[];

    const int z = blockIdx.z;
    const __half* B = (z == 0) ? Bq : ((z == 1) ? Bk : Bv);
    const int K = Dc, N = Dc;

    const int tid  = threadIdx.x;
    const int wid  = tid >> 5;
    const int lane = tid & 31;
    const int wm = (wid & 1) * 64;
    const int wn = (wid >> 1) * 64;
    const int gp = lane >> 2;
    const int t4 = lane & 3;
    const int m0 = blockIdx.y * 128;
    const int n0 = blockIdx.x * 128;

    const int arow = (lane & 7) + ((lane >> 3) & 1) * 8;
    const int acol = (lane >> 4) * 8;
    const int brow = (lane & 7) + (lane >> 4) * 8;
    const int bcol = ((lane >> 3) & 1) * 8;

    const int lrow = tid >> 2;
    const int lseg = tid & 3;
    const __half* Ag = A + (size_t)(m0 + lrow) * K + lseg * 8;
    const __half* Bg = B + (size_t)(n0 + lrow) * K + lseg * 8;

    const uint32_t sS_u = (uint32_t)__cvta_generic_to_shared(hsm);

    auto load_st = [&](int st, int k0) {
        uint32_t bA = sS_u + (uint32_t)(st * QKV_STG_H * 2);
        uint32_t bB = bA + (uint32_t)(128 * HST * 2);
#pragma unroll
        for (int p = 0; p < 4; p++) {
            int row = lrow + p * 32;
            CP_ASYNC16(bA + (uint32_t)((row * HST + lseg * 8) * 2),
                       Ag + (size_t)p * 32 * K + k0);
            CP_ASYNC16(bB + (uint32_t)((row * HST + lseg * 8) * 2),
                       Bg + (size_t)p * 32 * K + k0);
        }
        asm volatile("cp.async.commit_group;\n");
    };

    float acc[4][8][4];
#pragma unroll
    for (int im = 0; im < 4; im++)
#pragma unroll
        for (int in_ = 0; in_ < 8; in_++)
#pragma unroll
            for (int r = 0; r < 4; r++) acc[im][in_][r] = 0.f;

    const int nt = K / 32;

    load_st(0, 0);
    load_st(1, 32);

    int cs = 0, ld = 2;
    for (int kt = 0; kt < nt; kt++) {
        if (kt + 1 < nt) asm volatile("cp.async.wait_group 1;\n");
        else             asm volatile("cp.async.wait_group 0;\n");
        __syncthreads();

        if (kt + 2 < nt) {
            load_st(ld, (kt + 2) * 32);
            ld = (ld == 2) ? 0 : ld + 1;
        }

        const uint32_t cA_u = sS_u + (uint32_t)(cs * QKV_STG_H * 2);
        const uint32_t cB_u = cA_u + (uint32_t)(128 * HST * 2);
        cs = (cs == 2) ? 0 : cs + 1;

#pragma unroll
        for (int ks = 0; ks < 2; ks++) {
            const int kk = ks * 16;
            uint32_t af[4][4];
#pragma unroll
            for (int im = 0; im < 4; im++)
                LDSM_X4(af[im][0], af[im][1], af[im][2], af[im][3],
                        cA_u + (uint32_t)(((wm + im * 16 + arow) * HST + kk + acol) * 2));
            uint32_t bf[8][2];
#pragma unroll
            for (int j2 = 0; j2 < 4; j2++)
                LDSM_X4(bf[2 * j2][0], bf[2 * j2][1],
                        bf[2 * j2 + 1][0], bf[2 * j2 + 1][1],
                        cB_u + (uint32_t)(((wn + j2 * 16 + brow) * HST + kk + bcol) * 2));
#pragma unroll
            for (int im = 0; im < 4; im++)
#pragma unroll
                for (int in_ = 0; in_ < 8; in_++)
                    MMA_F16(acc[im][in_], af[im][0], af[im][1], af[im][2],
                            af[im][3], bf[in_][0], bf[in_][1]);
        }
    }
    __syncthreads();   // done with smem before epilogue reuses it

    if (z == 2) {
#pragma unroll
        for (int im = 0; im < 4; im++) {
            const int mA = m0 + wm + im * 16 + gp;
#pragma unroll
            for (int in_ = 0; in_ < 8; in_++) {
                const int n = n0 + wn + in_ * 8 + 2 * t4;
                *(__half2*)(Vh + (size_t)mA * N + n) =
                    __floats2half2_rn(acc[im][in_][0], acc[im][in_][1]);
                *(__half2*)(Vh + (size_t)(mA + 8) * N + n) =
                    __floats2half2_rn(acc[im][in_][2], acc[im][in_][3]);
            }
        }
        return;
    }

    // RoPE epilogue (Q/K) via smem exchange. Q scale includes log2(e).
    float* sf = (float*)hsm;   // [128][68] fp32 = 34816 B <= 61440 B
    if (wn == 64) {
#pragma unroll
        for (int im = 0; im < 4; im++) {
            int row = wm + im * 16 + gp;
#pragma unroll
            for (int in_ = 0; in_ < 8; in_++) {
                int col = in_ * 8 + 2 * t4;
                sf[row * 68 + col]           = acc[im][in_][0];
                sf[row * 68 + col + 1]       = acc[im][in_][1];
                sf[(row + 8) * 68 + col]     = acc[im][in_][2];
                sf[(row + 8) * 68 + col + 1] = acc[im][in_][3];
            }
        }
    }
    __syncthreads();
    if (wn == 0) {
        const float scale = (z == 0)
            ? 0.08838834764831845f * 1.44269504088896340736f : 1.0f;
        __half* Out = (z == 0) ? Qh : Kh;
#pragma unroll
        for (int im = 0; im < 4; im++) {
            int row = wm + im * 16 + gp;
            int sAi = (m0 + row) & (Sc - 1);
            int sBi = (m0 + row + 8) & (Sc - 1);
#pragma unroll
            for (int in_ = 0; in_ < 8; in_++) {
                int col = in_ * 8 + 2 * t4;
                float2 cA  = *(const float2*)(cosp + sAi * DHc + col);
                float2 snA = *(const float2*)(sinp + sAi * DHc + col);
                float2 cB  = *(const float2*)(cosp + sBi * DHc + col);
                float2 snB = *(const float2*)(sinp + sBi * DHc + col);
                float a0 = acc[im][in_][0], a1 = acc[im][in_][1];
                float a2 = acc[im][in_][2], a3 = acc[im][in_][3];
                float b0 = sf[row * 68 + col],       b1 = sf[row * 68 + col + 1];
                float b2 = sf[(row + 8) * 68 + col], b3 = sf[(row + 8) * 68 + col + 1];
                __half2 loA = __floats2half2_rn(scale * (a0 * cA.x - b0 * snA.x),
                                                scale * (a1 * cA.y - b1 * snA.y));
                __half2 hiA = __floats2half2_rn(scale * (b0 * cA.x + a0 * snA.x),
                                                scale * (b1 * cA.y + a1 * snA.y));
                __half2 loB = __floats2half2_rn(scale * (a2 * cB.x - b2 * snB.x),
                                                scale * (a3 * cB.y - b3 * snB.y));
                __half2 hiB = __floats2half2_rn(scale * (b2 * cB.x + a2 * snB.x),
                                                scale * (b3 * cB.y + a3 * snB.y));
                size_t gr = (size_t)(m0 + row) * Dc + n0 + col;
                *(__half2*)(Out + gr)                      = loA;
                *(__half2*)(Out + gr + 64)                 = hiA;
                *(__half2*)(Out + gr + (size_t)8 * Dc)      = loB;
                *(__half2*)(Out + gr + (size_t)8 * Dc + 64) = hiB;
            }
        }
    }
}

// ---------------------------------------------------------------------------
// O projection GEMM: BM=64, BN=128, 128 thr, warp tile 64x32, 3-stage
// pipeline, 4 CTAs/SM. fp32 out. (Unchanged from round 14.)
// ---------------------------------------------------------------------------
__global__ void __launch_bounds__(128, 4) gemm_o(const __half* __restrict__ A,
                                                 const __half* __restrict__ B,
                                                 float* __restrict__ Cf,
                                                 int M, int N, int K) {
    extern __shared__ __half hsm[];

    const int tid  = threadIdx.x;
    const int wid  = tid >> 5;
    const int lane = tid & 31;
    const int wn = wid * 32;
    const int gp = lane >> 2;
    const int t4 = lane & 3;
    const int m0 = blockIdx.y * 64;
    const int n0 = blockIdx.x * 128;

    const int arow = (lane & 7) + ((lane >> 3) & 1) * 8;
    const int acol = (lane >> 4) * 8;
    const int brow = (lane & 7) + (lane >> 4) * 8;
    const int bcol = ((lane >> 3) & 1) * 8;

    const int lrow = tid >> 2;         // 0..31
    const int lseg = tid & 3;
    const __half* Ag = A + (size_t)(m0 + lrow) * K + lseg * 8;
    const __half* Bg = B + (size_t)(n0 + lrow) * K + lseg * 8;

    const uint32_t sS_u = (uint32_t)__cvta_generic_to_shared(hsm);

    auto load_st = [&](int st, int k0) {
        uint32_t bA = sS_u + (uint32_t)(st * GO_STG_H * 2);
        uint32_t bB = bA + (uint32_t)(64 * HST * 2);
#pragma unroll
        for (int p = 0; p < 2; p++) {
            int row = lrow + p * 32;
            CP_ASYNC16(bA + (uint32_t)((row * HST + lseg * 8) * 2),
                       Ag + (size_t)p * 32 * K + k0);
        }
#pragma unroll
        for (int p = 0; p < 4; p++) {
            int row = lrow + p * 32;
            CP_ASYNC16(bB + (uint32_t)((row * HST + lseg * 8) * 2),
                       Bg + (size_t)p * 32 * K + k0);
        }
        asm volatile("cp.async.commit_group;\n");
    };

    float acc[4][4][4];
#pragma unroll
    for (int im = 0; im < 4; im++)
#pragma unroll
        for (int in_ = 0; in_ < 4; in_++)
#pragma unroll
            for (int r = 0; r < 4; r++) acc[im][in_][r] = 0.f;

    const int nt = K / 32;

    load_st(0, 0);
    load_st(1, 32);

    int cs = 0, ld = 2;
    for (int kt = 0; kt < nt; kt++) {
        if (kt + 1 < nt) asm volatile("cp.async.wait_group 1;\n");
        else             asm volatile("cp.async.wait_group 0;\n");
        __syncthreads();

        if (kt + 2 < nt) {
            load_st(ld, (kt + 2) * 32);
            ld = (ld == 2) ? 0 : ld + 1;
        }

        const uint32_t cA_u = sS_u + (uint32_t)(cs * GO_STG_H * 2);
        const uint32_t cB_u = cA_u + (uint32_t)(64 * HST * 2);
        cs = (cs == 2) ? 0 : cs + 1;

#pragma unroll
        for (int ks = 0; ks < 2; ks++) {
            const int kk = ks * 16;
            uint32_t af[4][4];
#pragma unroll
            for (int im = 0; im < 4; im++)
                LDSM_X4(af[im][0], af[im][1], af[im][2], af[im][3],
                        cA_u + (uint32_t)(((im * 16 + arow) * HST + kk + acol) * 2));
            uint32_t bf[4][2];
#pragma unroll
            for (int j2 = 0; j2 < 2; j2++)
                LDSM_X4(bf[2 * j2][0], bf[2 * j2][1],
                        bf[2 * j2 + 1][0], bf[2 * j2 + 1][1],
                        cB_u + (uint32_t)(((wn + j2 * 16 + brow) * HST + kk + bcol) * 2));
#pragma unroll
            for (int im = 0; im < 4; im++)
#pragma unroll
                for (int in_ = 0; in_ < 4; in_++)
                    MMA_F16(acc[im][in_], af[im][0], af[im][1], af[im][2],
                            af[im][3], bf[in_][0], bf[in_][1]);
        }
    }

#pragma unroll
    for (int im = 0; im < 4; im++) {
        const int mA = m0 + im * 16 + gp;
#pragma unroll
        for (int in_ = 0; in_ < 4; in_++) {
            const int n = n0 + wn + in_ * 8 + 2 * t4;
            *(float2*)(Cf + (size_t)mA * N + n) =
                make_float2(acc[im][in_][0], acc[im][in_][1]);
            *(float2*)(Cf + (size_t)(mA + 8) * N + n) =
                make_float2(acc[im][in_][2], acc[im][in_][3]);
        }
    }
}

// ---------------------------------------------------------------------------
// Flash attention: BM=BN=64, 128 thr / 4 warps, fp16 mma, XOR-swizzled smem,
// 3 CTAs/SM, exp2 softmax, skip-rescale, early K prefetch, heavy-first.
// (Unchanged from round 14.)
// ---------------------------------------------------------------------------
constexpr int OFF_Q  = 0;
constexpr int OFF_K0 = 16384;
constexpr int OFF_K1 = 32768;
constexpr int OFF_V  = 49152;
constexpr int OFF_P  = 65536;
constexpr int FL_SMEM_B = 73728;

__global__ void __launch_bounds__(128, 3) flash_tc(const __half* __restrict__ Q,
                                                   const __half* __restrict__ K,
                                                   const __half* __restrict__ V,
                                                   __half* __restrict__ O) {
    extern __shared__ char smraw[];
    char* sPc = smraw + OFF_P;
    const uint32_t sQ_u  = (uint32_t)__cvta_generic_to_shared(smraw + OFF_Q);
    const uint32_t sK0_u = (uint32_t)__cvta_generic_to_shared(smraw + OFF_K0);
    const uint32_t sK1_u = (uint32_t)__cvta_generic_to_shared(smraw + OFF_K1);
    const uint32_t sV_u  = (uint32_t)__cvta_generic_to_shared(smraw + OFF_V);
    const uint32_t sP_u  = (uint32_t)__cvta_generic_to_shared(sPc);

    const int tid  = threadIdx.x;
    const int wid  = tid >> 5;
    const int lane = tid & 31;
    const int gp   = lane >> 2;
    const int t4   = lane & 3;
    const int qb   = gridDim.x - 1 - blockIdx.x;   // heavy blocks first
    const int bh   = blockIdx.y;
    const int b    = bh >> 4;
    const int h    = bh & (Hc - 1);
    const size_t base = ((size_t)b * Sc) * Dc + (size_t)h * DHc;
    const int q0   = qb * 64;
    const int wrow = wid * 16;
    const int r0loc = wrow + gp;
    const int r1loc = r0loc + 8;

    const int arow = (lane & 7) + ((lane >> 3) & 1) * 8;
    const int aseg = lane >> 4;
    const int brow = (lane & 7) + (lane >> 4) * 8;
    const int bseg = (lane >> 3) & 1;
    const int vrow = (lane & 7) + ((lane >> 3) & 1) * 8;
    const int vseg = lane >> 4;

    {
#pragma unroll
        for (int p = 0; p < 8; p++) {
            int idx = tid + p * 128;
            int r = idx >> 4, sg = idx & 15;
            CP_ASYNC16(sQ_u + swz16(r, sg),
                       Q + base + (size_t)(q0 + r) * Dc + sg * 8);
        }
#pragma unroll
        for (int p = 0; p < 8; p++) {
            int idx = tid + p * 128;
            int r = idx >> 4, sg = idx & 15;
            CP_ASYNC16(sK0_u + swz16(r, sg),
                       K + base + (size_t)r * Dc + sg * 8);
        }
        asm volatile("cp.async.commit_group;\n");
#pragma unroll
        for (int p = 0; p < 8; p++) {
            int idx = tid + p * 128;
            int r = idx >> 4, sg = idx & 15;
            CP_ASYNC16(sV_u + swz16(r, sg),
                       V + base + (size_t)r * Dc + sg * 8);
        }
        asm volatile("cp.async.commit_group;\n");
    }

    float o[16][4];
#pragma unroll
    for (int n = 0; n < 16; n++)
#pragma unroll
        for (int r = 0; r < 4; r++) o[n][r] = 0.f;
    float m0 = -1e30f, m1 = -1e30f, l0 = 0.f, l1 = 0.f;

    for (int j = 0; j <= qb; ++j) {
        const uint32_t sKc_u = (j & 1) ? sK1_u : sK0_u;
        const uint32_t sKn_u = (j & 1) ? sK0_u : sK1_u;

        asm volatile("cp.async.wait_group 1;\n");
        __syncthreads();

        if (j < qb) {
            const int k0n = (j + 1) * 64;
#pragma unroll
            for (int p = 0; p < 8; p++) {
                int idx = tid + p * 128;
                int r = idx >> 4, sg = idx & 15;
                CP_ASYNC16(sKn_u + swz16(r, sg),
                           K + base + (size_t)(k0n + r) * Dc + sg * 8);
            }
            asm volatile("cp.async.commit_group;\n");
        }

        float sacc[8][4];
#pragma unroll
        for (int n = 0; n < 8; n++)
#pragma unroll
            for (int r = 0; r < 4; r++) sacc[n][r] = 0.f;

#pragma unroll
        for (int kk8 = 0; kk8 < 8; kk8++) {
            uint32_t a0, a1, a2, a3;
            LDSM_X4(a0, a1, a2, a3,
                    sQ_u + swz16(wrow + arow, kk8 * 2 + aseg));
            uint32_t bf[8][2];
#pragma unroll
            for (int j2 = 0; j2 < 4; j2++)
                LDSM_X4(bf[2 * j2][0], bf[2 * j2][1],
                        bf[2 * j2 + 1][0], bf[2 * j2 + 1][1],
                        sKc_u + swz16(j2 * 16 + brow, kk8 * 2 + bseg));
#pragma unroll
            for (int nt = 0; nt < 8; nt++)
                MMA_F16(sacc[nt], a0, a1, a2, a3, bf[nt][0], bf[nt][1]);
        }

        if (j == qb) {
#pragma unroll
            for (int nt = 0; nt < 8; nt++) {
                int c0 = nt * 8 + 2 * t4;
                if (c0 > r0loc)     sacc[nt][0] = -1e30f;
                if (c0 + 1 > r0loc) sacc[nt][1] = -1e30f;
                if (c0 > r1loc)     sacc[nt][2] = -1e30f;
                if (c0 + 1 > r1loc) sacc[nt][3] = -1e30f;
            }
        }

        float mx0 = -1e30f, mx1 = -1e30f;
#pragma unroll
        for (int nt = 0; nt < 8; nt++) {
            mx0 = fmaxf(mx0, fmaxf(sacc[nt][0], sacc[nt][1]));
            mx1 = fmaxf(mx1, fmaxf(sacc[nt][2], sacc[nt][3]));
        }
        mx0 = fmaxf(mx0, __shfl_xor_sync(0xffffffff, mx0, 1));
        mx0 = fmaxf(mx0, __shfl_xor_sync(0xffffffff, mx0, 2));
        mx1 = fmaxf(mx1, __shfl_xor_sync(0xffffffff, mx1, 1));
        mx1 = fmaxf(mx1, __shfl_xor_sync(0xffffffff, mx1, 2));

        float m0n = fmaxf(m0, mx0);
        float m1n = fmaxf(m1, mx1);
        bool nochg = (m0n == m0) && (m1n == m1);
        if (!__all_sync(0xffffffff, nochg)) {
            float corr0 = exp2f(m0 - m0n);
            float corr1 = exp2f(m1 - m1n);
            l0 *= corr0;
            l1 *= corr1;
#pragma unroll
            for (int nt = 0; nt < 16; nt++) {
                o[nt][0] *= corr0; o[nt][1] *= corr0;
                o[nt][2] *= corr1; o[nt][3] *= corr1;
            }
            m0 = m0n; m1 = m1n;
        }

        float ls0 = 0.f, ls1 = 0.f;
#pragma unroll
        for (int nt = 0; nt < 8; nt++) {
            float p0 = exp2f(sacc[nt][0] - m0);
            float p1 = exp2f(sacc[nt][1] - m0);
            float p2 = exp2f(sacc[nt][2] - m1);
            float p3 = exp2f(sacc[nt][3] - m1);
            ls0 += p0 + p1;
            ls1 += p2 + p3;
            *(__half2*)(sPc + swz8(r0loc, nt) + t4 * 4) = __floats2half2_rn(p0, p1);
            *(__half2*)(sPc + swz8(r1loc, nt) + t4 * 4) = __floats2half2_rn(p2, p3);
        }
        ls0 += __shfl_xor_sync(0xffffffff, ls0, 1);
        ls0 += __shfl_xor_sync(0xffffffff, ls0, 2);
        ls1 += __shfl_xor_sync(0xffffffff, ls1, 1);
        ls1 += __shfl_xor_sync(0xffffffff, ls1, 2);
        l0 += ls0;
        l1 += ls1;

        if (j < qb) asm volatile("cp.async.wait_group 1;\n");
        else        asm volatile("cp.async.wait_group 0;\n");
        __syncthreads();

#pragma unroll
        for (int ks = 0; ks < 4; ks++) {
            const int kk = ks * 16;
            uint32_t a0, a1, a2, a3;
            LDSM_X4(a0, a1, a2, a3,
                    sP_u + swz8(wrow + arow, ks * 2 + aseg));
#pragma unroll
            for (int j2 = 0; j2 < 8; j2++) {
                uint32_t b00, b01, b10, b11;
                LDSM_X4_T(b00, b01, b10, b11,
                          sV_u + swz16(kk + vrow, j2 * 2 + vseg));
                MMA_F16(o[2 * j2],     a0, a1, a2, a3, b00, b01);
                MMA_F16(o[2 * j2 + 1], a0, a1, a2, a3, b10, b11);
            }
        }
        __syncthreads();

        if (j < qb) {
            const int k0n = (j + 1) * 64;
#pragma unroll
            for (int p = 0; p < 8; p++) {
                int idx = tid + p * 128;
                int r = idx >> 4, sg = idx & 15;
                CP_ASYNC16(sV_u + swz16(r, sg),
                           V + base + (size_t)(k0n + r) * Dc + sg * 8);
            }
            asm volatile("cp.async.commit_group;\n");
        }
    }

    float inv0 = 1.0f / l0, inv1 = 1.0f / l1;
    const size_t row0 = base + (size_t)(q0 + r0loc) * Dc;
    const size_t row1 = base + (size_t)(q0 + r1loc) * Dc;
#pragma unroll
    for (int nt = 0; nt < 16; nt++) {
        int c0 = nt * 8 + 2 * t4;
        *(__half2*)(O + row0 + c0) =
            __floats2half2_rn(o[nt][0] * inv0, o[nt][1] * inv0);
        *(__half2*)(O + row1 + c0) =
            __floats2half2_rn(o[nt][2] * inv1, o[nt][3] * inv1);
    }
}

// ---------------------------------------------------------------------------
// Launch
// ---------------------------------------------------------------------------
extern "C" void kernel_launch(void* const* d_in, const int* in_sizes, int n_in,
                              void* d_out, int out_size) {
    const float* x    = (const float*)d_in[0];
    const float* cosp = (const float*)d_in[1];
    const float* sinp = (const float*)d_in[2];
    const float* Wq   = (const float*)d_in[3];
    const float* Wk   = (const float*)d_in[4];
    const float* Wv   = (const float*)d_in[5];
    const float* Wo   = (const float*)d_in[6];
    float* out = (float*)d_out;

    __half *Vh, *xh, *Qh, *Kh, *Ah, *wqh, *wkh, *wvh, *woh;
    cudaGetSymbolAddress((void**)&Vh, g_Vh);
    cudaGetSymbolAddress((void**)&xh, g_xh);
    cudaGetSymbolAddress((void**)&Qh, g_Qh);
    cudaGetSymbolAddress((void**)&Kh, g_Kh);
    cudaGetSymbolAddress((void**)&Ah, g_Ah);
    cudaGetSymbolAddress((void**)&wqh, g_wqh);
    cudaGetSymbolAddress((void**)&wkh, g_wkh);
    cudaGetSymbolAddress((void**)&wvh, g_wvh);
    cudaGetSymbolAddress((void**)&woh, g_woh);

    cudaFuncSetAttribute(gemm_qkv, cudaFuncAttributeMaxDynamicSharedMemorySize,
                         GEMM_SMEM_B);
    cudaFuncSetAttribute(gemm_o, cudaFuncAttributeMaxDynamicSharedMemorySize,
                         GO_SMEM_B);
    cudaFuncSetAttribute(flash_tc, cudaFuncAttributeMaxDynamicSharedMemorySize,
                         FL_SMEM_B);

    // all fp16 conversions in one launch (4 float4 per thread, MLP=4)
    {
        const int nw = Dc * Dc / 4;
        dim3 cgrid((nw + 1023) / 1024, 6);
        cvt_all<<<cgrid, 256>>>(x, Wq, Wk, Wv, Wo,
                                xh, wqh, wkh, wvh, woh, nw);
    }

    // fused QKV projections + RoPE/scale epilogue (3-stage pipeline)
    {
        dim3 qgrid(Dc / 128, Mc / 128, 3);   // (16, 32, 3)
        gemm_qkv<<<qgrid, 128, GEMM_SMEM_B>>>(xh, wqh, wkh, wvh,
                                              Qh, Kh, Vh, cosp, sinp);
    }

    // flash attention (heavy-first)
    {
        dim3 fgrid(Sc / 64, Bc * Hc);   // (32, 32)
        flash_tc<<<fgrid, 128, FL_SMEM_B>>>(Qh, Kh, Vh, Ah);
    }

    // O projection (3-stage pipeline, fp32 out)
    {
        dim3 ggrid(Dc / 128, Mc / 64);   // (16, 64)
        gemm_o<<<ggrid, 128, GO_SMEM_B>>>(Ah, woh, out, Mc, Dc, Dc);
    }
}